// round 7
// baseline (speedup 1.0000x reference)
#include <cuda_runtime.h>
#include <cuda_bf16.h>
#include <cuda_fp16.h>
#include <cstdint>

// Problem constants
#define B_  4
#define S_  2048
#define D_  1024
#define H_  16
#define HD_ 64
#define M_  (B_*S_)   // 8192

// ---------------- scratch (__device__ globals; no allocs allowed) ----------
// activations fp16 hi/lo (A operands of projection GEMMs)
__device__ __half g_xq_h[(size_t)M_*D_], g_xq_l[(size_t)M_*D_];
__device__ __half g_xk_h[(size_t)M_*D_], g_xk_l[(size_t)M_*D_];
__device__ __half g_xv_h[(size_t)M_*D_], g_xv_l[(size_t)M_*D_];
// weights single fp16 (B operands)
__device__ __half g_wq[(size_t)D_*D_], g_wk[(size_t)D_*D_];
__device__ __half g_wv[(size_t)D_*D_], g_wo[(size_t)D_*D_];
// projected Q,K,V split hi/lo bf16 in head-compact layout [b,h,s,d]
__device__ __nv_bfloat16 g_qh[(size_t)M_*D_], g_ql[(size_t)M_*D_];
__device__ __nv_bfloat16 g_kh[(size_t)M_*D_], g_kl[(size_t)M_*D_];
__device__ __nv_bfloat16 g_vh[(size_t)M_*D_], g_vl[(size_t)M_*D_];
// attention output fp16 hi/lo in [m][1024] layout (A of final GEMM)
__device__ __half g_hh[(size_t)M_*D_], g_hl[(size_t)M_*D_];

extern __shared__ char dynsmem[];

// ---------------- PTX helpers ------------------------------------------------
__device__ __forceinline__ uint32_t smem_u32(const void* p) {
    uint32_t a;
    asm("{ .reg .u64 t; cvta.to.shared.u64 t, %1; cvt.u32.u64 %0, t; }" : "=r"(a) : "l"(p));
    return a;
}
__device__ __forceinline__ void cp16(uint32_t dst, const void* src) {
    asm volatile("cp.async.cg.shared.global [%0], [%1], 16;" :: "r"(dst), "l"(src) : "memory");
}
__device__ __forceinline__ void cp_commit() {
    asm volatile("cp.async.commit_group;" ::: "memory");
}
__device__ __forceinline__ void ldsm4(uint32_t* r, uint32_t addr) {
    asm volatile("ldmatrix.sync.aligned.m8n8.x4.shared.b16 {%0,%1,%2,%3}, [%4];"
                 : "=r"(r[0]), "=r"(r[1]), "=r"(r[2]), "=r"(r[3]) : "r"(addr));
}
__device__ __forceinline__ void ldsm4t(uint32_t* r, uint32_t addr) {
    asm volatile("ldmatrix.sync.aligned.m8n8.x4.trans.shared.b16 {%0,%1,%2,%3}, [%4];"
                 : "=r"(r[0]), "=r"(r[1]), "=r"(r[2]), "=r"(r[3]) : "r"(addr));
}
__device__ __forceinline__ void mma_bf16(float* d, const uint32_t* a, const uint32_t* b) {
    asm volatile(
        "mma.sync.aligned.m16n8k16.row.col.f32.bf16.bf16.f32 "
        "{%0,%1,%2,%3}, {%4,%5,%6,%7}, {%8,%9}, {%0,%1,%2,%3};"
        : "+f"(d[0]), "+f"(d[1]), "+f"(d[2]), "+f"(d[3])
        : "r"(a[0]), "r"(a[1]), "r"(a[2]), "r"(a[3]), "r"(b[0]), "r"(b[1]));
}
__device__ __forceinline__ void mma_f16(float* d, const uint32_t* a, const uint32_t* b) {
    asm volatile(
        "mma.sync.aligned.m16n8k16.row.col.f32.f16.f16.f32 "
        "{%0,%1,%2,%3}, {%4,%5,%6,%7}, {%8,%9}, {%0,%1,%2,%3};"
        : "+f"(d[0]), "+f"(d[1]), "+f"(d[2]), "+f"(d[3])
        : "r"(a[0]), "r"(a[1]), "r"(a[2]), "r"(a[3]), "r"(b[0]), "r"(b[1]));
}
// bf16 split (17-bit effective)
__device__ __forceinline__ uint32_t cvt2bf(float lo, float hi) {
    uint32_t r;
    asm("cvt.rn.bf16x2.f32 %0, %1, %2;" : "=r"(r) : "f"(hi), "f"(lo));
    return r;
}
__device__ __forceinline__ void split2bf(float x0, float x1, uint32_t& hp, uint32_t& lp) {
    hp = cvt2bf(x0, x1);
    float h0 = __uint_as_float(hp << 16);
    float h1 = __uint_as_float(hp & 0xffff0000u);
    lp = cvt2bf(x0 - h0, x1 - h1);
}
// fp16 split (22-bit effective)
__device__ __forceinline__ void split2h(float x0, float x1, uint32_t& hp, uint32_t& lp) {
    __half2 h = __floats2half2_rn(x0, x1);
    float2 f = __half22float2(h);
    __half2 l = __floats2half2_rn(x0 - f.x, x1 - f.y);
    hp = *(uint32_t*)&h;
    lp = *(uint32_t*)&l;
}

// ---------------- cvt kernels ------------------------------------------------
// activations: fp32 -> fp16 hi/lo, z selects tensor
__global__ __launch_bounds__(256) void cvt_act_kernel(
    const float* __restrict__ x0, const float* __restrict__ x1, const float* __restrict__ x2,
    __half* __restrict__ h0, __half* __restrict__ l0,
    __half* __restrict__ h1, __half* __restrict__ l1,
    __half* __restrict__ h2, __half* __restrict__ l2, int n4)
{
    int i = blockIdx.x * blockDim.x + threadIdx.x;
    if (i >= n4) return;
    const float* x = blockIdx.y == 0 ? x0 : (blockIdx.y == 1 ? x1 : x2);
    __half* hh = blockIdx.y == 0 ? h0 : (blockIdx.y == 1 ? h1 : h2);
    __half* ll = blockIdx.y == 0 ? l0 : (blockIdx.y == 1 ? l1 : l2);
    float4 v = ((const float4*)x)[i];
    uint32_t a, b, c, d;
    split2h(v.x, v.y, a, c);
    split2h(v.z, v.w, b, d);
    ((uint2*)hh)[i] = make_uint2(a, b);
    ((uint2*)ll)[i] = make_uint2(c, d);
}
// weights: fp32 -> single fp16, z selects tensor
__global__ __launch_bounds__(256) void cvt_w_kernel(
    const float* __restrict__ w0, const float* __restrict__ w1,
    const float* __restrict__ w2, const float* __restrict__ w3,
    __half* __restrict__ o0, __half* __restrict__ o1,
    __half* __restrict__ o2, __half* __restrict__ o3, int n4)
{
    int i = blockIdx.x * blockDim.x + threadIdx.x;
    if (i >= n4) return;
    const float* w = blockIdx.y == 0 ? w0 : (blockIdx.y == 1 ? w1 : (blockIdx.y == 2 ? w2 : w3));
    __half* o = blockIdx.y == 0 ? o0 : (blockIdx.y == 1 ? o1 : (blockIdx.y == 2 ? o2 : o3));
    float4 v = ((const float4*)w)[i];
    __half2 p0 = __floats2half2_rn(v.x, v.y);
    __half2 p1 = __floats2half2_rn(v.z, v.w);
    ((uint2*)o)[i] = make_uint2(*(uint32_t*)&p0, *(uint32_t*)&p1);
}

// ---------------- fp16 2-call GEMM: out = A @ B^T + bias --------------------
// A split fp16 hi/lo, B single fp16. CTA 128x128, BK=32, 8 warps, warp 64x32.
#define BM 128
#define BN 128
#define GBK 32
#define ROWB 80
#define TILEB (128 * ROWB)      // 10240
#define BUFB  (3 * TILEB)       // Ah, Al, B
#define GEMM_SMEM (2 * BUFB)    // 61440 -> 3 CTAs/SM

__device__ __forceinline__ void g2s_chunk(
    uint32_t sbuf, const __half* Ah, const __half* Al, const __half* Bw, int tid)
{
#pragma unroll
    for (int r = 0; r < 2; r++) {
        int c = tid + (r << 8);
        int row = c >> 2, c16 = c & 3;
        uint32_t soff = (uint32_t)row * ROWB + (uint32_t)c16 * 16;
        size_t goff = (size_t)row * D_ + c16 * 8;
        cp16(sbuf + 0 * TILEB + soff, Ah + goff);
        cp16(sbuf + 1 * TILEB + soff, Al + goff);
        cp16(sbuf + 2 * TILEB + soff, Bw + goff);
    }
}

template <int EPI>
__global__ __launch_bounds__(256) void gemm_mma_kernel(
    const __half* __restrict__ Ahi, const __half* __restrict__ Alo,
    const __half* __restrict__ Bw,
    const float* __restrict__ bias, float* __restrict__ out,
    __nv_bfloat16* __restrict__ outh, __nv_bfloat16* __restrict__ outl)
{
    const uint32_t sb = smem_u32(dynsmem);
    const int tid = threadIdx.x, wid = tid >> 5, lane = tid & 31;
    const int wm = wid >> 2, wn = wid & 3;
    const int n0 = blockIdx.x * BN, m0 = blockIdx.y * BM;

    const __half* Ah = Ahi + (size_t)m0 * D_;
    const __half* Al = Alo + (size_t)m0 * D_;
    const __half* Bp = Bw + (size_t)n0 * D_;

    float acc[4][4][4];
#pragma unroll
    for (int i = 0; i < 4; i++)
#pragma unroll
        for (int j = 0; j < 4; j++)
#pragma unroll
            for (int k = 0; k < 4; k++) acc[i][j][k] = 0.f;

    g2s_chunk(sb,        Ah,       Al,       Bp,       tid); cp_commit();
    g2s_chunk(sb + BUFB, Ah + GBK, Al + GBK, Bp + GBK, tid); cp_commit();

    const int lr = lane & 7, lq = lane >> 3;
    const uint32_t a_base_off =
        (uint32_t)(wm * 64 + (lq & 1) * 8 + lr) * ROWB + (uint32_t)((lq >> 1) * 8) * 2;
    const uint32_t b_base_off =
        (uint32_t)(wn * 32 + (lq >> 1) * 8 + lr) * ROWB + (uint32_t)((lq & 1) * 8) * 2;

    const int NCHUNK = D_ / GBK;
#pragma unroll 1
    for (int c = 0; c < NCHUNK; c++) {
        if (c >= NCHUNK - 2) asm volatile("cp.async.wait_group 0;" ::: "memory");
        else                 asm volatile("cp.async.wait_group 1;" ::: "memory");
        __syncthreads();

        const uint32_t buf = sb + (uint32_t)(c & 1) * BUFB;
        const uint32_t sAh = buf, sAl = buf + TILEB, sB = buf + 2 * TILEB;

#pragma unroll
        for (int ks = 0; ks < 2; ks++) {
            const uint32_t ko = (uint32_t)(ks * 16) * 2;
            uint32_t ahr[4][4], alr[4][4], br[2][4];
#pragma unroll
            for (int mt = 0; mt < 4; mt++) {
                ldsm4(ahr[mt], sAh + a_base_off + ko + (uint32_t)mt * (16 * ROWB));
                ldsm4(alr[mt], sAl + a_base_off + ko + (uint32_t)mt * (16 * ROWB));
            }
#pragma unroll
            for (int np = 0; np < 2; np++)
                ldsm4(br[np], sB + b_base_off + ko + (uint32_t)np * (16 * ROWB));
#pragma unroll
            for (int mt = 0; mt < 4; mt++)
#pragma unroll
                for (int nt = 0; nt < 4; nt++) {
                    const uint32_t* b2 = &br[nt >> 1][(nt & 1) * 2];
                    mma_f16(acc[mt][nt], ahr[mt], b2);
                    mma_f16(acc[mt][nt], alr[mt], b2);
                }
        }
        __syncthreads();

        if (c + 2 < NCHUNK) {
            const int kc = (c + 2) * GBK;
            g2s_chunk(sb + (uint32_t)(c & 1) * BUFB, Ah + kc, Al + kc, Bp + kc, tid);
            cp_commit();
        }
    }

    const int g = lane >> 2, tq = lane & 3;
#pragma unroll
    for (int mt = 0; mt < 4; mt++) {
#pragma unroll
        for (int nt = 0; nt < 4; nt++) {
            int row = m0 + wm * 64 + mt * 16 + g;
            int col = n0 + wn * 32 + nt * 8 + tq * 2;
            float2 bv = *(const float2*)&bias[col];
            float v0 = acc[mt][nt][0] + bv.x, v1 = acc[mt][nt][1] + bv.y;
            float v2 = acc[mt][nt][2] + bv.x, v3 = acc[mt][nt][3] + bv.y;
            if (EPI == 0) {
                *(float2*)&out[(size_t)row * D_ + col]       = make_float2(v0, v1);
                *(float2*)&out[(size_t)(row + 8) * D_ + col] = make_float2(v2, v3);
            } else {
                int bb = row >> 11, s = row & 2047, hh = col >> 6, d = col & 63;
                size_t i0 = ((size_t)(bb * H_ + hh) * S_ + s) * HD_ + d;
                size_t i1 = i0 + 8 * HD_;
                uint32_t hp, lp;
                split2bf(v0, v1, hp, lp);
                *(uint32_t*)&outh[i0] = hp; *(uint32_t*)&outl[i0] = lp;
                split2bf(v2, v3, hp, lp);
                *(uint32_t*)&outh[i1] = hp; *(uint32_t*)&outl[i1] = lp;
            }
        }
    }
}

// ---------------- tensor-core flash attention --------------------------------
// grid (16 qtiles, 16 h, 4 b), 256 threads (8 warps x 16 q-rows).
// K and V tiles both [64 s][72 d]@144B (V consumed via ldmatrix.trans).
#define FQ_H 0u
#define FQ_L 18432u
#define FKV  36864u          // + buf*36864; inside: Kh,Kl,Vh,Vl each 9216
#define FMK  110592u         // + buf*256
#define FLASH_SMEM 111104

__global__ __launch_bounds__(256) void flash_tc_kernel(const int* __restrict__ mask)
{
    char* sm = dynsmem;
    const uint32_t sb = smem_u32(sm);
    const int tid = threadIdx.x, w = tid >> 5, lane = tid & 31;
    const int lr = lane & 7, lq = lane >> 3, g = lane >> 2, q = lane & 3;
    const int b = blockIdx.z, h = blockIdx.y;
    const int bh = b * H_ + h;
    const int q0 = blockIdx.x * 128;

    const __nv_bfloat16* Qhp = g_qh + ((size_t)bh * S_ + q0) * HD_;
    const __nv_bfloat16* Qlp = g_ql + ((size_t)bh * S_ + q0) * HD_;
    const __nv_bfloat16* Khp = g_kh + (size_t)bh * S_ * HD_;
    const __nv_bfloat16* Klp = g_kl + (size_t)bh * S_ * HD_;
    const __nv_bfloat16* Vhp = g_vh + (size_t)bh * S_ * HD_;
    const __nv_bfloat16* Vlp = g_vl + (size_t)bh * S_ * HD_;
    const int* mg = mask + b * S_;

    {
        int r = tid >> 1, half = tid & 1;
        const __nv_bfloat16* src = (half ? Qlp : Qhp) + (size_t)r * HD_;
        uint32_t dst = sb + (half ? FQ_L : FQ_H) + (uint32_t)r * 144u;
#pragma unroll
        for (int j = 0; j < 8; j++) cp16(dst + j * 16, src + j * 8);
    }
    cp_commit();

    auto load_tile = [&](int kt, int buf) {
        int k0 = kt * 64;
        int r = tid >> 2, which = tid & 3;
        uint32_t dst = sb + FKV + (uint32_t)buf * 36864u +
                       (uint32_t)which * 9216u + (uint32_t)r * 144u;
        const __nv_bfloat16* src;
        if (which == 0)      src = Khp + (size_t)(k0 + r) * HD_;
        else if (which == 1) src = Klp + (size_t)(k0 + r) * HD_;
        else if (which == 2) src = Vhp + (size_t)(k0 + r) * HD_;
        else                 src = Vlp + (size_t)(k0 + r) * HD_;
#pragma unroll
        for (int j = 0; j < 8; j++) cp16(dst + j * 16, src + j * 8);
        if (tid < 16) cp16(sb + FMK + (uint32_t)buf * 256u + tid * 16, mg + k0 + tid * 4);
        cp_commit();
    };
    load_tile(0, 0);
    load_tile(1, 1);

    asm volatile("cp.async.wait_group 2;" ::: "memory");
    __syncthreads();

    uint32_t qfh[4][4], qfl[4][4];
    {
        uint32_t aoff = (uint32_t)(w * 16 + (lq & 1) * 8 + lr) * 144u +
                        (uint32_t)((lq >> 1) * 8) * 2u;
#pragma unroll
        for (int ks = 0; ks < 4; ks++) {
            ldsm4(qfh[ks], sb + FQ_H + aoff + ks * 32);
            ldsm4(qfl[ks], sb + FQ_L + aoff + ks * 32);
        }
    }

    float o[8][4];
#pragma unroll
    for (int i = 0; i < 8; i++) { o[i][0] = o[i][1] = o[i][2] = o[i][3] = 0.f; }
    float m0r = -1e30f, m1r = -1e30f, l0 = 0.f, l1 = 0.f;
    // K (non-trans) fragment base: rows = keys
    const uint32_t boff = (uint32_t)((lq >> 1) * 8 + lr) * 144u +
                          (uint32_t)((lq & 1) * 8) * 2u;
    // V (trans) fragment base: rows = keys, matrices (keys±8)x(d±8)
    const uint32_t voff = (uint32_t)((lq & 1) * 8 + lr) * 144u +
                          (uint32_t)((lq >> 1) * 8) * 2u;

#pragma unroll 1
    for (int kt = 0; kt < 32; kt++) {
        if (kt >= 30) asm volatile("cp.async.wait_group 0;" ::: "memory");
        else          asm volatile("cp.async.wait_group 1;" ::: "memory");
        __syncthreads();

        const uint32_t kb = sb + FKV + (uint32_t)(kt & 1) * 36864u;
        const int* mkb = (const int*)(sm + FMK + (kt & 1) * 256);

        // ---- scores: S = Q @ K^T (3-call bf16 split) ----
        float sc[8][4];
#pragma unroll
        for (int i = 0; i < 8; i++) { sc[i][0] = sc[i][1] = sc[i][2] = sc[i][3] = 0.f; }

#pragma unroll
        for (int ks = 0; ks < 4; ks++) {
            uint32_t kfh[4][4], kfl[4][4];
#pragma unroll
            for (int np = 0; np < 4; np++) {
                ldsm4(kfh[np], kb + boff + (uint32_t)np * 2304u + ks * 32);
                ldsm4(kfl[np], kb + 9216u + boff + (uint32_t)np * 2304u + ks * 32);
            }
#pragma unroll
            for (int nt = 0; nt < 8; nt++) {
                const uint32_t* bh2 = &kfh[nt >> 1][(nt & 1) * 2];
                const uint32_t* bl2 = &kfl[nt >> 1][(nt & 1) * 2];
                mma_bf16(sc[nt], qfh[ks], bh2);
                mma_bf16(sc[nt], qfh[ks], bl2);
                mma_bf16(sc[nt], qfl[ks], bh2);
            }
        }

        // ---- scale + mask ----
#pragma unroll
        for (int nt = 0; nt < 8; nt++) {
            int c0 = nt * 8 + q * 2;
            int mk0 = mkb[c0], mk1 = mkb[c0 + 1];
            sc[nt][0] = mk0 ? sc[nt][0] * 0.125f : -1e10f;
            sc[nt][1] = mk1 ? sc[nt][1] * 0.125f : -1e10f;
            sc[nt][2] = mk0 ? sc[nt][2] * 0.125f : -1e10f;
            sc[nt][3] = mk1 ? sc[nt][3] * 0.125f : -1e10f;
        }

        // ---- online softmax ----
        float tm0 = -1e30f, tm1 = -1e30f;
#pragma unroll
        for (int nt = 0; nt < 8; nt++) {
            tm0 = fmaxf(tm0, fmaxf(sc[nt][0], sc[nt][1]));
            tm1 = fmaxf(tm1, fmaxf(sc[nt][2], sc[nt][3]));
        }
        tm0 = fmaxf(tm0, __shfl_xor_sync(0xffffffffu, tm0, 1));
        tm0 = fmaxf(tm0, __shfl_xor_sync(0xffffffffu, tm0, 2));
        tm1 = fmaxf(tm1, __shfl_xor_sync(0xffffffffu, tm1, 1));
        tm1 = fmaxf(tm1, __shfl_xor_sync(0xffffffffu, tm1, 2));
        float nm0 = fmaxf(m0r, tm0), nm1 = fmaxf(m1r, tm1);
        float al0 = __expf(m0r - nm0), al1 = __expf(m1r - nm1);
        m0r = nm0; m1r = nm1;
        float rs0 = 0.f, rs1 = 0.f;
#pragma unroll
        for (int nt = 0; nt < 8; nt++) {
            sc[nt][0] = __expf(sc[nt][0] - nm0);
            sc[nt][1] = __expf(sc[nt][1] - nm0);
            sc[nt][2] = __expf(sc[nt][2] - nm1);
            sc[nt][3] = __expf(sc[nt][3] - nm1);
            rs0 += sc[nt][0] + sc[nt][1];
            rs1 += sc[nt][2] + sc[nt][3];
        }
        rs0 += __shfl_xor_sync(0xffffffffu, rs0, 1);
        rs0 += __shfl_xor_sync(0xffffffffu, rs0, 2);
        rs1 += __shfl_xor_sync(0xffffffffu, rs1, 1);
        rs1 += __shfl_xor_sync(0xffffffffu, rs1, 2);
        l0 = l0 * al0 + rs0;
        l1 = l1 * al1 + rs1;
#pragma unroll
        for (int nt = 0; nt < 8; nt++) {
            o[nt][0] *= al0; o[nt][1] *= al0; o[nt][2] *= al1; o[nt][3] *= al1;
        }

        // ---- O += P @ V (V via ldmatrix.trans on [s][d], 3-call bf16) ----
#pragma unroll
        for (int ks = 0; ks < 4; ks++) {
            const int t0 = 2 * ks, t1 = t0 + 1;
            uint32_t ah[4], apl[4];
            split2bf(sc[t0][0], sc[t0][1], ah[0], apl[0]);
            split2bf(sc[t0][2], sc[t0][3], ah[1], apl[1]);
            split2bf(sc[t1][0], sc[t1][1], ah[2], apl[2]);
            split2bf(sc[t1][2], sc[t1][3], ah[3], apl[3]);
            uint32_t vfh[4][4], vfl[4][4];
            const uint32_t kso = (uint32_t)(ks * 16) * 144u;
#pragma unroll
            for (int np = 0; np < 4; np++) {
                ldsm4t(vfh[np], kb + 18432u + voff + kso + (uint32_t)np * 32u);
                ldsm4t(vfl[np], kb + 27648u + voff + kso + (uint32_t)np * 32u);
            }
#pragma unroll
            for (int nt = 0; nt < 8; nt++) {
                const uint32_t* bh2 = &vfh[nt >> 1][(nt & 1) * 2];
                const uint32_t* bl2 = &vfl[nt >> 1][(nt & 1) * 2];
                mma_bf16(o[nt], ah, bh2);
                mma_bf16(o[nt], apl, bh2);
                mma_bf16(o[nt], ah, bl2);
            }
        }
        __syncthreads();
        if (kt + 2 < 32) load_tile(kt + 2, kt & 1);
    }

    // ---- normalize, split fp16, store to [m][1024] hi/lo ----
    float inv0 = 1.f / l0, inv1 = 1.f / l1;
    size_t row0 = (size_t)(b * S_ + q0 + w * 16 + g);
    int colb = h * HD_;
#pragma unroll
    for (int nt = 0; nt < 8; nt++) {
        int col = colb + nt * 8 + q * 2;
        uint32_t hp, lp;
        split2h(o[nt][0] * inv0, o[nt][1] * inv0, hp, lp);
        *(uint32_t*)&g_hh[row0 * D_ + col] = hp;
        *(uint32_t*)&g_hl[row0 * D_ + col] = lp;
        split2h(o[nt][2] * inv1, o[nt][3] * inv1, hp, lp);
        *(uint32_t*)&g_hh[(row0 + 8) * D_ + col] = hp;
        *(uint32_t*)&g_hl[(row0 + 8) * D_ + col] = lp;
    }
}

// ---------------------------------------------------------------------------
extern "C" void kernel_launch(void* const* d_in, const int* in_sizes, int n_in,
                              void* d_out, int out_size)
{
    const float* query = (const float*)d_in[0];
    const float* key   = (const float*)d_in[1];
    const float* value = (const float*)d_in[2];
    const int*   mask  = (const int*)d_in[3];
    const float* Wq = (const float*)d_in[4];
    const float* bq = (const float*)d_in[5];
    const float* Wk = (const float*)d_in[6];
    const float* bk = (const float*)d_in[7];
    const float* Wv = (const float*)d_in[8];
    const float* bv = (const float*)d_in[9];
    const float* Wo = (const float*)d_in[10];
    const float* bo = (const float*)d_in[11];
    float* out = (float*)d_out;

    __half *xqh,*xql,*xkh,*xkl,*xvh,*xvl,*wq,*wk,*wv,*wo,*hh,*hl;
    __nv_bfloat16 *qh,*ql,*kh,*kl,*vh,*vl;
    cudaGetSymbolAddress((void**)&xqh, g_xq_h); cudaGetSymbolAddress((void**)&xql, g_xq_l);
    cudaGetSymbolAddress((void**)&xkh, g_xk_h); cudaGetSymbolAddress((void**)&xkl, g_xk_l);
    cudaGetSymbolAddress((void**)&xvh, g_xv_h); cudaGetSymbolAddress((void**)&xvl, g_xv_l);
    cudaGetSymbolAddress((void**)&wq, g_wq);    cudaGetSymbolAddress((void**)&wk, g_wk);
    cudaGetSymbolAddress((void**)&wv, g_wv);    cudaGetSymbolAddress((void**)&wo, g_wo);
    cudaGetSymbolAddress((void**)&qh, g_qh);    cudaGetSymbolAddress((void**)&ql, g_ql);
    cudaGetSymbolAddress((void**)&kh, g_kh);    cudaGetSymbolAddress((void**)&kl, g_kl);
    cudaGetSymbolAddress((void**)&vh, g_vh);    cudaGetSymbolAddress((void**)&vl, g_vl);
    cudaGetSymbolAddress((void**)&hh, g_hh);    cudaGetSymbolAddress((void**)&hl, g_hl);

    static int attr_set = 0;
    if (!attr_set) {
        cudaFuncSetAttribute(gemm_mma_kernel<0>,
                             cudaFuncAttributeMaxDynamicSharedMemorySize, GEMM_SMEM);
        cudaFuncSetAttribute(gemm_mma_kernel<1>,
                             cudaFuncAttributeMaxDynamicSharedMemorySize, GEMM_SMEM);
        cudaFuncSetAttribute(flash_tc_kernel,
                             cudaFuncAttributeMaxDynamicSharedMemorySize, FLASH_SMEM);
        attr_set = 1;
    }

    const int NX4 = M_ * D_ / 4;
    const int NW4 = D_ * D_ / 4;
    // launch 0: activations, launch 1: weights (flash lands at ncu skip=5)
    cvt_act_kernel<<<dim3((NX4 + 255) / 256, 3), 256>>>(
        query, key, value, xqh, xql, xkh, xkl, xvh, xvl, NX4);
    cvt_w_kernel<<<dim3((NW4 + 255) / 256, 4), 256>>>(
        Wq, Wk, Wv, Wo, wq, wk, wv, wo, NW4);

    dim3 ggrid(D_ / BN, M_ / BM);   // (8, 64)
    gemm_mma_kernel<1><<<ggrid, 256, GEMM_SMEM>>>(xqh, xql, wq, bq, nullptr, qh, ql);
    gemm_mma_kernel<1><<<ggrid, 256, GEMM_SMEM>>>(xkh, xkl, wk, bk, nullptr, kh, kl);
    gemm_mma_kernel<1><<<ggrid, 256, GEMM_SMEM>>>(xvh, xvl, wv, bv, nullptr, vh, vl);

    flash_tc_kernel<<<dim3(S_ / 128, H_, B_), 256, FLASH_SMEM>>>(mask);

    gemm_mma_kernel<0><<<ggrid, 256, GEMM_SMEM>>>(hh, hl, wo, bo, out, nullptr, nullptr);
}

// round 8
// speedup vs baseline: 1.5135x; 1.5135x over previous
#include <cuda_runtime.h>
#include <cuda_bf16.h>
#include <cuda_fp16.h>
#include <cstdint>

// Problem constants
#define B_  4
#define S_  2048
#define D_  1024
#define H_  16
#define HD_ 64
#define M_  (B_*S_)   // 8192

// ---------------- scratch (__device__ globals) ------------------------------
__device__ __half g_xq_h[(size_t)M_*D_], g_xq_l[(size_t)M_*D_];
__device__ __half g_xk_h[(size_t)M_*D_], g_xk_l[(size_t)M_*D_];
__device__ __half g_xv_h[(size_t)M_*D_], g_xv_l[(size_t)M_*D_];
__device__ __half g_wq[(size_t)D_*D_], g_wk[(size_t)D_*D_];
__device__ __half g_wv[(size_t)D_*D_], g_wo[(size_t)D_*D_];
// projected Q,K,V split hi/lo bf16, head-compact [b,h,s,d]
__device__ __nv_bfloat16 g_qh[(size_t)M_*D_], g_ql[(size_t)M_*D_];
__device__ __nv_bfloat16 g_kh[(size_t)M_*D_], g_kl[(size_t)M_*D_];
__device__ __nv_bfloat16 g_vh[(size_t)M_*D_], g_vl[(size_t)M_*D_];
// V transposed [b,h,d,s]
__device__ __nv_bfloat16 g_vth[(size_t)M_*D_], g_vtl[(size_t)M_*D_];
// attention output fp16 hi/lo [m][1024]
__device__ __half g_hh[(size_t)M_*D_], g_hl[(size_t)M_*D_];

extern __shared__ char dynsmem[];

// ---------------- PTX helpers ------------------------------------------------
__device__ __forceinline__ uint32_t smem_u32(const void* p) {
    uint32_t a;
    asm("{ .reg .u64 t; cvta.to.shared.u64 t, %1; cvt.u32.u64 %0, t; }" : "=r"(a) : "l"(p));
    return a;
}
__device__ __forceinline__ void cp16(uint32_t dst, const void* src) {
    asm volatile("cp.async.cg.shared.global [%0], [%1], 16;" :: "r"(dst), "l"(src) : "memory");
}
__device__ __forceinline__ void cp_commit() {
    asm volatile("cp.async.commit_group;" ::: "memory");
}
__device__ __forceinline__ void ldsm4(uint32_t* r, uint32_t addr) {
    asm volatile("ldmatrix.sync.aligned.m8n8.x4.shared.b16 {%0,%1,%2,%3}, [%4];"
                 : "=r"(r[0]), "=r"(r[1]), "=r"(r[2]), "=r"(r[3]) : "r"(addr));
}
__device__ __forceinline__ void mma_bf16(float* d, const uint32_t* a, const uint32_t* b) {
    asm volatile(
        "mma.sync.aligned.m16n8k16.row.col.f32.bf16.bf16.f32 "
        "{%0,%1,%2,%3}, {%4,%5,%6,%7}, {%8,%9}, {%0,%1,%2,%3};"
        : "+f"(d[0]), "+f"(d[1]), "+f"(d[2]), "+f"(d[3])
        : "r"(a[0]), "r"(a[1]), "r"(a[2]), "r"(a[3]), "r"(b[0]), "r"(b[1]));
}
__device__ __forceinline__ void mma_f16(float* d, const uint32_t* a, const uint32_t* b) {
    asm volatile(
        "mma.sync.aligned.m16n8k16.row.col.f32.f16.f16.f32 "
        "{%0,%1,%2,%3}, {%4,%5,%6,%7}, {%8,%9}, {%0,%1,%2,%3};"
        : "+f"(d[0]), "+f"(d[1]), "+f"(d[2]), "+f"(d[3])
        : "r"(a[0]), "r"(a[1]), "r"(a[2]), "r"(a[3]), "r"(b[0]), "r"(b[1]));
}
__device__ __forceinline__ uint32_t cvt2bf(float lo, float hi) {
    uint32_t r;
    asm("cvt.rn.bf16x2.f32 %0, %1, %2;" : "=r"(r) : "f"(hi), "f"(lo));
    return r;
}
__device__ __forceinline__ void split2bf(float x0, float x1, uint32_t& hp, uint32_t& lp) {
    hp = cvt2bf(x0, x1);
    float h0 = __uint_as_float(hp << 16);
    float h1 = __uint_as_float(hp & 0xffff0000u);
    lp = cvt2bf(x0 - h0, x1 - h1);
}
__device__ __forceinline__ void split2h(float x0, float x1, uint32_t& hp, uint32_t& lp) {
    __half2 h = __floats2half2_rn(x0, x1);
    float2 f = __half22float2(h);
    __half2 l = __floats2half2_rn(x0 - f.x, x1 - f.y);
    hp = *(uint32_t*)&h;
    lp = *(uint32_t*)&l;
}

// ---------------- fused conversion kernel (one launch) -----------------------
// y = 0..2: activations fp32 -> fp16 hi/lo; y = 3..6: weights fp32 -> fp16.
__global__ __launch_bounds__(256) void cvt_all_kernel(
    const float* __restrict__ xq, const float* __restrict__ xk, const float* __restrict__ xv,
    const float* __restrict__ Wq, const float* __restrict__ Wk,
    const float* __restrict__ Wv, const float* __restrict__ Wo,
    __half* __restrict__ qh2, __half* __restrict__ ql2,
    __half* __restrict__ kh2, __half* __restrict__ kl2,
    __half* __restrict__ vh2, __half* __restrict__ vl2,
    __half* __restrict__ owq, __half* __restrict__ owk,
    __half* __restrict__ owv, __half* __restrict__ owo)
{
    const int y = blockIdx.y;
    int i = blockIdx.x * blockDim.x + threadIdx.x;
    if (y < 3) {
        const int n4 = M_ * D_ / 4;
        if (i >= n4) return;
        const float* x = y == 0 ? xq : (y == 1 ? xk : xv);
        __half* hh = y == 0 ? qh2 : (y == 1 ? kh2 : vh2);
        __half* ll = y == 0 ? ql2 : (y == 1 ? kl2 : vl2);
        float4 v = ((const float4*)x)[i];
        uint32_t a, b, c, d;
        split2h(v.x, v.y, a, c);
        split2h(v.z, v.w, b, d);
        ((uint2*)hh)[i] = make_uint2(a, b);
        ((uint2*)ll)[i] = make_uint2(c, d);
    } else {
        const int n4 = D_ * D_ / 4;
        if (i >= n4) return;
        const float* w = y == 3 ? Wq : (y == 4 ? Wk : (y == 5 ? Wv : Wo));
        __half* o = y == 3 ? owq : (y == 4 ? owk : (y == 5 ? owv : owo));
        float4 v = ((const float4*)w)[i];
        __half2 p0 = __floats2half2_rn(v.x, v.y);
        __half2 p1 = __floats2half2_rn(v.z, v.w);
        ((uint2*)o)[i] = make_uint2(*(uint32_t*)&p0, *(uint32_t*)&p1);
    }
}

// ---------------- fp16 2-call GEMM: out = A @ B^T + bias --------------------
#define BM 128
#define BN 128
#define GBK 32
#define ROWB 80
#define TILEB (128 * ROWB)
#define BUFB  (3 * TILEB)
#define GEMM_SMEM (2 * BUFB)    // 61440

__device__ __forceinline__ void g2s_chunk(
    uint32_t sbuf, const __half* Ah, const __half* Al, const __half* Bw, int tid)
{
#pragma unroll
    for (int r = 0; r < 2; r++) {
        int c = tid + (r << 8);
        int row = c >> 2, c16 = c & 3;
        uint32_t soff = (uint32_t)row * ROWB + (uint32_t)c16 * 16;
        size_t goff = (size_t)row * D_ + c16 * 8;
        cp16(sbuf + 0 * TILEB + soff, Ah + goff);
        cp16(sbuf + 1 * TILEB + soff, Al + goff);
        cp16(sbuf + 2 * TILEB + soff, Bw + goff);
    }
}

template <int EPI>
__global__ __launch_bounds__(256) void gemm_mma_kernel(
    const __half* __restrict__ Ahi, const __half* __restrict__ Alo,
    const __half* __restrict__ Bw,
    const float* __restrict__ bias, float* __restrict__ out,
    __nv_bfloat16* __restrict__ outh, __nv_bfloat16* __restrict__ outl)
{
    const uint32_t sb = smem_u32(dynsmem);
    const int tid = threadIdx.x, wid = tid >> 5, lane = tid & 31;
    const int wm = wid >> 2, wn = wid & 3;
    const int n0 = blockIdx.x * BN, m0 = blockIdx.y * BM;

    const __half* Ah = Ahi + (size_t)m0 * D_;
    const __half* Al = Alo + (size_t)m0 * D_;
    const __half* Bp = Bw + (size_t)n0 * D_;

    float acc[4][4][4];
#pragma unroll
    for (int i = 0; i < 4; i++)
#pragma unroll
        for (int j = 0; j < 4; j++)
#pragma unroll
            for (int k = 0; k < 4; k++) acc[i][j][k] = 0.f;

    g2s_chunk(sb,        Ah,       Al,       Bp,       tid); cp_commit();
    g2s_chunk(sb + BUFB, Ah + GBK, Al + GBK, Bp + GBK, tid); cp_commit();

    const int lr = lane & 7, lq = lane >> 3;
    const uint32_t a_base_off =
        (uint32_t)(wm * 64 + (lq & 1) * 8 + lr) * ROWB + (uint32_t)((lq >> 1) * 8) * 2;
    const uint32_t b_base_off =
        (uint32_t)(wn * 32 + (lq >> 1) * 8 + lr) * ROWB + (uint32_t)((lq & 1) * 8) * 2;

    const int NCHUNK = D_ / GBK;
#pragma unroll 1
    for (int c = 0; c < NCHUNK; c++) {
        if (c >= NCHUNK - 2) asm volatile("cp.async.wait_group 0;" ::: "memory");
        else                 asm volatile("cp.async.wait_group 1;" ::: "memory");
        __syncthreads();

        const uint32_t buf = sb + (uint32_t)(c & 1) * BUFB;
        const uint32_t sAh = buf, sAl = buf + TILEB, sB = buf + 2 * TILEB;

#pragma unroll
        for (int ks = 0; ks < 2; ks++) {
            const uint32_t ko = (uint32_t)(ks * 16) * 2;
            uint32_t ahr[4][4], alr[4][4], br[2][4];
#pragma unroll
            for (int mt = 0; mt < 4; mt++) {
                ldsm4(ahr[mt], sAh + a_base_off + ko + (uint32_t)mt * (16 * ROWB));
                ldsm4(alr[mt], sAl + a_base_off + ko + (uint32_t)mt * (16 * ROWB));
            }
#pragma unroll
            for (int np = 0; np < 2; np++)
                ldsm4(br[np], sB + b_base_off + ko + (uint32_t)np * (16 * ROWB));
#pragma unroll
            for (int mt = 0; mt < 4; mt++)
#pragma unroll
                for (int nt = 0; nt < 4; nt++) {
                    const uint32_t* b2 = &br[nt >> 1][(nt & 1) * 2];
                    mma_f16(acc[mt][nt], ahr[mt], b2);
                    mma_f16(acc[mt][nt], alr[mt], b2);
                }
        }
        __syncthreads();

        if (c + 2 < NCHUNK) {
            const int kc = (c + 2) * GBK;
            g2s_chunk(sb + (uint32_t)(c & 1) * BUFB, Ah + kc, Al + kc, Bp + kc, tid);
            cp_commit();
        }
    }

    const int g = lane >> 2, tq = lane & 3;
#pragma unroll
    for (int mt = 0; mt < 4; mt++) {
#pragma unroll
        for (int nt = 0; nt < 4; nt++) {
            int row = m0 + wm * 64 + mt * 16 + g;
            int col = n0 + wn * 32 + nt * 8 + tq * 2;
            float2 bv = *(const float2*)&bias[col];
            float v0 = acc[mt][nt][0] + bv.x, v1 = acc[mt][nt][1] + bv.y;
            float v2 = acc[mt][nt][2] + bv.x, v3 = acc[mt][nt][3] + bv.y;
            if (EPI == 0) {
                *(float2*)&out[(size_t)row * D_ + col]       = make_float2(v0, v1);
                *(float2*)&out[(size_t)(row + 8) * D_ + col] = make_float2(v2, v3);
            } else {
                int bb = row >> 11, s = row & 2047, hh = col >> 6, d = col & 63;
                size_t i0 = ((size_t)(bb * H_ + hh) * S_ + s) * HD_ + d;
                size_t i1 = i0 + 8 * HD_;
                uint32_t hp, lp;
                split2bf(v0, v1, hp, lp);
                *(uint32_t*)&outh[i0] = hp; *(uint32_t*)&outl[i0] = lp;
                split2bf(v2, v3, hp, lp);
                *(uint32_t*)&outh[i1] = hp; *(uint32_t*)&outl[i1] = lp;
            }
        }
    }
}

// ---------------- V transpose: [b,h,s,d] -> [b,h,d,s] (hi and lo) ----------
__global__ __launch_bounds__(256) void vtrans_kernel()
{
    __shared__ __align__(16) unsigned short ts[64 * 66];
    const int b = blockIdx.z, h = blockIdx.y, st = blockIdx.x;
    const int bh = b * H_ + h;
    const int s0 = st * 64;
    const int tid = threadIdx.x;

#pragma unroll 1
    for (int p = 0; p < 2; p++) {
        if (p) __syncthreads();
        const __nv_bfloat16* inp = (p ? g_vl : g_vh) + ((size_t)bh * S_ + s0) * HD_;
        const uint32_t* src = (const uint32_t*)inp;
#pragma unroll
        for (int i = 0; i < 8; i++) {
            int flat = tid + i * 256;
            int r = flat >> 5, c2 = flat & 31;
            *(uint32_t*)&ts[r * 66 + c2 * 2] = src[r * 32 + c2];
        }
        __syncthreads();
        __nv_bfloat16* outp = (p ? g_vtl : g_vth) + (size_t)bh * HD_ * S_ + s0;
        uint32_t* dst = (uint32_t*)outp;
#pragma unroll
        for (int i = 0; i < 8; i++) {
            int flat = tid + i * 256;
            int d = flat >> 5, sp = flat & 31;
            uint32_t v = (uint32_t)ts[(2 * sp) * 66 + d] |
                         ((uint32_t)ts[(2 * sp + 1) * 66 + d] << 16);
            dst[(size_t)d * (S_ / 2) + sp] = v;
        }
    }
}

// ---------------- tensor-core flash attention (R6 version) -------------------
#define FQ_H 0u
#define FQ_L 18432u
#define FKV  36864u
#define FMK  110592u
#define FLASH_SMEM 111104

__global__ __launch_bounds__(256) void flash_tc_kernel(const int* __restrict__ mask)
{
    char* sm = dynsmem;
    const uint32_t sb = smem_u32(sm);
    const int tid = threadIdx.x, w = tid >> 5, lane = tid & 31;
    const int lr = lane & 7, lq = lane >> 3, g = lane >> 2, q = lane & 3;
    const int b = blockIdx.z, h = blockIdx.y;
    const int bh = b * H_ + h;
    const int q0 = blockIdx.x * 128;

    const __nv_bfloat16* Qhp = g_qh + ((size_t)bh * S_ + q0) * HD_;
    const __nv_bfloat16* Qlp = g_ql + ((size_t)bh * S_ + q0) * HD_;
    const __nv_bfloat16* Khp = g_kh + (size_t)bh * S_ * HD_;
    const __nv_bfloat16* Klp = g_kl + (size_t)bh * S_ * HD_;
    const __nv_bfloat16* Vhp = g_vth + (size_t)bh * HD_ * S_;
    const __nv_bfloat16* Vlp = g_vtl + (size_t)bh * HD_ * S_;
    const int* mg = mask + b * S_;

    {
        int r = tid >> 1, half = tid & 1;
        const __nv_bfloat16* src = (half ? Qlp : Qhp) + (size_t)r * HD_;
        uint32_t dst = sb + (half ? FQ_L : FQ_H) + (uint32_t)r * 144u;
#pragma unroll
        for (int j = 0; j < 8; j++) cp16(dst + j * 16, src + j * 8);
    }
    cp_commit();

    auto load_tile = [&](int kt, int buf) {
        int k0 = kt * 64;
        int r = tid >> 2, which = tid & 3;
        uint32_t dst = sb + FKV + (uint32_t)buf * 36864u +
                       (uint32_t)which * 9216u + (uint32_t)r * 144u;
        const __nv_bfloat16* src;
        if (which == 0)      src = Khp + (size_t)(k0 + r) * HD_;
        else if (which == 1) src = Klp + (size_t)(k0 + r) * HD_;
        else if (which == 2) src = Vhp + (size_t)r * S_ + k0;
        else                 src = Vlp + (size_t)r * S_ + k0;
#pragma unroll
        for (int j = 0; j < 8; j++) cp16(dst + j * 16, src + j * 8);
        if (tid < 16) cp16(sb + FMK + (uint32_t)buf * 256u + tid * 16, mg + k0 + tid * 4);
        cp_commit();
    };
    load_tile(0, 0);
    load_tile(1, 1);

    asm volatile("cp.async.wait_group 2;" ::: "memory");
    __syncthreads();

    uint32_t qfh[4][4], qfl[4][4];
    {
        uint32_t aoff = (uint32_t)(w * 16 + (lq & 1) * 8 + lr) * 144u +
                        (uint32_t)((lq >> 1) * 8) * 2u;
#pragma unroll
        for (int ks = 0; ks < 4; ks++) {
            ldsm4(qfh[ks], sb + FQ_H + aoff + ks * 32);
            ldsm4(qfl[ks], sb + FQ_L + aoff + ks * 32);
        }
    }

    float o[8][4];
#pragma unroll
    for (int i = 0; i < 8; i++) { o[i][0] = o[i][1] = o[i][2] = o[i][3] = 0.f; }
    float m0r = -1e30f, m1r = -1e30f, l0 = 0.f, l1 = 0.f;
    const uint32_t boff = (uint32_t)((lq >> 1) * 8 + lr) * 144u +
                          (uint32_t)((lq & 1) * 8) * 2u;

#pragma unroll 1
    for (int kt = 0; kt < 32; kt++) {
        if (kt >= 30) asm volatile("cp.async.wait_group 0;" ::: "memory");
        else          asm volatile("cp.async.wait_group 1;" ::: "memory");
        __syncthreads();

        const uint32_t kb = sb + FKV + (uint32_t)(kt & 1) * 36864u;
        const int* mkb = (const int*)(sm + FMK + (kt & 1) * 256);

        float sc[8][4];
#pragma unroll
        for (int i = 0; i < 8; i++) { sc[i][0] = sc[i][1] = sc[i][2] = sc[i][3] = 0.f; }

#pragma unroll
        for (int ks = 0; ks < 4; ks++) {
            uint32_t kfh[4][4], kfl[4][4];
#pragma unroll
            for (int np = 0; np < 4; np++) {
                ldsm4(kfh[np], kb + boff + (uint32_t)np * 2304u + ks * 32);
                ldsm4(kfl[np], kb + 9216u + boff + (uint32_t)np * 2304u + ks * 32);
            }
#pragma unroll
            for (int nt = 0; nt < 8; nt++) {
                const uint32_t* bh2 = &kfh[nt >> 1][(nt & 1) * 2];
                const uint32_t* bl2 = &kfl[nt >> 1][(nt & 1) * 2];
                mma_bf16(sc[nt], qfh[ks], bh2);
                mma_bf16(sc[nt], qfh[ks], bl2);
                mma_bf16(sc[nt], qfl[ks], bh2);
            }
        }

#pragma unroll
        for (int nt = 0; nt < 8; nt++) {
            int c0 = nt * 8 + q * 2;
            int mk0 = mkb[c0], mk1 = mkb[c0 + 1];
            sc[nt][0] = mk0 ? sc[nt][0] * 0.125f : -1e10f;
            sc[nt][1] = mk1 ? sc[nt][1] * 0.125f : -1e10f;
            sc[nt][2] = mk0 ? sc[nt][2] * 0.125f : -1e10f;
            sc[nt][3] = mk1 ? sc[nt][3] * 0.125f : -1e10f;
        }

        float tm0 = -1e30f, tm1 = -1e30f;
#pragma unroll
        for (int nt = 0; nt < 8; nt++) {
            tm0 = fmaxf(tm0, fmaxf(sc[nt][0], sc[nt][1]));
            tm1 = fmaxf(tm1, fmaxf(sc[nt][2], sc[nt][3]));
        }
        tm0 = fmaxf(tm0, __shfl_xor_sync(0xffffffffu, tm0, 1));
        tm0 = fmaxf(tm0, __shfl_xor_sync(0xffffffffu, tm0, 2));
        tm1 = fmaxf(tm1, __shfl_xor_sync(0xffffffffu, tm1, 1));
        tm1 = fmaxf(tm1, __shfl_xor_sync(0xffffffffu, tm1, 2));
        float nm0 = fmaxf(m0r, tm0), nm1 = fmaxf(m1r, tm1);
        float al0 = __expf(m0r - nm0), al1 = __expf(m1r - nm1);
        m0r = nm0; m1r = nm1;
        float rs0 = 0.f, rs1 = 0.f;
#pragma unroll
        for (int nt = 0; nt < 8; nt++) {
            sc[nt][0] = __expf(sc[nt][0] - nm0);
            sc[nt][1] = __expf(sc[nt][1] - nm0);
            sc[nt][2] = __expf(sc[nt][2] - nm1);
            sc[nt][3] = __expf(sc[nt][3] - nm1);
            rs0 += sc[nt][0] + sc[nt][1];
            rs1 += sc[nt][2] + sc[nt][3];
        }
        rs0 += __shfl_xor_sync(0xffffffffu, rs0, 1);
        rs0 += __shfl_xor_sync(0xffffffffu, rs0, 2);
        rs1 += __shfl_xor_sync(0xffffffffu, rs1, 1);
        rs1 += __shfl_xor_sync(0xffffffffu, rs1, 2);
        l0 = l0 * al0 + rs0;
        l1 = l1 * al1 + rs1;
#pragma unroll
        for (int nt = 0; nt < 8; nt++) {
            o[nt][0] *= al0; o[nt][1] *= al0; o[nt][2] *= al1; o[nt][3] *= al1;
        }

#pragma unroll
        for (int ks = 0; ks < 4; ks++) {
            const int t0 = 2 * ks, t1 = t0 + 1;
            uint32_t ah[4], apl[4];
            split2bf(sc[t0][0], sc[t0][1], ah[0], apl[0]);
            split2bf(sc[t0][2], sc[t0][3], ah[1], apl[1]);
            split2bf(sc[t1][0], sc[t1][1], ah[2], apl[2]);
            split2bf(sc[t1][2], sc[t1][3], ah[3], apl[3]);
            uint32_t vfh[4][4], vfl[4][4];
#pragma unroll
            for (int np = 0; np < 4; np++) {
                ldsm4(vfh[np], kb + 18432u + boff + (uint32_t)np * 2304u + ks * 32);
                ldsm4(vfl[np], kb + 27648u + boff + (uint32_t)np * 2304u + ks * 32);
            }
#pragma unroll
            for (int nt = 0; nt < 8; nt++) {
                const uint32_t* bh2 = &vfh[nt >> 1][(nt & 1) * 2];
                const uint32_t* bl2 = &vfl[nt >> 1][(nt & 1) * 2];
                mma_bf16(o[nt], ah, bh2);
                mma_bf16(o[nt], apl, bh2);
                mma_bf16(o[nt], ah, bl2);
            }
        }
        __syncthreads();
        if (kt + 2 < 32) load_tile(kt + 2, kt & 1);
    }

    float inv0 = 1.f / l0, inv1 = 1.f / l1;
    size_t row0 = (size_t)(b * S_ + q0 + w * 16 + g);
    int colb = h * HD_;
#pragma unroll
    for (int nt = 0; nt < 8; nt++) {
        int col = colb + nt * 8 + q * 2;
        uint32_t hp, lp;
        split2h(o[nt][0] * inv0, o[nt][1] * inv0, hp, lp);
        *(uint32_t*)&g_hh[row0 * D_ + col] = hp;
        *(uint32_t*)&g_hl[row0 * D_ + col] = lp;
        split2h(o[nt][2] * inv1, o[nt][3] * inv1, hp, lp);
        *(uint32_t*)&g_hh[(row0 + 8) * D_ + col] = hp;
        *(uint32_t*)&g_hl[(row0 + 8) * D_ + col] = lp;
    }
}

// ---------------------------------------------------------------------------
extern "C" void kernel_launch(void* const* d_in, const int* in_sizes, int n_in,
                              void* d_out, int out_size)
{
    const float* query = (const float*)d_in[0];
    const float* key   = (const float*)d_in[1];
    const float* value = (const float*)d_in[2];
    const int*   mask  = (const int*)d_in[3];
    const float* Wq = (const float*)d_in[4];
    const float* bq = (const float*)d_in[5];
    const float* Wk = (const float*)d_in[6];
    const float* bk = (const float*)d_in[7];
    const float* Wv = (const float*)d_in[8];
    const float* bv = (const float*)d_in[9];
    const float* Wo = (const float*)d_in[10];
    const float* bo = (const float*)d_in[11];
    float* out = (float*)d_out;

    __half *xqh,*xql,*xkh,*xkl,*xvh,*xvl,*wq,*wk,*wv,*wo,*hh,*hl;
    __nv_bfloat16 *qh,*ql,*kh,*kl,*vh,*vl;
    cudaGetSymbolAddress((void**)&xqh, g_xq_h); cudaGetSymbolAddress((void**)&xql, g_xq_l);
    cudaGetSymbolAddress((void**)&xkh, g_xk_h); cudaGetSymbolAddress((void**)&xkl, g_xk_l);
    cudaGetSymbolAddress((void**)&xvh, g_xv_h); cudaGetSymbolAddress((void**)&xvl, g_xv_l);
    cudaGetSymbolAddress((void**)&wq, g_wq);    cudaGetSymbolAddress((void**)&wk, g_wk);
    cudaGetSymbolAddress((void**)&wv, g_wv);    cudaGetSymbolAddress((void**)&wo, g_wo);
    cudaGetSymbolAddress((void**)&qh, g_qh);    cudaGetSymbolAddress((void**)&ql, g_ql);
    cudaGetSymbolAddress((void**)&kh, g_kh);    cudaGetSymbolAddress((void**)&kl, g_kl);
    cudaGetSymbolAddress((void**)&vh, g_vh);    cudaGetSymbolAddress((void**)&vl, g_vl);
    cudaGetSymbolAddress((void**)&hh, g_hh);    cudaGetSymbolAddress((void**)&hl, g_hl);

    static int attr_set = 0;
    if (!attr_set) {
        cudaFuncSetAttribute(gemm_mma_kernel<0>,
                             cudaFuncAttributeMaxDynamicSharedMemorySize, GEMM_SMEM);
        cudaFuncSetAttribute(gemm_mma_kernel<1>,
                             cudaFuncAttributeMaxDynamicSharedMemorySize, GEMM_SMEM);
        cudaFuncSetAttribute(flash_tc_kernel,
                             cudaFuncAttributeMaxDynamicSharedMemorySize, FLASH_SMEM);
        attr_set = 1;
    }

    const int NX4 = M_ * D_ / 4;
    // one fused conversion launch (index 0) -> flash lands at ncu skip index 5
    cvt_all_kernel<<<dim3((NX4 + 255) / 256, 7), 256>>>(
        query, key, value, Wq, Wk, Wv, Wo,
        xqh, xql, xkh, xkl, xvh, xvl, wq, wk, wv, wo);

    dim3 ggrid(D_ / BN, M_ / BM);   // (8, 64)
    gemm_mma_kernel<1><<<ggrid, 256, GEMM_SMEM>>>(xqh, xql, wq, bq, nullptr, qh, ql);   // 1
    gemm_mma_kernel<1><<<ggrid, 256, GEMM_SMEM>>>(xkh, xkl, wk, bk, nullptr, kh, kl);   // 2
    gemm_mma_kernel<1><<<ggrid, 256, GEMM_SMEM>>>(xvh, xvl, wv, bv, nullptr, vh, vl);   // 3

    vtrans_kernel<<<dim3(S_ / 64, H_, B_), 256>>>();                                    // 4

    flash_tc_kernel<<<dim3(S_ / 128, H_, B_), 256, FLASH_SMEM>>>(mask);                 // 5

    gemm_mma_kernel<0><<<ggrid, 256, GEMM_SMEM>>>(hh, hl, wo, bo, out, nullptr, nullptr); // 6
}

// round 9
// speedup vs baseline: 2.0073x; 1.3263x over previous
#include <cuda_runtime.h>
#include <cuda_bf16.h>
#include <cuda_fp16.h>
#include <cstdint>

// Problem constants
#define B_  4
#define S_  2048
#define D_  1024
#define H_  16
#define HD_ 64
#define M_  (B_*S_)   // 8192

// ---------------- scratch (__device__ globals) ------------------------------
__device__ __half g_xq_h[(size_t)M_*D_], g_xq_l[(size_t)M_*D_];
__device__ __half g_xk_h[(size_t)M_*D_], g_xk_l[(size_t)M_*D_];
__device__ __half g_xv_h[(size_t)M_*D_], g_xv_l[(size_t)M_*D_];
__device__ __half g_wq[(size_t)D_*D_], g_wk[(size_t)D_*D_];
__device__ __half g_wv[(size_t)D_*D_], g_wo[(size_t)D_*D_];
// projected Q (fp16 hi/lo), K, V (single fp16), head-compact [b,h,s,d]
__device__ __half g_qh[(size_t)M_*D_], g_ql[(size_t)M_*D_];
__device__ __half g_k [(size_t)M_*D_];
__device__ __half g_v [(size_t)M_*D_];
// V transposed [b,h,d,s], single fp16
__device__ __half g_vt[(size_t)M_*D_];
// attention output fp16 hi/lo [m][1024]
__device__ __half g_hh[(size_t)M_*D_], g_hl[(size_t)M_*D_];

extern __shared__ char dynsmem[];

// ---------------- PTX helpers ------------------------------------------------
__device__ __forceinline__ uint32_t smem_u32(const void* p) {
    uint32_t a;
    asm("{ .reg .u64 t; cvta.to.shared.u64 t, %1; cvt.u32.u64 %0, t; }" : "=r"(a) : "l"(p));
    return a;
}
__device__ __forceinline__ void cp16(uint32_t dst, const void* src) {
    asm volatile("cp.async.cg.shared.global [%0], [%1], 16;" :: "r"(dst), "l"(src) : "memory");
}
__device__ __forceinline__ void cp_commit() {
    asm volatile("cp.async.commit_group;" ::: "memory");
}
__device__ __forceinline__ void ldsm4(uint32_t* r, uint32_t addr) {
    asm volatile("ldmatrix.sync.aligned.m8n8.x4.shared.b16 {%0,%1,%2,%3}, [%4];"
                 : "=r"(r[0]), "=r"(r[1]), "=r"(r[2]), "=r"(r[3]) : "r"(addr));
}
__device__ __forceinline__ void mma_f16(float* d, const uint32_t* a, const uint32_t* b) {
    asm volatile(
        "mma.sync.aligned.m16n8k16.row.col.f32.f16.f16.f32 "
        "{%0,%1,%2,%3}, {%4,%5,%6,%7}, {%8,%9}, {%0,%1,%2,%3};"
        : "+f"(d[0]), "+f"(d[1]), "+f"(d[2]), "+f"(d[3])
        : "r"(a[0]), "r"(a[1]), "r"(a[2]), "r"(a[3]), "r"(b[0]), "r"(b[1]));
}
__device__ __forceinline__ void split2h(float x0, float x1, uint32_t& hp, uint32_t& lp) {
    __half2 h = __floats2half2_rn(x0, x1);
    float2 f = __half22float2(h);
    __half2 l = __floats2half2_rn(x0 - f.x, x1 - f.y);
    hp = *(uint32_t*)&h;
    lp = *(uint32_t*)&l;
}
__device__ __forceinline__ uint32_t pack2h(float x0, float x1) {
    __half2 h = __floats2half2_rn(x0, x1);
    return *(uint32_t*)&h;
}

// ---------------- fused conversion kernel (one launch) -----------------------
__global__ __launch_bounds__(256) void cvt_all_kernel(
    const float* __restrict__ xq, const float* __restrict__ xk, const float* __restrict__ xv,
    const float* __restrict__ Wq, const float* __restrict__ Wk,
    const float* __restrict__ Wv, const float* __restrict__ Wo,
    __half* __restrict__ qh2, __half* __restrict__ ql2,
    __half* __restrict__ kh2, __half* __restrict__ kl2,
    __half* __restrict__ vh2, __half* __restrict__ vl2,
    __half* __restrict__ owq, __half* __restrict__ owk,
    __half* __restrict__ owv, __half* __restrict__ owo)
{
    const int y = blockIdx.y;
    int i = blockIdx.x * blockDim.x + threadIdx.x;
    if (y < 3) {
        const int n4 = M_ * D_ / 4;
        if (i >= n4) return;
        const float* x = y == 0 ? xq : (y == 1 ? xk : xv);
        __half* hh = y == 0 ? qh2 : (y == 1 ? kh2 : vh2);
        __half* ll = y == 0 ? ql2 : (y == 1 ? kl2 : vl2);
        float4 v = ((const float4*)x)[i];
        uint32_t a, b, c, d;
        split2h(v.x, v.y, a, c);
        split2h(v.z, v.w, b, d);
        ((uint2*)hh)[i] = make_uint2(a, b);
        ((uint2*)ll)[i] = make_uint2(c, d);
    } else {
        const int n4 = D_ * D_ / 4;
        if (i >= n4) return;
        const float* w = y == 3 ? Wq : (y == 4 ? Wk : (y == 5 ? Wv : Wo));
        __half* o = y == 3 ? owq : (y == 4 ? owk : (y == 5 ? owv : owo));
        float4 v = ((const float4*)w)[i];
        ((uint2*)o)[i] = make_uint2(pack2h(v.x, v.y), pack2h(v.z, v.w));
    }
}

// ---------------- fp16 2-call GEMM: out = A @ B^T + bias --------------------
// EPI 0: fp32 out [m][D].  EPI 1: fp16 hi/lo head-compact.  EPI 2: fp16 single.
#define BM 128
#define BN 128
#define GBK 32
#define ROWB 80
#define TILEB (128 * ROWB)
#define BUFB  (3 * TILEB)
#define GEMM_SMEM (2 * BUFB)    // 61440

__device__ __forceinline__ void g2s_chunk(
    uint32_t sbuf, const __half* Ah, const __half* Al, const __half* Bw, int tid)
{
#pragma unroll
    for (int r = 0; r < 2; r++) {
        int c = tid + (r << 8);
        int row = c >> 2, c16 = c & 3;
        uint32_t soff = (uint32_t)row * ROWB + (uint32_t)c16 * 16;
        size_t goff = (size_t)row * D_ + c16 * 8;
        cp16(sbuf + 0 * TILEB + soff, Ah + goff);
        cp16(sbuf + 1 * TILEB + soff, Al + goff);
        cp16(sbuf + 2 * TILEB + soff, Bw + goff);
    }
}

template <int EPI>
__global__ __launch_bounds__(256) void gemm_mma_kernel(
    const __half* __restrict__ Ahi, const __half* __restrict__ Alo,
    const __half* __restrict__ Bw,
    const float* __restrict__ bias, float* __restrict__ out,
    __half* __restrict__ outh, __half* __restrict__ outl)
{
    const uint32_t sb = smem_u32(dynsmem);
    const int tid = threadIdx.x, wid = tid >> 5, lane = tid & 31;
    const int wm = wid >> 2, wn = wid & 3;
    const int n0 = blockIdx.x * BN, m0 = blockIdx.y * BM;

    const __half* Ah = Ahi + (size_t)m0 * D_;
    const __half* Al = Alo + (size_t)m0 * D_;
    const __half* Bp = Bw + (size_t)n0 * D_;

    float acc[4][4][4];
#pragma unroll
    for (int i = 0; i < 4; i++)
#pragma unroll
        for (int j = 0; j < 4; j++)
#pragma unroll
            for (int k = 0; k < 4; k++) acc[i][j][k] = 0.f;

    g2s_chunk(sb,        Ah,       Al,       Bp,       tid); cp_commit();
    g2s_chunk(sb + BUFB, Ah + GBK, Al + GBK, Bp + GBK, tid); cp_commit();

    const int lr = lane & 7, lq = lane >> 3;
    const uint32_t a_base_off =
        (uint32_t)(wm * 64 + (lq & 1) * 8 + lr) * ROWB + (uint32_t)((lq >> 1) * 8) * 2;
    const uint32_t b_base_off =
        (uint32_t)(wn * 32 + (lq >> 1) * 8 + lr) * ROWB + (uint32_t)((lq & 1) * 8) * 2;

    const int NCHUNK = D_ / GBK;
#pragma unroll 1
    for (int c = 0; c < NCHUNK; c++) {
        if (c >= NCHUNK - 2) asm volatile("cp.async.wait_group 0;" ::: "memory");
        else                 asm volatile("cp.async.wait_group 1;" ::: "memory");
        __syncthreads();

        const uint32_t buf = sb + (uint32_t)(c & 1) * BUFB;
        const uint32_t sAh = buf, sAl = buf + TILEB, sB = buf + 2 * TILEB;

#pragma unroll
        for (int ks = 0; ks < 2; ks++) {
            const uint32_t ko = (uint32_t)(ks * 16) * 2;
            uint32_t ahr[4][4], alr[4][4], br[2][4];
#pragma unroll
            for (int mt = 0; mt < 4; mt++) {
                ldsm4(ahr[mt], sAh + a_base_off + ko + (uint32_t)mt * (16 * ROWB));
                ldsm4(alr[mt], sAl + a_base_off + ko + (uint32_t)mt * (16 * ROWB));
            }
#pragma unroll
            for (int np = 0; np < 2; np++)
                ldsm4(br[np], sB + b_base_off + ko + (uint32_t)np * (16 * ROWB));
#pragma unroll
            for (int mt = 0; mt < 4; mt++)
#pragma unroll
                for (int nt = 0; nt < 4; nt++) {
                    const uint32_t* b2 = &br[nt >> 1][(nt & 1) * 2];
                    mma_f16(acc[mt][nt], ahr[mt], b2);
                    mma_f16(acc[mt][nt], alr[mt], b2);
                }
        }
        __syncthreads();

        if (c + 2 < NCHUNK) {
            const int kc = (c + 2) * GBK;
            g2s_chunk(sb + (uint32_t)(c & 1) * BUFB, Ah + kc, Al + kc, Bp + kc, tid);
            cp_commit();
        }
    }

    const int g = lane >> 2, tq = lane & 3;
#pragma unroll
    for (int mt = 0; mt < 4; mt++) {
#pragma unroll
        for (int nt = 0; nt < 4; nt++) {
            int row = m0 + wm * 64 + mt * 16 + g;
            int col = n0 + wn * 32 + nt * 8 + tq * 2;
            float2 bv = *(const float2*)&bias[col];
            float v0 = acc[mt][nt][0] + bv.x, v1 = acc[mt][nt][1] + bv.y;
            float v2 = acc[mt][nt][2] + bv.x, v3 = acc[mt][nt][3] + bv.y;
            if (EPI == 0) {
                *(float2*)&out[(size_t)row * D_ + col]       = make_float2(v0, v1);
                *(float2*)&out[(size_t)(row + 8) * D_ + col] = make_float2(v2, v3);
            } else {
                int bb = row >> 11, s = row & 2047, hh = col >> 6, d = col & 63;
                size_t i0 = ((size_t)(bb * H_ + hh) * S_ + s) * HD_ + d;
                size_t i1 = i0 + 8 * HD_;
                if (EPI == 1) {
                    uint32_t hp, lp;
                    split2h(v0, v1, hp, lp);
                    *(uint32_t*)&outh[i0] = hp; *(uint32_t*)&outl[i0] = lp;
                    split2h(v2, v3, hp, lp);
                    *(uint32_t*)&outh[i1] = hp; *(uint32_t*)&outl[i1] = lp;
                } else {
                    *(uint32_t*)&outh[i0] = pack2h(v0, v1);
                    *(uint32_t*)&outh[i1] = pack2h(v2, v3);
                }
            }
        }
    }
}

// ---------------- V transpose: [b,h,s,d] -> [b,h,d,s] (single fp16) ---------
__global__ __launch_bounds__(256) void vtrans_kernel()
{
    __shared__ __align__(16) unsigned short ts[64 * 66];
    const int b = blockIdx.z, h = blockIdx.y, st = blockIdx.x;
    const int bh = b * H_ + h;
    const int s0 = st * 64;
    const int tid = threadIdx.x;

    const uint32_t* src = (const uint32_t*)(g_v + ((size_t)bh * S_ + s0) * HD_);
#pragma unroll
    for (int i = 0; i < 8; i++) {
        int flat = tid + i * 256;
        int r = flat >> 5, c2 = flat & 31;
        *(uint32_t*)&ts[r * 66 + c2 * 2] = src[r * 32 + c2];
    }
    __syncthreads();
    uint32_t* dst = (uint32_t*)(g_vt + (size_t)bh * HD_ * S_ + s0);
#pragma unroll
    for (int i = 0; i < 8; i++) {
        int flat = tid + i * 256;
        int d = flat >> 5, sp = flat & 31;
        uint32_t v = (uint32_t)ts[(2 * sp) * 66 + d] |
                     ((uint32_t)ts[(2 * sp + 1) * 66 + d] << 16);
        dst[(size_t)d * (S_ / 2) + sp] = v;
    }
}

// ---------------- tensor-core flash attention (fp16 2-call) ------------------
// smem: Qh 18432, Ql 18432; 2 bufs x {K 9216, Vt 9216}; mask 2x256.
#define FQ_H 0u
#define FQ_L 18432u
#define FKV  36864u
#define FBUF 18432u
#define FMK  73728u
#define FLASH_SMEM 74240

__global__ __launch_bounds__(256) void flash_tc_kernel(const int* __restrict__ mask)
{
    char* sm = dynsmem;
    const uint32_t sb = smem_u32(sm);
    const int tid = threadIdx.x, w = tid >> 5, lane = tid & 31;
    const int lr = lane & 7, lq = lane >> 3, g = lane >> 2, q = lane & 3;
    const int b = blockIdx.z, h = blockIdx.y;
    const int bh = b * H_ + h;
    const int q0 = blockIdx.x * 128;

    const __half* Qhp = g_qh + ((size_t)bh * S_ + q0) * HD_;
    const __half* Qlp = g_ql + ((size_t)bh * S_ + q0) * HD_;
    const __half* Kp  = g_k  + (size_t)bh * S_ * HD_;
    const __half* Vtp = g_vt + (size_t)bh * HD_ * S_;
    const int* mg = mask + b * S_;

    {
        int r = tid >> 1, half = tid & 1;
        const __half* src = (half ? Qlp : Qhp) + (size_t)r * HD_;
        uint32_t dst = sb + (half ? FQ_L : FQ_H) + (uint32_t)r * 144u;
#pragma unroll
        for (int j = 0; j < 8; j++) cp16(dst + j * 16, src + j * 8);
    }
    cp_commit();

    auto load_tile = [&](int kt, int buf) {
        int k0 = kt * 64;
        int which = tid & 1;            // 0=K, 1=V^T
        int halfr = (tid >> 1) & 1;     // half-row
        int r = tid >> 2;               // 0..63
        uint32_t dst = sb + FKV + (uint32_t)buf * FBUF + (uint32_t)which * 9216u +
                       (uint32_t)r * 144u + (uint32_t)halfr * 64u;
        const __half* src = which ? (Vtp + (size_t)r * S_ + k0 + halfr * 32)
                                  : (Kp + (size_t)(k0 + r) * HD_ + halfr * 32);
#pragma unroll
        for (int j = 0; j < 4; j++) cp16(dst + j * 16, src + j * 8);
        if (tid < 16) cp16(sb + FMK + (uint32_t)buf * 256u + tid * 16, mg + k0 + tid * 4);
        cp_commit();
    };
    load_tile(0, 0);
    load_tile(1, 1);

    asm volatile("cp.async.wait_group 2;" ::: "memory");
    __syncthreads();

    uint32_t qfh[4][4], qfl[4][4];
    {
        uint32_t aoff = (uint32_t)(w * 16 + (lq & 1) * 8 + lr) * 144u +
                        (uint32_t)((lq >> 1) * 8) * 2u;
#pragma unroll
        for (int ks = 0; ks < 4; ks++) {
            ldsm4(qfh[ks], sb + FQ_H + aoff + ks * 32);
            ldsm4(qfl[ks], sb + FQ_L + aoff + ks * 32);
        }
    }

    float o[8][4];
#pragma unroll
    for (int i = 0; i < 8; i++) { o[i][0] = o[i][1] = o[i][2] = o[i][3] = 0.f; }
    float m0r = -1e30f, m1r = -1e30f, l0 = 0.f, l1 = 0.f;
    const uint32_t boff = (uint32_t)((lq >> 1) * 8 + lr) * 144u +
                          (uint32_t)((lq & 1) * 8) * 2u;

#pragma unroll 1
    for (int kt = 0; kt < 32; kt++) {
        if (kt >= 30) asm volatile("cp.async.wait_group 0;" ::: "memory");
        else          asm volatile("cp.async.wait_group 1;" ::: "memory");
        __syncthreads();

        const uint32_t kb = sb + FKV + (uint32_t)(kt & 1) * FBUF;
        const int* mkb = (const int*)(sm + FMK + (kt & 1) * 256);

        // ---- scores: S = Q @ K^T (2-call fp16) ----
        float sc[8][4];
#pragma unroll
        for (int i = 0; i < 8; i++) { sc[i][0] = sc[i][1] = sc[i][2] = sc[i][3] = 0.f; }

#pragma unroll
        for (int ks = 0; ks < 4; ks++) {
            uint32_t kf[4][4];
#pragma unroll
            for (int np = 0; np < 4; np++)
                ldsm4(kf[np], kb + boff + (uint32_t)np * 2304u + ks * 32);
#pragma unroll
            for (int nt = 0; nt < 8; nt++) {
                const uint32_t* b2 = &kf[nt >> 1][(nt & 1) * 2];
                mma_f16(sc[nt], qfh[ks], b2);
                mma_f16(sc[nt], qfl[ks], b2);
            }
        }

        // ---- scale + mask ----
#pragma unroll
        for (int nt = 0; nt < 8; nt++) {
            int c0 = nt * 8 + q * 2;
            int mk0 = mkb[c0], mk1 = mkb[c0 + 1];
            sc[nt][0] = mk0 ? sc[nt][0] * 0.125f : -1e10f;
            sc[nt][1] = mk1 ? sc[nt][1] * 0.125f : -1e10f;
            sc[nt][2] = mk0 ? sc[nt][2] * 0.125f : -1e10f;
            sc[nt][3] = mk1 ? sc[nt][3] * 0.125f : -1e10f;
        }

        // ---- online softmax ----
        float tm0 = -1e30f, tm1 = -1e30f;
#pragma unroll
        for (int nt = 0; nt < 8; nt++) {
            tm0 = fmaxf(tm0, fmaxf(sc[nt][0], sc[nt][1]));
            tm1 = fmaxf(tm1, fmaxf(sc[nt][2], sc[nt][3]));
        }
        tm0 = fmaxf(tm0, __shfl_xor_sync(0xffffffffu, tm0, 1));
        tm0 = fmaxf(tm0, __shfl_xor_sync(0xffffffffu, tm0, 2));
        tm1 = fmaxf(tm1, __shfl_xor_sync(0xffffffffu, tm1, 1));
        tm1 = fmaxf(tm1, __shfl_xor_sync(0xffffffffu, tm1, 2));
        float nm0 = fmaxf(m0r, tm0), nm1 = fmaxf(m1r, tm1);
        float al0 = __expf(m0r - nm0), al1 = __expf(m1r - nm1);
        m0r = nm0; m1r = nm1;
        float rs0 = 0.f, rs1 = 0.f;
#pragma unroll
        for (int nt = 0; nt < 8; nt++) {
            sc[nt][0] = __expf(sc[nt][0] - nm0);
            sc[nt][1] = __expf(sc[nt][1] - nm0);
            sc[nt][2] = __expf(sc[nt][2] - nm1);
            sc[nt][3] = __expf(sc[nt][3] - nm1);
            rs0 += sc[nt][0] + sc[nt][1];
            rs1 += sc[nt][2] + sc[nt][3];
        }
        rs0 += __shfl_xor_sync(0xffffffffu, rs0, 1);
        rs0 += __shfl_xor_sync(0xffffffffu, rs0, 2);
        rs1 += __shfl_xor_sync(0xffffffffu, rs1, 1);
        rs1 += __shfl_xor_sync(0xffffffffu, rs1, 2);
        l0 = l0 * al0 + rs0;
        l1 = l1 * al1 + rs1;
#pragma unroll
        for (int nt = 0; nt < 8; nt++) {
            o[nt][0] *= al0; o[nt][1] *= al0; o[nt][2] *= al1; o[nt][3] *= al1;
        }

        // ---- O += P @ V (V^T tile at kb+9216, 2-call fp16) ----
#pragma unroll
        for (int ks = 0; ks < 4; ks++) {
            const int t0 = 2 * ks, t1 = t0 + 1;
            uint32_t ah[4], apl[4];
            split2h(sc[t0][0], sc[t0][1], ah[0], apl[0]);
            split2h(sc[t0][2], sc[t0][3], ah[1], apl[1]);
            split2h(sc[t1][0], sc[t1][1], ah[2], apl[2]);
            split2h(sc[t1][2], sc[t1][3], ah[3], apl[3]);
            uint32_t vf[4][4];
#pragma unroll
            for (int np = 0; np < 4; np++)
                ldsm4(vf[np], kb + 9216u + boff + (uint32_t)np * 2304u + ks * 32);
#pragma unroll
            for (int nt = 0; nt < 8; nt++) {
                const uint32_t* b2 = &vf[nt >> 1][(nt & 1) * 2];
                mma_f16(o[nt], ah, b2);
                mma_f16(o[nt], apl, b2);
            }
        }
        __syncthreads();
        if (kt + 2 < 32) load_tile(kt + 2, kt & 1);
    }

    float inv0 = 1.f / l0, inv1 = 1.f / l1;
    size_t row0 = (size_t)(b * S_ + q0 + w * 16 + g);
    int colb = h * HD_;
#pragma unroll
    for (int nt = 0; nt < 8; nt++) {
        int col = colb + nt * 8 + q * 2;
        uint32_t hp, lp;
        split2h(o[nt][0] * inv0, o[nt][1] * inv0, hp, lp);
        *(uint32_t*)&g_hh[row0 * D_ + col] = hp;
        *(uint32_t*)&g_hl[row0 * D_ + col] = lp;
        split2h(o[nt][2] * inv1, o[nt][3] * inv1, hp, lp);
        *(uint32_t*)&g_hh[(row0 + 8) * D_ + col] = hp;
        *(uint32_t*)&g_hl[(row0 + 8) * D_ + col] = lp;
    }
}

// ---------------------------------------------------------------------------
extern "C" void kernel_launch(void* const* d_in, const int* in_sizes, int n_in,
                              void* d_out, int out_size)
{
    const float* query = (const float*)d_in[0];
    const float* key   = (const float*)d_in[1];
    const float* value = (const float*)d_in[2];
    const int*   mask  = (const int*)d_in[3];
    const float* Wq = (const float*)d_in[4];
    const float* bq = (const float*)d_in[5];
    const float* Wk = (const float*)d_in[6];
    const float* bk = (const float*)d_in[7];
    const float* Wv = (const float*)d_in[8];
    const float* bv = (const float*)d_in[9];
    const float* Wo = (const float*)d_in[10];
    const float* bo = (const float*)d_in[11];
    float* out = (float*)d_out;

    __half *xqh,*xql,*xkh,*xkl,*xvh,*xvl,*wq,*wk,*wv,*wo,*hh,*hl;
    __half *qh,*ql,*kk,*vv;
    cudaGetSymbolAddress((void**)&xqh, g_xq_h); cudaGetSymbolAddress((void**)&xql, g_xq_l);
    cudaGetSymbolAddress((void**)&xkh, g_xk_h); cudaGetSymbolAddress((void**)&xkl, g_xk_l);
    cudaGetSymbolAddress((void**)&xvh, g_xv_h); cudaGetSymbolAddress((void**)&xvl, g_xv_l);
    cudaGetSymbolAddress((void**)&wq, g_wq);    cudaGetSymbolAddress((void**)&wk, g_wk);
    cudaGetSymbolAddress((void**)&wv, g_wv);    cudaGetSymbolAddress((void**)&wo, g_wo);
    cudaGetSymbolAddress((void**)&qh, g_qh);    cudaGetSymbolAddress((void**)&ql, g_ql);
    cudaGetSymbolAddress((void**)&kk, g_k);     cudaGetSymbolAddress((void**)&vv, g_v);
    cudaGetSymbolAddress((void**)&hh, g_hh);    cudaGetSymbolAddress((void**)&hl, g_hl);

    static int attr_set = 0;
    if (!attr_set) {
        cudaFuncSetAttribute(gemm_mma_kernel<0>,
                             cudaFuncAttributeMaxDynamicSharedMemorySize, GEMM_SMEM);
        cudaFuncSetAttribute(gemm_mma_kernel<1>,
                             cudaFuncAttributeMaxDynamicSharedMemorySize, GEMM_SMEM);
        cudaFuncSetAttribute(gemm_mma_kernel<2>,
                             cudaFuncAttributeMaxDynamicSharedMemorySize, GEMM_SMEM);
        cudaFuncSetAttribute(flash_tc_kernel,
                             cudaFuncAttributeMaxDynamicSharedMemorySize, FLASH_SMEM);
        attr_set = 1;
    }

    const int NX4 = M_ * D_ / 4;
    cvt_all_kernel<<<dim3((NX4 + 255) / 256, 7), 256>>>(
        query, key, value, Wq, Wk, Wv, Wo,
        xqh, xql, xkh, xkl, xvh, xvl, wq, wk, wv, wo);                                   // 0

    dim3 ggrid(D_ / BN, M_ / BM);   // (8, 64)
    gemm_mma_kernel<1><<<ggrid, 256, GEMM_SMEM>>>(xqh, xql, wq, bq, nullptr, qh, ql);    // 1
    gemm_mma_kernel<2><<<ggrid, 256, GEMM_SMEM>>>(xkh, xkl, wk, bk, nullptr, kk, nullptr); // 2
    gemm_mma_kernel<2><<<ggrid, 256, GEMM_SMEM>>>(xvh, xvl, wv, bv, nullptr, vv, nullptr); // 3

    vtrans_kernel<<<dim3(S_ / 64, H_, B_), 256>>>();                                     // 4

    flash_tc_kernel<<<dim3(S_ / 128, H_, B_), 256, FLASH_SMEM>>>(mask);                  // 5

    gemm_mma_kernel<0><<<ggrid, 256, GEMM_SMEM>>>(hh, hl, wo, bo, out, nullptr, nullptr); // 6
}

// round 10
// speedup vs baseline: 2.3007x; 1.1462x over previous
#include <cuda_runtime.h>
#include <cuda_bf16.h>
#include <cuda_fp16.h>
#include <cstdint>

// Problem constants
#define B_  4
#define S_  2048
#define D_  1024
#define H_  16
#define HD_ 64
#define M_  (B_*S_)   // 8192

// ---------------- scratch (__device__ globals) ------------------------------
__device__ __half g_xq_h[(size_t)M_*D_], g_xq_l[(size_t)M_*D_];
__device__ __half g_xk_h[(size_t)M_*D_], g_xk_l[(size_t)M_*D_];
__device__ __half g_xv_h[(size_t)M_*D_], g_xv_l[(size_t)M_*D_];
__device__ __half g_wq[(size_t)D_*D_], g_wk[(size_t)D_*D_];
__device__ __half g_wv[(size_t)D_*D_], g_wo[(size_t)D_*D_];
// projected Q (fp16 hi/lo), K, V (single fp16), head-compact [b,h,s,d]
__device__ __half g_qh[(size_t)M_*D_], g_ql[(size_t)M_*D_];
__device__ __half g_k [(size_t)M_*D_];
__device__ __half g_v [(size_t)M_*D_];
// V transposed [b,h,d,s], single fp16
__device__ __half g_vt[(size_t)M_*D_];
// attention output single fp16 [m][1024]
__device__ __half g_hh[(size_t)M_*D_];

extern __shared__ char dynsmem[];

// ---------------- PTX helpers ------------------------------------------------
__device__ __forceinline__ uint32_t smem_u32(const void* p) {
    uint32_t a;
    asm("{ .reg .u64 t; cvta.to.shared.u64 t, %1; cvt.u32.u64 %0, t; }" : "=r"(a) : "l"(p));
    return a;
}
__device__ __forceinline__ void cp16(uint32_t dst, const void* src) {
    asm volatile("cp.async.cg.shared.global [%0], [%1], 16;" :: "r"(dst), "l"(src) : "memory");
}
__device__ __forceinline__ void cp_commit() {
    asm volatile("cp.async.commit_group;" ::: "memory");
}
__device__ __forceinline__ void ldsm4(uint32_t* r, uint32_t addr) {
    asm volatile("ldmatrix.sync.aligned.m8n8.x4.shared.b16 {%0,%1,%2,%3}, [%4];"
                 : "=r"(r[0]), "=r"(r[1]), "=r"(r[2]), "=r"(r[3]) : "r"(addr));
}
__device__ __forceinline__ void mma_f16(float* d, const uint32_t* a, const uint32_t* b) {
    asm volatile(
        "mma.sync.aligned.m16n8k16.row.col.f32.f16.f16.f32 "
        "{%0,%1,%2,%3}, {%4,%5,%6,%7}, {%8,%9}, {%0,%1,%2,%3};"
        : "+f"(d[0]), "+f"(d[1]), "+f"(d[2]), "+f"(d[3])
        : "r"(a[0]), "r"(a[1]), "r"(a[2]), "r"(a[3]), "r"(b[0]), "r"(b[1]));
}
__device__ __forceinline__ void split2h(float x0, float x1, uint32_t& hp, uint32_t& lp) {
    __half2 h = __floats2half2_rn(x0, x1);
    float2 f = __half22float2(h);
    __half2 l = __floats2half2_rn(x0 - f.x, x1 - f.y);
    hp = *(uint32_t*)&h;
    lp = *(uint32_t*)&l;
}
__device__ __forceinline__ uint32_t pack2h(float x0, float x1) {
    __half2 h = __floats2half2_rn(x0, x1);
    return *(uint32_t*)&h;
}

// ---------------- fused conversion kernel (one launch) -----------------------
__global__ __launch_bounds__(256) void cvt_all_kernel(
    const float* __restrict__ xq, const float* __restrict__ xk, const float* __restrict__ xv,
    const float* __restrict__ Wq, const float* __restrict__ Wk,
    const float* __restrict__ Wv, const float* __restrict__ Wo,
    __half* __restrict__ qh2, __half* __restrict__ ql2,
    __half* __restrict__ kh2, __half* __restrict__ kl2,
    __half* __restrict__ vh2, __half* __restrict__ vl2,
    __half* __restrict__ owq, __half* __restrict__ owk,
    __half* __restrict__ owv, __half* __restrict__ owo)
{
    const int y = blockIdx.y;
    int i = blockIdx.x * blockDim.x + threadIdx.x;
    if (y < 3) {
        const int n4 = M_ * D_ / 4;
        if (i >= n4) return;
        const float* x = y == 0 ? xq : (y == 1 ? xk : xv);
        __half* hh = y == 0 ? qh2 : (y == 1 ? kh2 : vh2);
        __half* ll = y == 0 ? ql2 : (y == 1 ? kl2 : vl2);
        float4 v = ((const float4*)x)[i];
        uint32_t a, b, c, d;
        split2h(v.x, v.y, a, c);
        split2h(v.z, v.w, b, d);
        ((uint2*)hh)[i] = make_uint2(a, b);
        ((uint2*)ll)[i] = make_uint2(c, d);
    } else {
        const int n4 = D_ * D_ / 4;
        if (i >= n4) return;
        const float* w = y == 3 ? Wq : (y == 4 ? Wk : (y == 5 ? Wv : Wo));
        __half* o = y == 3 ? owq : (y == 4 ? owk : (y == 5 ? owv : owo));
        float4 v = ((const float4*)w)[i];
        ((uint2*)o)[i] = make_uint2(pack2h(v.x, v.y), pack2h(v.z, v.w));
    }
}

// ---------------- fp16 GEMM: out = A @ B^T + bias ---------------------------
// SPLIT=2: A = Ahi+Alo (2 MMA calls). SPLIT=1: single A.
// EPI 0: fp32 out [m][D].  EPI 1: fp16 hi/lo head-compact.  EPI 2: fp16 single.
#define BM 128
#define BN 128
#define GBK 32
#define ROWB 80
#define TILEB (128 * ROWB)
#define BUFB  (3 * TILEB)
#define GEMM_SMEM (2 * BUFB)    // 61440

template <int SPLIT>
__device__ __forceinline__ void g2s_chunk(
    uint32_t sbuf, const __half* Ah, const __half* Al, const __half* Bw, int tid)
{
#pragma unroll
    for (int r = 0; r < 2; r++) {
        int c = tid + (r << 8);
        int row = c >> 2, c16 = c & 3;
        uint32_t soff = (uint32_t)row * ROWB + (uint32_t)c16 * 16;
        size_t goff = (size_t)row * D_ + c16 * 8;
        cp16(sbuf + 0 * TILEB + soff, Ah + goff);
        if (SPLIT == 2) cp16(sbuf + 1 * TILEB + soff, Al + goff);
        cp16(sbuf + 2 * TILEB + soff, Bw + goff);
    }
}

template <int EPI, int SPLIT>
__global__ __launch_bounds__(256) void gemm_mma_kernel(
    const __half* __restrict__ Ahi, const __half* __restrict__ Alo,
    const __half* __restrict__ Bw,
    const float* __restrict__ bias, float* __restrict__ out,
    __half* __restrict__ outh, __half* __restrict__ outl)
{
    const uint32_t sb = smem_u32(dynsmem);
    const int tid = threadIdx.x, wid = tid >> 5, lane = tid & 31;
    const int wm = wid >> 2, wn = wid & 3;
    const int n0 = blockIdx.x * BN, m0 = blockIdx.y * BM;

    const __half* Ah = Ahi + (size_t)m0 * D_;
    const __half* Al = SPLIT == 2 ? Alo + (size_t)m0 * D_ : nullptr;
    const __half* Bp = Bw + (size_t)n0 * D_;

    float acc[4][4][4];
#pragma unroll
    for (int i = 0; i < 4; i++)
#pragma unroll
        for (int j = 0; j < 4; j++)
#pragma unroll
            for (int k = 0; k < 4; k++) acc[i][j][k] = 0.f;

    g2s_chunk<SPLIT>(sb,        Ah,       Al,                          Bp,       tid); cp_commit();
    g2s_chunk<SPLIT>(sb + BUFB, Ah + GBK, SPLIT == 2 ? Al + GBK : Al, Bp + GBK, tid); cp_commit();

    const int lr = lane & 7, lq = lane >> 3;
    const uint32_t a_base_off =
        (uint32_t)(wm * 64 + (lq & 1) * 8 + lr) * ROWB + (uint32_t)((lq >> 1) * 8) * 2;
    const uint32_t b_base_off =
        (uint32_t)(wn * 32 + (lq >> 1) * 8 + lr) * ROWB + (uint32_t)((lq & 1) * 8) * 2;

    const int NCHUNK = D_ / GBK;
#pragma unroll 1
    for (int c = 0; c < NCHUNK; c++) {
        if (c >= NCHUNK - 2) asm volatile("cp.async.wait_group 0;" ::: "memory");
        else                 asm volatile("cp.async.wait_group 1;" ::: "memory");
        __syncthreads();

        const uint32_t buf = sb + (uint32_t)(c & 1) * BUFB;
        const uint32_t sAh = buf, sAl = buf + TILEB, sB = buf + 2 * TILEB;

#pragma unroll
        for (int ks = 0; ks < 2; ks++) {
            const uint32_t ko = (uint32_t)(ks * 16) * 2;
            uint32_t ahr[4][4], alr[4][4], br[2][4];
#pragma unroll
            for (int mt = 0; mt < 4; mt++) {
                ldsm4(ahr[mt], sAh + a_base_off + ko + (uint32_t)mt * (16 * ROWB));
                if (SPLIT == 2)
                    ldsm4(alr[mt], sAl + a_base_off + ko + (uint32_t)mt * (16 * ROWB));
            }
#pragma unroll
            for (int np = 0; np < 2; np++)
                ldsm4(br[np], sB + b_base_off + ko + (uint32_t)np * (16 * ROWB));
#pragma unroll
            for (int mt = 0; mt < 4; mt++)
#pragma unroll
                for (int nt = 0; nt < 4; nt++) {
                    const uint32_t* b2 = &br[nt >> 1][(nt & 1) * 2];
                    mma_f16(acc[mt][nt], ahr[mt], b2);
                    if (SPLIT == 2) mma_f16(acc[mt][nt], alr[mt], b2);
                }
        }
        __syncthreads();

        if (c + 2 < NCHUNK) {
            const int kc = (c + 2) * GBK;
            g2s_chunk<SPLIT>(sb + (uint32_t)(c & 1) * BUFB,
                             Ah + kc, SPLIT == 2 ? Al + kc : Al, Bp + kc, tid);
            cp_commit();
        }
    }

    const int g = lane >> 2, tq = lane & 3;
#pragma unroll
    for (int mt = 0; mt < 4; mt++) {
#pragma unroll
        for (int nt = 0; nt < 4; nt++) {
            int row = m0 + wm * 64 + mt * 16 + g;
            int col = n0 + wn * 32 + nt * 8 + tq * 2;
            float2 bv = *(const float2*)&bias[col];
            float v0 = acc[mt][nt][0] + bv.x, v1 = acc[mt][nt][1] + bv.y;
            float v2 = acc[mt][nt][2] + bv.x, v3 = acc[mt][nt][3] + bv.y;
            if (EPI == 0) {
                *(float2*)&out[(size_t)row * D_ + col]       = make_float2(v0, v1);
                *(float2*)&out[(size_t)(row + 8) * D_ + col] = make_float2(v2, v3);
            } else {
                int bb = row >> 11, s = row & 2047, hh = col >> 6, d = col & 63;
                size_t i0 = ((size_t)(bb * H_ + hh) * S_ + s) * HD_ + d;
                size_t i1 = i0 + 8 * HD_;
                if (EPI == 1) {
                    uint32_t hp, lp;
                    split2h(v0, v1, hp, lp);
                    *(uint32_t*)&outh[i0] = hp; *(uint32_t*)&outl[i0] = lp;
                    split2h(v2, v3, hp, lp);
                    *(uint32_t*)&outh[i1] = hp; *(uint32_t*)&outl[i1] = lp;
                } else {
                    *(uint32_t*)&outh[i0] = pack2h(v0, v1);
                    *(uint32_t*)&outh[i1] = pack2h(v2, v3);
                }
            }
        }
    }
}

// ---------------- V transpose: [b,h,s,d] -> [b,h,d,s] (single fp16) ---------
__global__ __launch_bounds__(256) void vtrans_kernel()
{
    __shared__ __align__(16) unsigned short ts[64 * 66];
    const int b = blockIdx.z, h = blockIdx.y, st = blockIdx.x;
    const int bh = b * H_ + h;
    const int s0 = st * 64;
    const int tid = threadIdx.x;

    const uint32_t* src = (const uint32_t*)(g_v + ((size_t)bh * S_ + s0) * HD_);
#pragma unroll
    for (int i = 0; i < 8; i++) {
        int flat = tid + i * 256;
        int r = flat >> 5, c2 = flat & 31;
        *(uint32_t*)&ts[r * 66 + c2 * 2] = src[r * 32 + c2];
    }
    __syncthreads();
    uint32_t* dst = (uint32_t*)(g_vt + (size_t)bh * HD_ * S_ + s0);
#pragma unroll
    for (int i = 0; i < 8; i++) {
        int flat = tid + i * 256;
        int d = flat >> 5, sp = flat & 31;
        uint32_t v = (uint32_t)ts[(2 * sp) * 66 + d] |
                     ((uint32_t)ts[(2 * sp + 1) * 66 + d] << 16);
        dst[(size_t)d * (S_ / 2) + sp] = v;
    }
}

// ---------------- tensor-core flash attention --------------------------------
// QK: (Qh+Ql fp16) x K.  PV: single-P fp16 x V^T.  Softmax in log2 domain.
#define FQ_H 0u
#define FQ_L 18432u
#define FKV  36864u
#define FBUF 18432u
#define FMK  73728u
#define FLASH_SMEM 74240

// 0.125 * log2(e)
#define SCALE_L2E 0.18033688011112042f

__global__ __launch_bounds__(256) void flash_tc_kernel(const int* __restrict__ mask)
{
    char* sm = dynsmem;
    const uint32_t sb = smem_u32(sm);
    const int tid = threadIdx.x, w = tid >> 5, lane = tid & 31;
    const int lr = lane & 7, lq = lane >> 3, g = lane >> 2, q = lane & 3;
    const int b = blockIdx.z, h = blockIdx.y;
    const int bh = b * H_ + h;
    const int q0 = blockIdx.x * 128;

    const __half* Qhp = g_qh + ((size_t)bh * S_ + q0) * HD_;
    const __half* Qlp = g_ql + ((size_t)bh * S_ + q0) * HD_;
    const __half* Kp  = g_k  + (size_t)bh * S_ * HD_;
    const __half* Vtp = g_vt + (size_t)bh * HD_ * S_;
    const int* mg = mask + b * S_;

    {
        int r = tid >> 1, half = tid & 1;
        const __half* src = (half ? Qlp : Qhp) + (size_t)r * HD_;
        uint32_t dst = sb + (half ? FQ_L : FQ_H) + (uint32_t)r * 144u;
#pragma unroll
        for (int j = 0; j < 8; j++) cp16(dst + j * 16, src + j * 8);
    }
    cp_commit();

    auto load_tile = [&](int kt, int buf) {
        int k0 = kt * 64;
        int which = tid & 1;
        int halfr = (tid >> 1) & 1;
        int r = tid >> 2;
        uint32_t dst = sb + FKV + (uint32_t)buf * FBUF + (uint32_t)which * 9216u +
                       (uint32_t)r * 144u + (uint32_t)halfr * 64u;
        const __half* src = which ? (Vtp + (size_t)r * S_ + k0 + halfr * 32)
                                  : (Kp + (size_t)(k0 + r) * HD_ + halfr * 32);
#pragma unroll
        for (int j = 0; j < 4; j++) cp16(dst + j * 16, src + j * 8);
        if (tid < 16) cp16(sb + FMK + (uint32_t)buf * 256u + tid * 16, mg + k0 + tid * 4);
        cp_commit();
    };
    load_tile(0, 0);
    load_tile(1, 1);

    asm volatile("cp.async.wait_group 2;" ::: "memory");
    __syncthreads();

    uint32_t qfh[4][4], qfl[4][4];
    {
        uint32_t aoff = (uint32_t)(w * 16 + (lq & 1) * 8 + lr) * 144u +
                        (uint32_t)((lq >> 1) * 8) * 2u;
#pragma unroll
        for (int ks = 0; ks < 4; ks++) {
            ldsm4(qfh[ks], sb + FQ_H + aoff + ks * 32);
            ldsm4(qfl[ks], sb + FQ_L + aoff + ks * 32);
        }
    }

    float o[8][4];
#pragma unroll
    for (int i = 0; i < 8; i++) { o[i][0] = o[i][1] = o[i][2] = o[i][3] = 0.f; }
    float m0r = -1e30f, m1r = -1e30f, l0 = 0.f, l1 = 0.f;
    const uint32_t boff = (uint32_t)((lq >> 1) * 8 + lr) * 144u +
                          (uint32_t)((lq & 1) * 8) * 2u;

#pragma unroll 1
    for (int kt = 0; kt < 32; kt++) {
        if (kt >= 30) asm volatile("cp.async.wait_group 0;" ::: "memory");
        else          asm volatile("cp.async.wait_group 1;" ::: "memory");
        __syncthreads();

        const uint32_t kb = sb + FKV + (uint32_t)(kt & 1) * FBUF;
        const int* mkb = (const int*)(sm + FMK + (kt & 1) * 256);

        // ---- scores in log2 domain: s~ = (q.k/8)*log2e ----
        float sc[8][4];
#pragma unroll
        for (int i = 0; i < 8; i++) { sc[i][0] = sc[i][1] = sc[i][2] = sc[i][3] = 0.f; }

#pragma unroll
        for (int ks = 0; ks < 4; ks++) {
            uint32_t kf[4][4];
#pragma unroll
            for (int np = 0; np < 4; np++)
                ldsm4(kf[np], kb + boff + (uint32_t)np * 2304u + ks * 32);
#pragma unroll
            for (int nt = 0; nt < 8; nt++) {
                const uint32_t* b2 = &kf[nt >> 1][(nt & 1) * 2];
                mma_f16(sc[nt], qfh[ks], b2);
                mma_f16(sc[nt], qfl[ks], b2);
            }
        }

#pragma unroll
        for (int nt = 0; nt < 8; nt++) {
            int c0 = nt * 8 + q * 2;
            int mk0 = mkb[c0], mk1 = mkb[c0 + 1];
            sc[nt][0] = mk0 ? sc[nt][0] * SCALE_L2E : -1e10f;
            sc[nt][1] = mk1 ? sc[nt][1] * SCALE_L2E : -1e10f;
            sc[nt][2] = mk0 ? sc[nt][2] * SCALE_L2E : -1e10f;
            sc[nt][3] = mk1 ? sc[nt][3] * SCALE_L2E : -1e10f;
        }

        // ---- online softmax (log2 domain; exp2f) ----
        float tm0 = -1e30f, tm1 = -1e30f;
#pragma unroll
        for (int nt = 0; nt < 8; nt++) {
            tm0 = fmaxf(tm0, fmaxf(sc[nt][0], sc[nt][1]));
            tm1 = fmaxf(tm1, fmaxf(sc[nt][2], sc[nt][3]));
        }
        tm0 = fmaxf(tm0, __shfl_xor_sync(0xffffffffu, tm0, 1));
        tm0 = fmaxf(tm0, __shfl_xor_sync(0xffffffffu, tm0, 2));
        tm1 = fmaxf(tm1, __shfl_xor_sync(0xffffffffu, tm1, 1));
        tm1 = fmaxf(tm1, __shfl_xor_sync(0xffffffffu, tm1, 2));
        float nm0 = fmaxf(m0r, tm0), nm1 = fmaxf(m1r, tm1);
        float al0 = exp2f(m0r - nm0), al1 = exp2f(m1r - nm1);
        m0r = nm0; m1r = nm1;
        float rs0 = 0.f, rs1 = 0.f;
#pragma unroll
        for (int nt = 0; nt < 8; nt++) {
            sc[nt][0] = exp2f(sc[nt][0] - nm0);
            sc[nt][1] = exp2f(sc[nt][1] - nm0);
            sc[nt][2] = exp2f(sc[nt][2] - nm1);
            sc[nt][3] = exp2f(sc[nt][3] - nm1);
            rs0 += sc[nt][0] + sc[nt][1];
            rs1 += sc[nt][2] + sc[nt][3];
        }
        rs0 += __shfl_xor_sync(0xffffffffu, rs0, 1);
        rs0 += __shfl_xor_sync(0xffffffffu, rs0, 2);
        rs1 += __shfl_xor_sync(0xffffffffu, rs1, 1);
        rs1 += __shfl_xor_sync(0xffffffffu, rs1, 2);
        l0 = l0 * al0 + rs0;
        l1 = l1 * al1 + rs1;
#pragma unroll
        for (int nt = 0; nt < 8; nt++) {
            o[nt][0] *= al0; o[nt][1] *= al0; o[nt][2] *= al1; o[nt][3] *= al1;
        }

        // ---- O += P @ V (single-P fp16) ----
#pragma unroll
        for (int ks = 0; ks < 4; ks++) {
            const int t0 = 2 * ks, t1 = t0 + 1;
            uint32_t ah[4];
            ah[0] = pack2h(sc[t0][0], sc[t0][1]);
            ah[1] = pack2h(sc[t0][2], sc[t0][3]);
            ah[2] = pack2h(sc[t1][0], sc[t1][1]);
            ah[3] = pack2h(sc[t1][2], sc[t1][3]);
            uint32_t vf[4][4];
#pragma unroll
            for (int np = 0; np < 4; np++)
                ldsm4(vf[np], kb + 9216u + boff + (uint32_t)np * 2304u + ks * 32);
#pragma unroll
            for (int nt = 0; nt < 8; nt++)
                mma_f16(o[nt], ah, &vf[nt >> 1][(nt & 1) * 2]);
        }
        __syncthreads();
        if (kt + 2 < 32) load_tile(kt + 2, kt & 1);
    }

    float inv0 = 1.f / l0, inv1 = 1.f / l1;
    size_t row0 = (size_t)(b * S_ + q0 + w * 16 + g);
    int colb = h * HD_;
#pragma unroll
    for (int nt = 0; nt < 8; nt++) {
        int col = colb + nt * 8 + q * 2;
        *(uint32_t*)&g_hh[row0 * D_ + col] = pack2h(o[nt][0] * inv0, o[nt][1] * inv0);
        *(uint32_t*)&g_hh[(row0 + 8) * D_ + col] = pack2h(o[nt][2] * inv1, o[nt][3] * inv1);
    }
}

// ---------------------------------------------------------------------------
extern "C" void kernel_launch(void* const* d_in, const int* in_sizes, int n_in,
                              void* d_out, int out_size)
{
    const float* query = (const float*)d_in[0];
    const float* key   = (const float*)d_in[1];
    const float* value = (const float*)d_in[2];
    const int*   mask  = (const int*)d_in[3];
    const float* Wq = (const float*)d_in[4];
    const float* bq = (const float*)d_in[5];
    const float* Wk = (const float*)d_in[6];
    const float* bk = (const float*)d_in[7];
    const float* Wv = (const float*)d_in[8];
    const float* bv = (const float*)d_in[9];
    const float* Wo = (const float*)d_in[10];
    const float* bo = (const float*)d_in[11];
    float* out = (float*)d_out;

    __half *xqh,*xql,*xkh,*xkl,*xvh,*xvl,*wq,*wk,*wv,*wo,*hh;
    __half *qh,*ql,*kk,*vv;
    cudaGetSymbolAddress((void**)&xqh, g_xq_h); cudaGetSymbolAddress((void**)&xql, g_xq_l);
    cudaGetSymbolAddress((void**)&xkh, g_xk_h); cudaGetSymbolAddress((void**)&xkl, g_xk_l);
    cudaGetSymbolAddress((void**)&xvh, g_xv_h); cudaGetSymbolAddress((void**)&xvl, g_xv_l);
    cudaGetSymbolAddress((void**)&wq, g_wq);    cudaGetSymbolAddress((void**)&wk, g_wk);
    cudaGetSymbolAddress((void**)&wv, g_wv);    cudaGetSymbolAddress((void**)&wo, g_wo);
    cudaGetSymbolAddress((void**)&qh, g_qh);    cudaGetSymbolAddress((void**)&ql, g_ql);
    cudaGetSymbolAddress((void**)&kk, g_k);     cudaGetSymbolAddress((void**)&vv, g_v);
    cudaGetSymbolAddress((void**)&hh, g_hh);

    static int attr_set = 0;
    if (!attr_set) {
        cudaFuncSetAttribute((const void*)gemm_mma_kernel<0,1>,
                             cudaFuncAttributeMaxDynamicSharedMemorySize, GEMM_SMEM);
        cudaFuncSetAttribute((const void*)gemm_mma_kernel<1,2>,
                             cudaFuncAttributeMaxDynamicSharedMemorySize, GEMM_SMEM);
        cudaFuncSetAttribute((const void*)gemm_mma_kernel<2,2>,
                             cudaFuncAttributeMaxDynamicSharedMemorySize, GEMM_SMEM);
        cudaFuncSetAttribute((const void*)flash_tc_kernel,
                             cudaFuncAttributeMaxDynamicSharedMemorySize, FLASH_SMEM);
        attr_set = 1;
    }

    const int NX4 = M_ * D_ / 4;
    cvt_all_kernel<<<dim3((NX4 + 255) / 256, 7), 256>>>(
        query, key, value, Wq, Wk, Wv, Wo,
        xqh, xql, xkh, xkl, xvh, xvl, wq, wk, wv, wo);                                     // 0

    dim3 ggrid(D_ / BN, M_ / BM);   // (8, 64)
    gemm_mma_kernel<1,2><<<ggrid, 256, GEMM_SMEM>>>(xqh, xql, wq, bq, nullptr, qh, ql);    // 1
    gemm_mma_kernel<2,2><<<ggrid, 256, GEMM_SMEM>>>(xkh, xkl, wk, bk, nullptr, kk, nullptr); // 2
    gemm_mma_kernel<2,2><<<ggrid, 256, GEMM_SMEM>>>(xvh, xvl, wv, bv, nullptr, vv, nullptr); // 3

    vtrans_kernel<<<dim3(S_ / 64, H_, B_), 256>>>();                                       // 4

    flash_tc_kernel<<<dim3(S_ / 128, H_, B_), 256, FLASH_SMEM>>>(mask);                    // 5

    gemm_mma_kernel<0,1><<<ggrid, 256, GEMM_SMEM>>>(hh, nullptr, wo, bo, out, nullptr, nullptr); // 6
}

// round 11
// speedup vs baseline: 2.7400x; 1.1909x over previous
#include <cuda_runtime.h>
#include <cuda_bf16.h>
#include <cuda_fp16.h>
#include <cstdint>

// Problem constants
#define B_  4
#define S_  2048
#define D_  1024
#define H_  16
#define HD_ 64
#define M_  (B_*S_)   // 8192

// ---------------- scratch (__device__ globals) ------------------------------
__device__ __half g_xq_h[(size_t)M_*D_], g_xq_l[(size_t)M_*D_];
__device__ __half g_xk_h[(size_t)M_*D_], g_xk_l[(size_t)M_*D_];
__device__ __half g_xv_h[(size_t)M_*D_], g_xv_l[(size_t)M_*D_];
__device__ __half g_wq[(size_t)D_*D_], g_wk[(size_t)D_*D_];
__device__ __half g_wv[(size_t)D_*D_], g_wo[(size_t)D_*D_];
// projected Q (pre-scaled by 0.125*log2e), K, V — single fp16, [b,h,s,d]
__device__ __half g_q [(size_t)M_*D_];
__device__ __half g_k [(size_t)M_*D_];
__device__ __half g_v [(size_t)M_*D_];
// V transposed [b,h,d,s], single fp16
__device__ __half g_vt[(size_t)M_*D_];
// attention output single fp16 [m][1024]
__device__ __half g_hh[(size_t)M_*D_];

extern __shared__ char dynsmem[];

// 0.125 * log2(e)
#define SCALE_L2E 0.18033688011112042f

// ---------------- PTX helpers ------------------------------------------------
__device__ __forceinline__ uint32_t smem_u32(const void* p) {
    uint32_t a;
    asm("{ .reg .u64 t; cvta.to.shared.u64 t, %1; cvt.u32.u64 %0, t; }" : "=r"(a) : "l"(p));
    return a;
}
__device__ __forceinline__ void cp16(uint32_t dst, const void* src) {
    asm volatile("cp.async.cg.shared.global [%0], [%1], 16;" :: "r"(dst), "l"(src) : "memory");
}
__device__ __forceinline__ void cp_commit() {
    asm volatile("cp.async.commit_group;" ::: "memory");
}
__device__ __forceinline__ void ldsm4(uint32_t* r, uint32_t addr) {
    asm volatile("ldmatrix.sync.aligned.m8n8.x4.shared.b16 {%0,%1,%2,%3}, [%4];"
                 : "=r"(r[0]), "=r"(r[1]), "=r"(r[2]), "=r"(r[3]) : "r"(addr));
}
__device__ __forceinline__ void mma_f16(float* d, const uint32_t* a, const uint32_t* b) {
    asm volatile(
        "mma.sync.aligned.m16n8k16.row.col.f32.f16.f16.f32 "
        "{%0,%1,%2,%3}, {%4,%5,%6,%7}, {%8,%9}, {%0,%1,%2,%3};"
        : "+f"(d[0]), "+f"(d[1]), "+f"(d[2]), "+f"(d[3])
        : "r"(a[0]), "r"(a[1]), "r"(a[2]), "r"(a[3]), "r"(b[0]), "r"(b[1]));
}
__device__ __forceinline__ void split2h(float x0, float x1, uint32_t& hp, uint32_t& lp) {
    __half2 h = __floats2half2_rn(x0, x1);
    float2 f = __half22float2(h);
    __half2 l = __floats2half2_rn(x0 - f.x, x1 - f.y);
    hp = *(uint32_t*)&h;
    lp = *(uint32_t*)&l;
}
__device__ __forceinline__ uint32_t pack2h(float x0, float x1) {
    __half2 h = __floats2half2_rn(x0, x1);
    return *(uint32_t*)&h;
}

// ---------------- fused conversion kernel (one launch) -----------------------
__global__ __launch_bounds__(256) void cvt_all_kernel(
    const float* __restrict__ xq, const float* __restrict__ xk, const float* __restrict__ xv,
    const float* __restrict__ Wq, const float* __restrict__ Wk,
    const float* __restrict__ Wv, const float* __restrict__ Wo,
    __half* __restrict__ qh2, __half* __restrict__ ql2,
    __half* __restrict__ kh2, __half* __restrict__ kl2,
    __half* __restrict__ vh2, __half* __restrict__ vl2,
    __half* __restrict__ owq, __half* __restrict__ owk,
    __half* __restrict__ owv, __half* __restrict__ owo)
{
    const int y = blockIdx.y;
    int i = blockIdx.x * blockDim.x + threadIdx.x;
    if (y < 3) {
        const int n4 = M_ * D_ / 4;
        if (i >= n4) return;
        const float* x = y == 0 ? xq : (y == 1 ? xk : xv);
        __half* hh = y == 0 ? qh2 : (y == 1 ? kh2 : vh2);
        __half* ll = y == 0 ? ql2 : (y == 1 ? kl2 : vl2);
        float4 v = ((const float4*)x)[i];
        uint32_t a, b, c, d;
        split2h(v.x, v.y, a, c);
        split2h(v.z, v.w, b, d);
        ((uint2*)hh)[i] = make_uint2(a, b);
        ((uint2*)ll)[i] = make_uint2(c, d);
    } else {
        const int n4 = D_ * D_ / 4;
        if (i >= n4) return;
        const float* w = y == 3 ? Wq : (y == 4 ? Wk : (y == 5 ? Wv : Wo));
        __half* o = y == 3 ? owq : (y == 4 ? owk : (y == 5 ? owv : owo));
        float4 v = ((const float4*)w)[i];
        ((uint2*)o)[i] = make_uint2(pack2h(v.x, v.y), pack2h(v.z, v.w));
    }
}

// ---------------- fp16 GEMM building blocks ---------------------------------
#define BM 128
#define BN 128
#define GBK 32
#define ROWB 80
#define TILEB (128 * ROWB)
#define BUFB  (3 * TILEB)
#define GEMM_SMEM (2 * BUFB)    // 61440

template <int SPLIT>
__device__ __forceinline__ void g2s_chunk(
    uint32_t sbuf, const __half* Ah, const __half* Al, const __half* Bw, int tid)
{
#pragma unroll
    for (int r = 0; r < 2; r++) {
        int c = tid + (r << 8);
        int row = c >> 2, c16 = c & 3;
        uint32_t soff = (uint32_t)row * ROWB + (uint32_t)c16 * 16;
        size_t goff = (size_t)row * D_ + c16 * 8;
        cp16(sbuf + 0 * TILEB + soff, Ah + goff);
        if (SPLIT == 2) cp16(sbuf + 1 * TILEB + soff, Al + goff);
        cp16(sbuf + 2 * TILEB + soff, Bw + goff);
    }
}

// mainloop shared by both GEMM kernels; leaves acc filled
template <int SPLIT>
__device__ __forceinline__ void gemm_mainloop(
    uint32_t sb, const __half* Ah, const __half* Al, const __half* Bp,
    int tid, int lane, int wm, int wn, float acc[4][4][4])
{
#pragma unroll
    for (int i = 0; i < 4; i++)
#pragma unroll
        for (int j = 0; j < 4; j++)
#pragma unroll
            for (int k = 0; k < 4; k++) acc[i][j][k] = 0.f;

    g2s_chunk<SPLIT>(sb,        Ah,       Al,                          Bp,       tid); cp_commit();
    g2s_chunk<SPLIT>(sb + BUFB, Ah + GBK, SPLIT == 2 ? Al + GBK : Al, Bp + GBK, tid); cp_commit();

    const int lr = lane & 7, lq = lane >> 3;
    const uint32_t a_base_off =
        (uint32_t)(wm * 64 + (lq & 1) * 8 + lr) * ROWB + (uint32_t)((lq >> 1) * 8) * 2;
    const uint32_t b_base_off =
        (uint32_t)(wn * 32 + (lq >> 1) * 8 + lr) * ROWB + (uint32_t)((lq & 1) * 8) * 2;

    const int NCHUNK = D_ / GBK;
#pragma unroll 1
    for (int c = 0; c < NCHUNK; c++) {
        if (c >= NCHUNK - 2) asm volatile("cp.async.wait_group 0;" ::: "memory");
        else                 asm volatile("cp.async.wait_group 1;" ::: "memory");
        __syncthreads();

        const uint32_t buf = sb + (uint32_t)(c & 1) * BUFB;
        const uint32_t sAh = buf, sAl = buf + TILEB, sB = buf + 2 * TILEB;

#pragma unroll
        for (int ks = 0; ks < 2; ks++) {
            const uint32_t ko = (uint32_t)(ks * 16) * 2;
            uint32_t ahr[4][4], alr[4][4], br[2][4];
#pragma unroll
            for (int mt = 0; mt < 4; mt++) {
                ldsm4(ahr[mt], sAh + a_base_off + ko + (uint32_t)mt * (16 * ROWB));
                if (SPLIT == 2)
                    ldsm4(alr[mt], sAl + a_base_off + ko + (uint32_t)mt * (16 * ROWB));
            }
#pragma unroll
            for (int np = 0; np < 2; np++)
                ldsm4(br[np], sB + b_base_off + ko + (uint32_t)np * (16 * ROWB));
#pragma unroll
            for (int mt = 0; mt < 4; mt++)
#pragma unroll
                for (int nt = 0; nt < 4; nt++) {
                    const uint32_t* b2 = &br[nt >> 1][(nt & 1) * 2];
                    mma_f16(acc[mt][nt], ahr[mt], b2);
                    if (SPLIT == 2) mma_f16(acc[mt][nt], alr[mt], b2);
                }
        }
        __syncthreads();

        if (c + 2 < NCHUNK) {
            const int kc = (c + 2) * GBK;
            g2s_chunk<SPLIT>(sb + (uint32_t)(c & 1) * BUFB,
                             Ah + kc, SPLIT == 2 ? Al + kc : Al, Bp + kc, tid);
            cp_commit();
        }
    }
}

// Fused projection GEMM: grid.z selects (X, W, bias, out, scale).
// out = ((X @ W^T) + bias) * scale, single fp16, head-compact [b,h,s,d].
__global__ __launch_bounds__(256) void gemm_proj_kernel(
    const __half* __restrict__ xqh, const __half* __restrict__ xql,
    const __half* __restrict__ xkh, const __half* __restrict__ xkl,
    const __half* __restrict__ xvh, const __half* __restrict__ xvl,
    const __half* __restrict__ wq, const __half* __restrict__ wk,
    const __half* __restrict__ wv,
    const float* __restrict__ bq, const float* __restrict__ bk,
    const float* __restrict__ bv,
    __half* __restrict__ oq, __half* __restrict__ ok, __half* __restrict__ ov)
{
    const uint32_t sb = smem_u32(dynsmem);
    const int tid = threadIdx.x, wid = tid >> 5, lane = tid & 31;
    const int wm = wid >> 2, wn = wid & 3;
    const int n0 = blockIdx.x * BN, m0 = blockIdx.y * BM;
    const int z = blockIdx.z;

    const __half* Ahb = z == 0 ? xqh : (z == 1 ? xkh : xvh);
    const __half* Alb = z == 0 ? xql : (z == 1 ? xkl : xvl);
    const __half* Wb  = z == 0 ? wq  : (z == 1 ? wk  : wv);
    const float* bias = z == 0 ? bq  : (z == 1 ? bk  : bv);
    __half* outp      = z == 0 ? oq  : (z == 1 ? ok  : ov);
    const float oscale = z == 0 ? SCALE_L2E : 1.0f;

    float acc[4][4][4];
    gemm_mainloop<2>(sb, Ahb + (size_t)m0 * D_, Alb + (size_t)m0 * D_,
                     Wb + (size_t)n0 * D_, tid, lane, wm, wn, acc);

    const int g = lane >> 2, tq = lane & 3;
#pragma unroll
    for (int mt = 0; mt < 4; mt++) {
#pragma unroll
        for (int nt = 0; nt < 4; nt++) {
            int row = m0 + wm * 64 + mt * 16 + g;
            int col = n0 + wn * 32 + nt * 8 + tq * 2;
            float2 bv2 = *(const float2*)&bias[col];
            float v0 = (acc[mt][nt][0] + bv2.x) * oscale;
            float v1 = (acc[mt][nt][1] + bv2.y) * oscale;
            float v2 = (acc[mt][nt][2] + bv2.x) * oscale;
            float v3 = (acc[mt][nt][3] + bv2.y) * oscale;
            int bb = row >> 11, s = row & 2047, hh = col >> 6, d = col & 63;
            size_t i0 = ((size_t)(bb * H_ + hh) * S_ + s) * HD_ + d;
            size_t i1 = i0 + 8 * HD_;
            *(uint32_t*)&outp[i0] = pack2h(v0, v1);
            *(uint32_t*)&outp[i1] = pack2h(v2, v3);
        }
    }
}

// Final GEMM: single-A fp16, fp32 out.
__global__ __launch_bounds__(256) void gemm_out_kernel(
    const __half* __restrict__ Ahi, const __half* __restrict__ Bw,
    const float* __restrict__ bias, float* __restrict__ out)
{
    const uint32_t sb = smem_u32(dynsmem);
    const int tid = threadIdx.x, wid = tid >> 5, lane = tid & 31;
    const int wm = wid >> 2, wn = wid & 3;
    const int n0 = blockIdx.x * BN, m0 = blockIdx.y * BM;

    float acc[4][4][4];
    gemm_mainloop<1>(sb, Ahi + (size_t)m0 * D_, nullptr,
                     Bw + (size_t)n0 * D_, tid, lane, wm, wn, acc);

    const int g = lane >> 2, tq = lane & 3;
#pragma unroll
    for (int mt = 0; mt < 4; mt++) {
#pragma unroll
        for (int nt = 0; nt < 4; nt++) {
            int row = m0 + wm * 64 + mt * 16 + g;
            int col = n0 + wn * 32 + nt * 8 + tq * 2;
            float2 bv2 = *(const float2*)&bias[col];
            *(float2*)&out[(size_t)row * D_ + col] =
                make_float2(acc[mt][nt][0] + bv2.x, acc[mt][nt][1] + bv2.y);
            *(float2*)&out[(size_t)(row + 8) * D_ + col] =
                make_float2(acc[mt][nt][2] + bv2.x, acc[mt][nt][3] + bv2.y);
        }
    }
}

// ---------------- V transpose: [b,h,s,d] -> [b,h,d,s] (single fp16) ---------
__global__ __launch_bounds__(256) void vtrans_kernel()
{
    __shared__ __align__(16) unsigned short ts[64 * 66];
    const int b = blockIdx.z, h = blockIdx.y, st = blockIdx.x;
    const int bh = b * H_ + h;
    const int s0 = st * 64;
    const int tid = threadIdx.x;

    const uint32_t* src = (const uint32_t*)(g_v + ((size_t)bh * S_ + s0) * HD_);
#pragma unroll
    for (int i = 0; i < 8; i++) {
        int flat = tid + i * 256;
        int r = flat >> 5, c2 = flat & 31;
        *(uint32_t*)&ts[r * 66 + c2 * 2] = src[r * 32 + c2];
    }
    __syncthreads();
    uint32_t* dst = (uint32_t*)(g_vt + (size_t)bh * HD_ * S_ + s0);
#pragma unroll
    for (int i = 0; i < 8; i++) {
        int flat = tid + i * 256;
        int d = flat >> 5, sp = flat & 31;
        uint32_t v = (uint32_t)ts[(2 * sp) * 66 + d] |
                     ((uint32_t)ts[(2 * sp + 1) * 66 + d] << 16);
        dst[(size_t)d * (S_ / 2) + sp] = v;
    }
}

// ---------------- tensor-core flash attention --------------------------------
// QK: single-Q (pre-scaled) x K, 1 call. PV: single-P x V^T, 1 call.
#define FQ   0u
#define FKV  18432u
#define FBUF 18432u
#define FMK  55296u
#define FLASH_SMEM 55808

__global__ __launch_bounds__(256) void flash_tc_kernel(const int* __restrict__ mask)
{
    char* sm = dynsmem;
    const uint32_t sb = smem_u32(sm);
    const int tid = threadIdx.x, w = tid >> 5, lane = tid & 31;
    const int lr = lane & 7, lq = lane >> 3, g = lane >> 2, q = lane & 3;
    const int b = blockIdx.z, h = blockIdx.y;
    const int bh = b * H_ + h;
    const int q0 = blockIdx.x * 128;

    const __half* Qp  = g_q  + ((size_t)bh * S_ + q0) * HD_;
    const __half* Kp  = g_k  + (size_t)bh * S_ * HD_;
    const __half* Vtp = g_vt + (size_t)bh * HD_ * S_;
    const int* mg = mask + b * S_;

    {
        int r = tid >> 1, halfr = tid & 1;
        const __half* src = Qp + (size_t)r * HD_ + halfr * 32;
        uint32_t dst = sb + FQ + (uint32_t)r * 144u + (uint32_t)halfr * 64u;
#pragma unroll
        for (int j = 0; j < 4; j++) cp16(dst + j * 16, src + j * 8);
    }
    cp_commit();

    auto load_tile = [&](int kt, int buf) {
        int k0 = kt * 64;
        int which = tid & 1;
        int halfr = (tid >> 1) & 1;
        int r = tid >> 2;
        uint32_t dst = sb + FKV + (uint32_t)buf * FBUF + (uint32_t)which * 9216u +
                       (uint32_t)r * 144u + (uint32_t)halfr * 64u;
        const __half* src = which ? (Vtp + (size_t)r * S_ + k0 + halfr * 32)
                                  : (Kp + (size_t)(k0 + r) * HD_ + halfr * 32);
#pragma unroll
        for (int j = 0; j < 4; j++) cp16(dst + j * 16, src + j * 8);
        if (tid < 16) cp16(sb + FMK + (uint32_t)buf * 256u + tid * 16, mg + k0 + tid * 4);
        cp_commit();
    };
    load_tile(0, 0);
    load_tile(1, 1);

    asm volatile("cp.async.wait_group 2;" ::: "memory");
    __syncthreads();

    uint32_t qf[4][4];
    {
        uint32_t aoff = (uint32_t)(w * 16 + (lq & 1) * 8 + lr) * 144u +
                        (uint32_t)((lq >> 1) * 8) * 2u;
#pragma unroll
        for (int ks = 0; ks < 4; ks++)
            ldsm4(qf[ks], sb + FQ + aoff + ks * 32);
    }

    float o[8][4];
#pragma unroll
    for (int i = 0; i < 8; i++) { o[i][0] = o[i][1] = o[i][2] = o[i][3] = 0.f; }
    float m0r = -1e30f, m1r = -1e30f, l0 = 0.f, l1 = 0.f;
    const uint32_t boff = (uint32_t)((lq >> 1) * 8 + lr) * 144u +
                          (uint32_t)((lq & 1) * 8) * 2u;

#pragma unroll 1
    for (int kt = 0; kt < 32; kt++) {
        if (kt >= 30) asm volatile("cp.async.wait_group 0;" ::: "memory");
        else          asm volatile("cp.async.wait_group 1;" ::: "memory");
        __syncthreads();

        const uint32_t kb = sb + FKV + (uint32_t)(kt & 1) * FBUF;
        const int* mkb = (const int*)(sm + FMK + (kt & 1) * 256);

        // ---- scores (Q pre-scaled: result already in log2 domain) ----
        float sc[8][4];
#pragma unroll
        for (int i = 0; i < 8; i++) { sc[i][0] = sc[i][1] = sc[i][2] = sc[i][3] = 0.f; }

#pragma unroll
        for (int ks = 0; ks < 4; ks++) {
            uint32_t kf[4][4];
#pragma unroll
            for (int np = 0; np < 4; np++)
                ldsm4(kf[np], kb + boff + (uint32_t)np * 2304u + ks * 32);
#pragma unroll
            for (int nt = 0; nt < 8; nt++)
                mma_f16(sc[nt], qf[ks], &kf[nt >> 1][(nt & 1) * 2]);
        }

        // ---- mask ----
#pragma unroll
        for (int nt = 0; nt < 8; nt++) {
            int c0 = nt * 8 + q * 2;
            int mk0 = mkb[c0], mk1 = mkb[c0 + 1];
            sc[nt][0] = mk0 ? sc[nt][0] : -1e10f;
            sc[nt][1] = mk1 ? sc[nt][1] : -1e10f;
            sc[nt][2] = mk0 ? sc[nt][2] : -1e10f;
            sc[nt][3] = mk1 ? sc[nt][3] : -1e10f;
        }

        // ---- online softmax (log2 domain) ----
        float tm0 = -1e30f, tm1 = -1e30f;
#pragma unroll
        for (int nt = 0; nt < 8; nt++) {
            tm0 = fmaxf(tm0, fmaxf(sc[nt][0], sc[nt][1]));
            tm1 = fmaxf(tm1, fmaxf(sc[nt][2], sc[nt][3]));
        }
        tm0 = fmaxf(tm0, __shfl_xor_sync(0xffffffffu, tm0, 1));
        tm0 = fmaxf(tm0, __shfl_xor_sync(0xffffffffu, tm0, 2));
        tm1 = fmaxf(tm1, __shfl_xor_sync(0xffffffffu, tm1, 1));
        tm1 = fmaxf(tm1, __shfl_xor_sync(0xffffffffu, tm1, 2));
        float nm0 = fmaxf(m0r, tm0), nm1 = fmaxf(m1r, tm1);
        float al0 = exp2f(m0r - nm0), al1 = exp2f(m1r - nm1);
        m0r = nm0; m1r = nm1;
        float rs0 = 0.f, rs1 = 0.f;
#pragma unroll
        for (int nt = 0; nt < 8; nt++) {
            sc[nt][0] = exp2f(sc[nt][0] - nm0);
            sc[nt][1] = exp2f(sc[nt][1] - nm0);
            sc[nt][2] = exp2f(sc[nt][2] - nm1);
            sc[nt][3] = exp2f(sc[nt][3] - nm1);
            rs0 += sc[nt][0] + sc[nt][1];
            rs1 += sc[nt][2] + sc[nt][3];
        }
        rs0 += __shfl_xor_sync(0xffffffffu, rs0, 1);
        rs0 += __shfl_xor_sync(0xffffffffu, rs0, 2);
        rs1 += __shfl_xor_sync(0xffffffffu, rs1, 1);
        rs1 += __shfl_xor_sync(0xffffffffu, rs1, 2);
        l0 = l0 * al0 + rs0;
        l1 = l1 * al1 + rs1;
#pragma unroll
        for (int nt = 0; nt < 8; nt++) {
            o[nt][0] *= al0; o[nt][1] *= al0; o[nt][2] *= al1; o[nt][3] *= al1;
        }

        // ---- O += P @ V (single-P fp16) ----
#pragma unroll
        for (int ks = 0; ks < 4; ks++) {
            const int t0 = 2 * ks, t1 = t0 + 1;
            uint32_t ah[4];
            ah[0] = pack2h(sc[t0][0], sc[t0][1]);
            ah[1] = pack2h(sc[t0][2], sc[t0][3]);
            ah[2] = pack2h(sc[t1][0], sc[t1][1]);
            ah[3] = pack2h(sc[t1][2], sc[t1][3]);
            uint32_t vf[4][4];
#pragma unroll
            for (int np = 0; np < 4; np++)
                ldsm4(vf[np], kb + 9216u + boff + (uint32_t)np * 2304u + ks * 32);
#pragma unroll
            for (int nt = 0; nt < 8; nt++)
                mma_f16(o[nt], ah, &vf[nt >> 1][(nt & 1) * 2]);
        }
        __syncthreads();
        if (kt + 2 < 32) load_tile(kt + 2, kt & 1);
    }

    float inv0 = 1.f / l0, inv1 = 1.f / l1;
    size_t row0 = (size_t)(b * S_ + q0 + w * 16 + g);
    int colb = h * HD_;
#pragma unroll
    for (int nt = 0; nt < 8; nt++) {
        int col = colb + nt * 8 + q * 2;
        *(uint32_t*)&g_hh[row0 * D_ + col] = pack2h(o[nt][0] * inv0, o[nt][1] * inv0);
        *(uint32_t*)&g_hh[(row0 + 8) * D_ + col] = pack2h(o[nt][2] * inv1, o[nt][3] * inv1);
    }
}

// ---------------------------------------------------------------------------
extern "C" void kernel_launch(void* const* d_in, const int* in_sizes, int n_in,
                              void* d_out, int out_size)
{
    const float* query = (const float*)d_in[0];
    const float* key   = (const float*)d_in[1];
    const float* value = (const float*)d_in[2];
    const int*   mask  = (const int*)d_in[3];
    const float* Wq = (const float*)d_in[4];
    const float* bq = (const float*)d_in[5];
    const float* Wk = (const float*)d_in[6];
    const float* bk = (const float*)d_in[7];
    const float* Wv = (const float*)d_in[8];
    const float* bv = (const float*)d_in[9];
    const float* Wo = (const float*)d_in[10];
    const float* bo = (const float*)d_in[11];
    float* out = (float*)d_out;

    __half *xqh,*xql,*xkh,*xkl,*xvh,*xvl,*wq,*wk,*wv,*wo,*hh;
    __half *qq,*kk,*vv;
    cudaGetSymbolAddress((void**)&xqh, g_xq_h); cudaGetSymbolAddress((void**)&xql, g_xq_l);
    cudaGetSymbolAddress((void**)&xkh, g_xk_h); cudaGetSymbolAddress((void**)&xkl, g_xk_l);
    cudaGetSymbolAddress((void**)&xvh, g_xv_h); cudaGetSymbolAddress((void**)&xvl, g_xv_l);
    cudaGetSymbolAddress((void**)&wq, g_wq);    cudaGetSymbolAddress((void**)&wk, g_wk);
    cudaGetSymbolAddress((void**)&wv, g_wv);    cudaGetSymbolAddress((void**)&wo, g_wo);
    cudaGetSymbolAddress((void**)&qq, g_q);     cudaGetSymbolAddress((void**)&kk, g_k);
    cudaGetSymbolAddress((void**)&vv, g_v);     cudaGetSymbolAddress((void**)&hh, g_hh);

    static int attr_set = 0;
    if (!attr_set) {
        cudaFuncSetAttribute((const void*)gemm_proj_kernel,
                             cudaFuncAttributeMaxDynamicSharedMemorySize, GEMM_SMEM);
        cudaFuncSetAttribute((const void*)gemm_out_kernel,
                             cudaFuncAttributeMaxDynamicSharedMemorySize, GEMM_SMEM);
        cudaFuncSetAttribute((const void*)flash_tc_kernel,
                             cudaFuncAttributeMaxDynamicSharedMemorySize, FLASH_SMEM);
        attr_set = 1;
    }

    const int NX4 = M_ * D_ / 4;
    cvt_all_kernel<<<dim3((NX4 + 255) / 256, 7), 256>>>(
        query, key, value, Wq, Wk, Wv, Wo,
        xqh, xql, xkh, xkl, xvh, xvl, wq, wk, wv, wo);

    gemm_proj_kernel<<<dim3(D_ / BN, M_ / BM, 3), 256, GEMM_SMEM>>>(
        xqh, xql, xkh, xkl, xvh, xvl, wq, wk, wv, bq, bk, bv, qq, kk, vv);

    vtrans_kernel<<<dim3(S_ / 64, H_, B_), 256>>>();

    flash_tc_kernel<<<dim3(S_ / 128, H_, B_), 256, FLASH_SMEM>>>(mask);

    gemm_out_kernel<<<dim3(D_ / BN, M_ / BM), 256, GEMM_SMEM>>>(hh, wo, bo, out);
}

// round 12
// speedup vs baseline: 3.3091x; 1.2077x over previous
#include <cuda_runtime.h>
#include <cuda_bf16.h>
#include <cuda_fp16.h>
#include <cstdint>

// Problem constants
#define B_  4
#define S_  2048
#define D_  1024
#define H_  16
#define HD_ 64
#define M_  (B_*S_)   // 8192

// ---------------- scratch (__device__ globals) ------------------------------
__device__ __half g_xq_h[(size_t)M_*D_], g_xq_l[(size_t)M_*D_];
__device__ __half g_xk_h[(size_t)M_*D_], g_xk_l[(size_t)M_*D_];
__device__ __half g_xv_h[(size_t)M_*D_], g_xv_l[(size_t)M_*D_];
__device__ __half g_wq[(size_t)D_*D_], g_wk[(size_t)D_*D_];
__device__ __half g_wv[(size_t)D_*D_], g_wo[(size_t)D_*D_];
// projected Q (pre-scaled by 0.125*log2e), K, V — single fp16, [b,h,s,d]
__device__ __half g_q [(size_t)M_*D_];
__device__ __half g_k [(size_t)M_*D_];
__device__ __half g_v [(size_t)M_*D_];
// compacted K [b,h,j,d] and compacted-transposed V [b,h,d,j]
__device__ __half g_kc[(size_t)M_*D_];
__device__ __half g_vt[(size_t)M_*D_];
// attention output single fp16 [m][1024]
__device__ __half g_hh[(size_t)M_*D_];
// mask compaction
__device__ int g_cnt[B_];
__device__ int g_idx[B_][S_];

extern __shared__ char dynsmem[];

// 0.125 * log2(e)
#define SCALE_L2E 0.18033688011112042f

// ---------------- PTX helpers ------------------------------------------------
__device__ __forceinline__ uint32_t smem_u32(const void* p) {
    uint32_t a;
    asm("{ .reg .u64 t; cvta.to.shared.u64 t, %1; cvt.u32.u64 %0, t; }" : "=r"(a) : "l"(p));
    return a;
}
__device__ __forceinline__ void cp16(uint32_t dst, const void* src) {
    asm volatile("cp.async.cg.shared.global [%0], [%1], 16;" :: "r"(dst), "l"(src) : "memory");
}
__device__ __forceinline__ void cp_commit() {
    asm volatile("cp.async.commit_group;" ::: "memory");
}
__device__ __forceinline__ void ldsm4(uint32_t* r, uint32_t addr) {
    asm volatile("ldmatrix.sync.aligned.m8n8.x4.shared.b16 {%0,%1,%2,%3}, [%4];"
                 : "=r"(r[0]), "=r"(r[1]), "=r"(r[2]), "=r"(r[3]) : "r"(addr));
}
__device__ __forceinline__ void mma_f16(float* d, const uint32_t* a, const uint32_t* b) {
    asm volatile(
        "mma.sync.aligned.m16n8k16.row.col.f32.f16.f16.f32 "
        "{%0,%1,%2,%3}, {%4,%5,%6,%7}, {%8,%9}, {%0,%1,%2,%3};"
        : "+f"(d[0]), "+f"(d[1]), "+f"(d[2]), "+f"(d[3])
        : "r"(a[0]), "r"(a[1]), "r"(a[2]), "r"(a[3]), "r"(b[0]), "r"(b[1]));
}
__device__ __forceinline__ void split2h(float x0, float x1, uint32_t& hp, uint32_t& lp) {
    __half2 h = __floats2half2_rn(x0, x1);
    float2 f = __half22float2(h);
    __half2 l = __floats2half2_rn(x0 - f.x, x1 - f.y);
    hp = *(uint32_t*)&h;
    lp = *(uint32_t*)&l;
}
__device__ __forceinline__ uint32_t pack2h(float x0, float x1) {
    __half2 h = __floats2half2_rn(x0, x1);
    return *(uint32_t*)&h;
}

// ---------------- fused conversion kernel ------------------------------------
__global__ __launch_bounds__(256) void cvt_all_kernel(
    const float* __restrict__ xq, const float* __restrict__ xk, const float* __restrict__ xv,
    const float* __restrict__ Wq, const float* __restrict__ Wk,
    const float* __restrict__ Wv, const float* __restrict__ Wo,
    __half* __restrict__ qh2, __half* __restrict__ ql2,
    __half* __restrict__ kh2, __half* __restrict__ kl2,
    __half* __restrict__ vh2, __half* __restrict__ vl2,
    __half* __restrict__ owq, __half* __restrict__ owk,
    __half* __restrict__ owv, __half* __restrict__ owo)
{
    const int y = blockIdx.y;
    int i = blockIdx.x * blockDim.x + threadIdx.x;
    if (y < 3) {
        const int n4 = M_ * D_ / 4;
        if (i >= n4) return;
        const float* x = y == 0 ? xq : (y == 1 ? xk : xv);
        __half* hh = y == 0 ? qh2 : (y == 1 ? kh2 : vh2);
        __half* ll = y == 0 ? ql2 : (y == 1 ? kl2 : vl2);
        float4 v = ((const float4*)x)[i];
        uint32_t a, b, c, d;
        split2h(v.x, v.y, a, c);
        split2h(v.z, v.w, b, d);
        ((uint2*)hh)[i] = make_uint2(a, b);
        ((uint2*)ll)[i] = make_uint2(c, d);
    } else {
        const int n4 = D_ * D_ / 4;
        if (i >= n4) return;
        const float* w = y == 3 ? Wq : (y == 4 ? Wk : (y == 5 ? Wv : Wo));
        __half* o = y == 3 ? owq : (y == 4 ? owk : (y == 5 ? owv : owo));
        float4 v = ((const float4*)w)[i];
        ((uint2*)o)[i] = make_uint2(pack2h(v.x, v.y), pack2h(v.z, v.w));
    }
}

// ---------------- mask compaction: one block per batch -----------------------
__global__ __launch_bounds__(256) void mask_compact_kernel(const int* __restrict__ mask)
{
    __shared__ int warp_off[8];
    const int b = blockIdx.x;
    const int tid = threadIdx.x, lane = tid & 31, wid = tid >> 5;
    const int* m = mask + b * S_;
    int vals[8], c = 0;
#pragma unroll
    for (int i = 0; i < 8; i++) { vals[i] = m[tid * 8 + i]; c += (vals[i] != 0); }
    int pre = c;
#pragma unroll
    for (int off = 1; off < 32; off <<= 1) {
        int t = __shfl_up_sync(0xffffffffu, pre, off);
        if (lane >= off) pre += t;
    }
    if (lane == 31) warp_off[wid] = pre;
    __syncthreads();
    if (tid == 0) {
        int s = 0;
#pragma unroll
        for (int i = 0; i < 8; i++) { int t = warp_off[i]; warp_off[i] = s; s += t; }
        g_cnt[b] = s;
    }
    __syncthreads();
    int pos = warp_off[wid] + pre - c;
#pragma unroll
    for (int i = 0; i < 8; i++)
        if (vals[i]) g_idx[b][pos++] = tid * 8 + i;
}

// ---------------- fp16 GEMM building blocks ---------------------------------
#define BM 128
#define BN 128
#define GBK 32
#define ROWB 80
#define TILEB (128 * ROWB)
#define BUFB  (3 * TILEB)
#define GEMM_SMEM (2 * BUFB)    // 61440

template <int SPLIT>
__device__ __forceinline__ void g2s_chunk(
    uint32_t sbuf, const __half* Ah, const __half* Al, const __half* Bw, int tid)
{
#pragma unroll
    for (int r = 0; r < 2; r++) {
        int c = tid + (r << 8);
        int row = c >> 2, c16 = c & 3;
        uint32_t soff = (uint32_t)row * ROWB + (uint32_t)c16 * 16;
        size_t goff = (size_t)row * D_ + c16 * 8;
        cp16(sbuf + 0 * TILEB + soff, Ah + goff);
        if (SPLIT == 2) cp16(sbuf + 1 * TILEB + soff, Al + goff);
        cp16(sbuf + 2 * TILEB + soff, Bw + goff);
    }
}

template <int SPLIT>
__device__ __forceinline__ void gemm_mainloop(
    uint32_t sb, const __half* Ah, const __half* Al, const __half* Bp,
    int tid, int lane, int wm, int wn, float acc[4][4][4])
{
#pragma unroll
    for (int i = 0; i < 4; i++)
#pragma unroll
        for (int j = 0; j < 4; j++)
#pragma unroll
            for (int k = 0; k < 4; k++) acc[i][j][k] = 0.f;

    g2s_chunk<SPLIT>(sb,        Ah,       Al,                          Bp,       tid); cp_commit();
    g2s_chunk<SPLIT>(sb + BUFB, Ah + GBK, SPLIT == 2 ? Al + GBK : Al, Bp + GBK, tid); cp_commit();

    const int lr = lane & 7, lq = lane >> 3;
    const uint32_t a_base_off =
        (uint32_t)(wm * 64 + (lq & 1) * 8 + lr) * ROWB + (uint32_t)((lq >> 1) * 8) * 2;
    const uint32_t b_base_off =
        (uint32_t)(wn * 32 + (lq >> 1) * 8 + lr) * ROWB + (uint32_t)((lq & 1) * 8) * 2;

    const int NCHUNK = D_ / GBK;
#pragma unroll 1
    for (int c = 0; c < NCHUNK; c++) {
        if (c >= NCHUNK - 2) asm volatile("cp.async.wait_group 0;" ::: "memory");
        else                 asm volatile("cp.async.wait_group 1;" ::: "memory");
        __syncthreads();

        const uint32_t buf = sb + (uint32_t)(c & 1) * BUFB;
        const uint32_t sAh = buf, sAl = buf + TILEB, sB = buf + 2 * TILEB;

#pragma unroll
        for (int ks = 0; ks < 2; ks++) {
            const uint32_t ko = (uint32_t)(ks * 16) * 2;
            uint32_t ahr[4][4], alr[4][4], br[2][4];
#pragma unroll
            for (int mt = 0; mt < 4; mt++) {
                ldsm4(ahr[mt], sAh + a_base_off + ko + (uint32_t)mt * (16 * ROWB));
                if (SPLIT == 2)
                    ldsm4(alr[mt], sAl + a_base_off + ko + (uint32_t)mt * (16 * ROWB));
            }
#pragma unroll
            for (int np = 0; np < 2; np++)
                ldsm4(br[np], sB + b_base_off + ko + (uint32_t)np * (16 * ROWB));
#pragma unroll
            for (int mt = 0; mt < 4; mt++)
#pragma unroll
                for (int nt = 0; nt < 4; nt++) {
                    const uint32_t* b2 = &br[nt >> 1][(nt & 1) * 2];
                    mma_f16(acc[mt][nt], ahr[mt], b2);
                    if (SPLIT == 2) mma_f16(acc[mt][nt], alr[mt], b2);
                }
        }
        __syncthreads();

        if (c + 2 < NCHUNK) {
            const int kc = (c + 2) * GBK;
            g2s_chunk<SPLIT>(sb + (uint32_t)(c & 1) * BUFB,
                             Ah + kc, SPLIT == 2 ? Al + kc : Al, Bp + kc, tid);
            cp_commit();
        }
    }
}

// Fused projection GEMM: grid.z selects (X, W, bias, out, scale).
__global__ __launch_bounds__(256) void gemm_proj_kernel(
    const __half* __restrict__ xqh, const __half* __restrict__ xql,
    const __half* __restrict__ xkh, const __half* __restrict__ xkl,
    const __half* __restrict__ xvh, const __half* __restrict__ xvl,
    const __half* __restrict__ wq, const __half* __restrict__ wk,
    const __half* __restrict__ wv,
    const float* __restrict__ bq, const float* __restrict__ bk,
    const float* __restrict__ bv,
    __half* __restrict__ oq, __half* __restrict__ ok, __half* __restrict__ ov)
{
    const uint32_t sb = smem_u32(dynsmem);
    const int tid = threadIdx.x, wid = tid >> 5, lane = tid & 31;
    const int wm = wid >> 2, wn = wid & 3;
    const int n0 = blockIdx.x * BN, m0 = blockIdx.y * BM;
    const int z = blockIdx.z;

    const __half* Ahb = z == 0 ? xqh : (z == 1 ? xkh : xvh);
    const __half* Alb = z == 0 ? xql : (z == 1 ? xkl : xvl);
    const __half* Wb  = z == 0 ? wq  : (z == 1 ? wk  : wv);
    const float* bias = z == 0 ? bq  : (z == 1 ? bk  : bv);
    __half* outp      = z == 0 ? oq  : (z == 1 ? ok  : ov);
    const float oscale = z == 0 ? SCALE_L2E : 1.0f;

    float acc[4][4][4];
    gemm_mainloop<2>(sb, Ahb + (size_t)m0 * D_, Alb + (size_t)m0 * D_,
                     Wb + (size_t)n0 * D_, tid, lane, wm, wn, acc);

    const int g = lane >> 2, tq = lane & 3;
#pragma unroll
    for (int mt = 0; mt < 4; mt++) {
#pragma unroll
        for (int nt = 0; nt < 4; nt++) {
            int row = m0 + wm * 64 + mt * 16 + g;
            int col = n0 + wn * 32 + nt * 8 + tq * 2;
            float2 bv2 = *(const float2*)&bias[col];
            float v0 = (acc[mt][nt][0] + bv2.x) * oscale;
            float v1 = (acc[mt][nt][1] + bv2.y) * oscale;
            float v2 = (acc[mt][nt][2] + bv2.x) * oscale;
            float v3 = (acc[mt][nt][3] + bv2.y) * oscale;
            int bb = row >> 11, s = row & 2047, hh = col >> 6, d = col & 63;
            size_t i0 = ((size_t)(bb * H_ + hh) * S_ + s) * HD_ + d;
            size_t i1 = i0 + 8 * HD_;
            *(uint32_t*)&outp[i0] = pack2h(v0, v1);
            *(uint32_t*)&outp[i1] = pack2h(v2, v3);
        }
    }
}

// Final GEMM: single-A fp16, fp32 out.
__global__ __launch_bounds__(256) void gemm_out_kernel(
    const __half* __restrict__ Ahi, const __half* __restrict__ Bw,
    const float* __restrict__ bias, float* __restrict__ out)
{
    const uint32_t sb = smem_u32(dynsmem);
    const int tid = threadIdx.x, wid = tid >> 5, lane = tid & 31;
    const int wm = wid >> 2, wn = wid & 3;
    const int n0 = blockIdx.x * BN, m0 = blockIdx.y * BM;

    float acc[4][4][4];
    gemm_mainloop<1>(sb, Ahi + (size_t)m0 * D_, nullptr,
                     Bw + (size_t)n0 * D_, tid, lane, wm, wn, acc);

    const int g = lane >> 2, tq = lane & 3;
#pragma unroll
    for (int mt = 0; mt < 4; mt++) {
#pragma unroll
        for (int nt = 0; nt < 4; nt++) {
            int row = m0 + wm * 64 + mt * 16 + g;
            int col = n0 + wn * 32 + nt * 8 + tq * 2;
            float2 bv2 = *(const float2*)&bias[col];
            *(float2*)&out[(size_t)row * D_ + col] =
                make_float2(acc[mt][nt][0] + bv2.x, acc[mt][nt][1] + bv2.y);
            *(float2*)&out[(size_t)(row + 8) * D_ + col] =
                make_float2(acc[mt][nt][2] + bv2.x, acc[mt][nt][3] + bv2.y);
        }
    }
}

// ---------------- gather: compact K rows; compact + transpose V --------------
// grid (32 tiles, H, B). Pads (j >= cnt) are zeroed.
__global__ __launch_bounds__(256) void gather_kv_kernel()
{
    __shared__ __align__(16) unsigned short ts[64 * 66];
    __shared__ int sidx[64];
    const int b = blockIdx.z, h = blockIdx.y, st = blockIdx.x;
    const int bh = b * H_ + h;
    const int j0 = st * 64;
    const int tid = threadIdx.x;
    const int cnt = g_cnt[b];

    if (tid < 64) sidx[tid] = (j0 + tid < cnt) ? g_idx[b][j0 + tid] : -1;
    __syncthreads();

    // K gather: 4 threads per row, 32B each
    {
        int r = tid >> 2, part = tid & 3;
        int s = sidx[r];
        const uint4* srcp = (const uint4*)(g_k + ((size_t)bh * S_ + (s < 0 ? 0 : s)) * HD_)
                            + part * 2;
        uint4 z = make_uint4(0, 0, 0, 0);
        uint4 v0 = s >= 0 ? srcp[0] : z;
        uint4 v1 = s >= 0 ? srcp[1] : z;
        uint4* dstp = (uint4*)(g_kc + ((size_t)bh * S_ + j0 + r) * HD_) + part * 2;
        dstp[0] = v0;
        dstp[1] = v1;
    }

    // V gather into smem (rows gathered), then write transposed columns
#pragma unroll
    for (int i = 0; i < 8; i++) {
        int flat = tid + i * 256;
        int r = flat >> 5, c2 = flat & 31;
        int s = sidx[r];
        uint32_t v = 0;
        if (s >= 0)
            v = ((const uint32_t*)(g_v + ((size_t)bh * S_ + s) * HD_))[c2];
        *(uint32_t*)&ts[r * 66 + c2 * 2] = v;
    }
    __syncthreads();
    uint32_t* dst = (uint32_t*)(g_vt + (size_t)bh * HD_ * S_ + j0);
#pragma unroll
    for (int i = 0; i < 8; i++) {
        int flat = tid + i * 256;
        int d = flat >> 5, sp = flat & 31;
        uint32_t v = (uint32_t)ts[(2 * sp) * 66 + d] |
                     ((uint32_t)ts[(2 * sp + 1) * 66 + d] << 16);
        dst[(size_t)d * (S_ / 2) + sp] = v;
    }
}

// ---------------- tensor-core flash attention (compacted keys) ---------------
#define FQ   0u
#define FKV  18432u
#define FBUF 18432u
#define FLASH_SMEM 55296

__global__ __launch_bounds__(256) void flash_tc_kernel()
{
    char* sm = dynsmem;
    const uint32_t sb = smem_u32(sm);
    const int tid = threadIdx.x, w = tid >> 5, lane = tid & 31;
    const int lr = lane & 7, lq = lane >> 3, g = lane >> 2, q = lane & 3;
    const int b = blockIdx.z, h = blockIdx.y;
    const int bh = b * H_ + h;
    const int q0 = blockIdx.x * 128;

    const int cnt = g_cnt[b];
    int nkt = (cnt + 63) >> 6;
    if (nkt < 1) nkt = 1;

    const __half* Qp  = g_q  + ((size_t)bh * S_ + q0) * HD_;
    const __half* Kp  = g_kc + (size_t)bh * S_ * HD_;
    const __half* Vtp = g_vt + (size_t)bh * HD_ * S_;

    {
        int r = tid >> 1, halfr = tid & 1;
        const __half* src = Qp + (size_t)r * HD_ + halfr * 32;
        uint32_t dst = sb + FQ + (uint32_t)r * 144u + (uint32_t)halfr * 64u;
#pragma unroll
        for (int j = 0; j < 4; j++) cp16(dst + j * 16, src + j * 8);
    }
    cp_commit();

    auto load_tile = [&](int kt, int buf) {
        int k0 = kt * 64;
        int which = tid & 1;
        int halfr = (tid >> 1) & 1;
        int r = tid >> 2;
        uint32_t dst = sb + FKV + (uint32_t)buf * FBUF + (uint32_t)which * 9216u +
                       (uint32_t)r * 144u + (uint32_t)halfr * 64u;
        const __half* src = which ? (Vtp + (size_t)r * S_ + k0 + halfr * 32)
                                  : (Kp + (size_t)(k0 + r) * HD_ + halfr * 32);
#pragma unroll
        for (int j = 0; j < 4; j++) cp16(dst + j * 16, src + j * 8);
        cp_commit();
    };
    load_tile(0, 0);
    load_tile(1, 1);

    asm volatile("cp.async.wait_group 2;" ::: "memory");
    __syncthreads();

    uint32_t qf[4][4];
    {
        uint32_t aoff = (uint32_t)(w * 16 + (lq & 1) * 8 + lr) * 144u +
                        (uint32_t)((lq >> 1) * 8) * 2u;
#pragma unroll
        for (int ks = 0; ks < 4; ks++)
            ldsm4(qf[ks], sb + FQ + aoff + ks * 32);
    }

    float o[8][4];
#pragma unroll
    for (int i = 0; i < 8; i++) { o[i][0] = o[i][1] = o[i][2] = o[i][3] = 0.f; }
    float m0r = -1e30f, m1r = -1e30f, l0 = 0.f, l1 = 0.f;
    const uint32_t boff = (uint32_t)((lq >> 1) * 8 + lr) * 144u +
                          (uint32_t)((lq & 1) * 8) * 2u;

#pragma unroll 1
    for (int kt = 0; kt < nkt; kt++) {
        if (kt >= nkt - 2) asm volatile("cp.async.wait_group 0;" ::: "memory");
        else               asm volatile("cp.async.wait_group 1;" ::: "memory");
        __syncthreads();

        const uint32_t kb = sb + FKV + (uint32_t)(kt & 1) * FBUF;

        // ---- scores (Q pre-scaled: already log2 domain) ----
        float sc[8][4];
#pragma unroll
        for (int i = 0; i < 8; i++) { sc[i][0] = sc[i][1] = sc[i][2] = sc[i][3] = 0.f; }

#pragma unroll
        for (int ks = 0; ks < 4; ks++) {
            uint32_t kf[4][4];
#pragma unroll
            for (int np = 0; np < 4; np++)
                ldsm4(kf[np], kb + boff + (uint32_t)np * 2304u + ks * 32);
#pragma unroll
            for (int nt = 0; nt < 8; nt++)
                mma_f16(sc[nt], qf[ks], &kf[nt >> 1][(nt & 1) * 2]);
        }

        // ---- pad mask: key index >= cnt -> -1e10 ----
#pragma unroll
        for (int nt = 0; nt < 8; nt++) {
            int j = kt * 64 + nt * 8 + q * 2;
            bool p0 = j < cnt, p1 = j + 1 < cnt;
            sc[nt][0] = p0 ? sc[nt][0] : -1e10f;
            sc[nt][1] = p1 ? sc[nt][1] : -1e10f;
            sc[nt][2] = p0 ? sc[nt][2] : -1e10f;
            sc[nt][3] = p1 ? sc[nt][3] : -1e10f;
        }

        // ---- online softmax (log2 domain) ----
        float tm0 = -1e30f, tm1 = -1e30f;
#pragma unroll
        for (int nt = 0; nt < 8; nt++) {
            tm0 = fmaxf(tm0, fmaxf(sc[nt][0], sc[nt][1]));
            tm1 = fmaxf(tm1, fmaxf(sc[nt][2], sc[nt][3]));
        }
        tm0 = fmaxf(tm0, __shfl_xor_sync(0xffffffffu, tm0, 1));
        tm0 = fmaxf(tm0, __shfl_xor_sync(0xffffffffu, tm0, 2));
        tm1 = fmaxf(tm1, __shfl_xor_sync(0xffffffffu, tm1, 1));
        tm1 = fmaxf(tm1, __shfl_xor_sync(0xffffffffu, tm1, 2));
        float nm0 = fmaxf(m0r, tm0), nm1 = fmaxf(m1r, tm1);
        float al0 = exp2f(m0r - nm0), al1 = exp2f(m1r - nm1);
        m0r = nm0; m1r = nm1;
        float rs0 = 0.f, rs1 = 0.f;
#pragma unroll
        for (int nt = 0; nt < 8; nt++) {
            sc[nt][0] = exp2f(sc[nt][0] - nm0);
            sc[nt][1] = exp2f(sc[nt][1] - nm0);
            sc[nt][2] = exp2f(sc[nt][2] - nm1);
            sc[nt][3] = exp2f(sc[nt][3] - nm1);
            rs0 += sc[nt][0] + sc[nt][1];
            rs1 += sc[nt][2] + sc[nt][3];
        }
        rs0 += __shfl_xor_sync(0xffffffffu, rs0, 1);
        rs0 += __shfl_xor_sync(0xffffffffu, rs0, 2);
        rs1 += __shfl_xor_sync(0xffffffffu, rs1, 1);
        rs1 += __shfl_xor_sync(0xffffffffu, rs1, 2);
        l0 = l0 * al0 + rs0;
        l1 = l1 * al1 + rs1;
#pragma unroll
        for (int nt = 0; nt < 8; nt++) {
            o[nt][0] *= al0; o[nt][1] *= al0; o[nt][2] *= al1; o[nt][3] *= al1;
        }

        // ---- O += P @ V ----
#pragma unroll
        for (int ks = 0; ks < 4; ks++) {
            const int t0 = 2 * ks, t1 = t0 + 1;
            uint32_t ah[4];
            ah[0] = pack2h(sc[t0][0], sc[t0][1]);
            ah[1] = pack2h(sc[t0][2], sc[t0][3]);
            ah[2] = pack2h(sc[t1][0], sc[t1][1]);
            ah[3] = pack2h(sc[t1][2], sc[t1][3]);
            uint32_t vf[4][4];
#pragma unroll
            for (int np = 0; np < 4; np++)
                ldsm4(vf[np], kb + 9216u + boff + (uint32_t)np * 2304u + ks * 32);
#pragma unroll
            for (int nt = 0; nt < 8; nt++)
                mma_f16(o[nt], ah, &vf[nt >> 1][(nt & 1) * 2]);
        }
        __syncthreads();
        if (kt + 2 < nkt) load_tile(kt + 2, kt & 1);
    }

    float inv0 = 1.f / l0, inv1 = 1.f / l1;
    size_t row0 = (size_t)(b * S_ + q0 + w * 16 + g);
    int colb = h * HD_;
#pragma unroll
    for (int nt = 0; nt < 8; nt++) {
        int col = colb + nt * 8 + q * 2;
        *(uint32_t*)&g_hh[row0 * D_ + col] = pack2h(o[nt][0] * inv0, o[nt][1] * inv0);
        *(uint32_t*)&g_hh[(row0 + 8) * D_ + col] = pack2h(o[nt][2] * inv1, o[nt][3] * inv1);
    }
}

// ---------------------------------------------------------------------------
extern "C" void kernel_launch(void* const* d_in, const int* in_sizes, int n_in,
                              void* d_out, int out_size)
{
    const float* query = (const float*)d_in[0];
    const float* key   = (const float*)d_in[1];
    const float* value = (const float*)d_in[2];
    const int*   mask  = (const int*)d_in[3];
    const float* Wq = (const float*)d_in[4];
    const float* bq = (const float*)d_in[5];
    const float* Wk = (const float*)d_in[6];
    const float* bk = (const float*)d_in[7];
    const float* Wv = (const float*)d_in[8];
    const float* bv = (const float*)d_in[9];
    const float* Wo = (const float*)d_in[10];
    const float* bo = (const float*)d_in[11];
    float* out = (float*)d_out;

    __half *xqh,*xql,*xkh,*xkl,*xvh,*xvl,*wq,*wk,*wv,*wo,*hh;
    __half *qq,*kk,*vv;
    cudaGetSymbolAddress((void**)&xqh, g_xq_h); cudaGetSymbolAddress((void**)&xql, g_xq_l);
    cudaGetSymbolAddress((void**)&xkh, g_xk_h); cudaGetSymbolAddress((void**)&xkl, g_xk_l);
    cudaGetSymbolAddress((void**)&xvh, g_xv_h); cudaGetSymbolAddress((void**)&xvl, g_xv_l);
    cudaGetSymbolAddress((void**)&wq, g_wq);    cudaGetSymbolAddress((void**)&wk, g_wk);
    cudaGetSymbolAddress((void**)&wv, g_wv);    cudaGetSymbolAddress((void**)&wo, g_wo);
    cudaGetSymbolAddress((void**)&qq, g_q);     cudaGetSymbolAddress((void**)&kk, g_k);
    cudaGetSymbolAddress((void**)&vv, g_v);     cudaGetSymbolAddress((void**)&hh, g_hh);

    static int attr_set = 0;
    if (!attr_set) {
        cudaFuncSetAttribute((const void*)gemm_proj_kernel,
                             cudaFuncAttributeMaxDynamicSharedMemorySize, GEMM_SMEM);
        cudaFuncSetAttribute((const void*)gemm_out_kernel,
                             cudaFuncAttributeMaxDynamicSharedMemorySize, GEMM_SMEM);
        cudaFuncSetAttribute((const void*)flash_tc_kernel,
                             cudaFuncAttributeMaxDynamicSharedMemorySize, FLASH_SMEM);
        attr_set = 1;
    }

    const int NX4 = M_ * D_ / 4;
    cvt_all_kernel<<<dim3((NX4 + 255) / 256, 7), 256>>>(
        query, key, value, Wq, Wk, Wv, Wo,
        xqh, xql, xkh, xkl, xvh, xvl, wq, wk, wv, wo);

    mask_compact_kernel<<<B_, 256>>>(mask);

    gemm_proj_kernel<<<dim3(D_ / BN, M_ / BM, 3), 256, GEMM_SMEM>>>(
        xqh, xql, xkh, xkl, xvh, xvl, wq, wk, wv, bq, bk, bv, qq, kk, vv);

    gather_kv_kernel<<<dim3(S_ / 64, H_, B_), 256>>>();

    flash_tc_kernel<<<dim3(S_ / 128, H_, B_), 256, FLASH_SMEM>>>();

    gemm_out_kernel<<<dim3(D_ / BN, M_ / BM), 256, GEMM_SMEM>>>(hh, wo, bo, out);
}

// round 13
// speedup vs baseline: 4.3261x; 1.3073x over previous
#include <cuda_runtime.h>
#include <cuda_bf16.h>
#include <cuda_fp16.h>
#include <cstdint>

// Problem constants
#define B_  4
#define S_  2048
#define D_  1024
#define H_  16
#define HD_ 64
#define M_  (B_*S_)   // 8192

// ---------------- scratch (__device__ globals) ------------------------------
// activations + weights, single fp16
__device__ __half g_xq[(size_t)M_*D_], g_xk[(size_t)M_*D_], g_xv[(size_t)M_*D_];
__device__ __half g_wq[(size_t)D_*D_], g_wk[(size_t)D_*D_];
__device__ __half g_wv[(size_t)D_*D_], g_wo[(size_t)D_*D_];
// projected Q (pre-scaled by 0.125*log2e), K, V — single fp16, [b,h,s,d]
__device__ __half g_q [(size_t)M_*D_];
__device__ __half g_k [(size_t)M_*D_];
__device__ __half g_v [(size_t)M_*D_];
// compacted K [b,h,j,d] and compacted-transposed V [b,h,d,j]
__device__ __half g_kc[(size_t)M_*D_];
__device__ __half g_vt[(size_t)M_*D_];
// attention output single fp16 [m][1024]
__device__ __half g_hh[(size_t)M_*D_];
// mask compaction
__device__ int g_cnt[B_];
__device__ int g_idx[B_][S_];

extern __shared__ char dynsmem[];

// 0.125 * log2(e)
#define SCALE_L2E 0.18033688011112042f

// ---------------- PTX helpers ------------------------------------------------
__device__ __forceinline__ uint32_t smem_u32(const void* p) {
    uint32_t a;
    asm("{ .reg .u64 t; cvta.to.shared.u64 t, %1; cvt.u32.u64 %0, t; }" : "=r"(a) : "l"(p));
    return a;
}
__device__ __forceinline__ void cp16(uint32_t dst, const void* src) {
    asm volatile("cp.async.cg.shared.global [%0], [%1], 16;" :: "r"(dst), "l"(src) : "memory");
}
__device__ __forceinline__ void cp_commit() {
    asm volatile("cp.async.commit_group;" ::: "memory");
}
__device__ __forceinline__ void ldsm4(uint32_t* r, uint32_t addr) {
    asm volatile("ldmatrix.sync.aligned.m8n8.x4.shared.b16 {%0,%1,%2,%3}, [%4];"
                 : "=r"(r[0]), "=r"(r[1]), "=r"(r[2]), "=r"(r[3]) : "r"(addr));
}
__device__ __forceinline__ void mma_f16(float* d, const uint32_t* a, const uint32_t* b) {
    asm volatile(
        "mma.sync.aligned.m16n8k16.row.col.f32.f16.f16.f32 "
        "{%0,%1,%2,%3}, {%4,%5,%6,%7}, {%8,%9}, {%0,%1,%2,%3};"
        : "+f"(d[0]), "+f"(d[1]), "+f"(d[2]), "+f"(d[3])
        : "r"(a[0]), "r"(a[1]), "r"(a[2]), "r"(a[3]), "r"(b[0]), "r"(b[1]));
}
__device__ __forceinline__ uint32_t pack2h(float x0, float x1) {
    __half2 h = __floats2half2_rn(x0, x1);
    return *(uint32_t*)&h;
}

// ---------------- fused conversion kernel ------------------------------------
// y = 0..2: activations (M*D), y = 3..6: weights (D*D). All single fp16.
__global__ __launch_bounds__(256) void cvt_all_kernel(
    const float* __restrict__ xq, const float* __restrict__ xk, const float* __restrict__ xv,
    const float* __restrict__ Wq, const float* __restrict__ Wk,
    const float* __restrict__ Wv, const float* __restrict__ Wo,
    __half* __restrict__ oxq, __half* __restrict__ oxk, __half* __restrict__ oxv,
    __half* __restrict__ owq, __half* __restrict__ owk,
    __half* __restrict__ owv, __half* __restrict__ owo)
{
    const int y = blockIdx.y;
    int i = blockIdx.x * blockDim.x + threadIdx.x;
    const int n4 = (y < 3) ? (M_ * D_ / 4) : (D_ * D_ / 4);
    if (i >= n4) return;
    const float* s = y == 0 ? xq : (y == 1 ? xk : (y == 2 ? xv :
                     (y == 3 ? Wq : (y == 4 ? Wk : (y == 5 ? Wv : Wo)))));
    __half* o = y == 0 ? oxq : (y == 1 ? oxk : (y == 2 ? oxv :
                (y == 3 ? owq : (y == 4 ? owk : (y == 5 ? owv : owo)))));
    float4 v = ((const float4*)s)[i];
    ((uint2*)o)[i] = make_uint2(pack2h(v.x, v.y), pack2h(v.z, v.w));
}

// ---------------- mask compaction: one block per batch -----------------------
__global__ __launch_bounds__(256) void mask_compact_kernel(const int* __restrict__ mask)
{
    __shared__ int warp_off[8];
    const int b = blockIdx.x;
    const int tid = threadIdx.x, lane = tid & 31, wid = tid >> 5;
    const int* m = mask + b * S_;
    int vals[8], c = 0;
#pragma unroll
    for (int i = 0; i < 8; i++) { vals[i] = m[tid * 8 + i]; c += (vals[i] != 0); }
    int pre = c;
#pragma unroll
    for (int off = 1; off < 32; off <<= 1) {
        int t = __shfl_up_sync(0xffffffffu, pre, off);
        if (lane >= off) pre += t;
    }
    if (lane == 31) warp_off[wid] = pre;
    __syncthreads();
    if (tid == 0) {
        int s = 0;
#pragma unroll
        for (int i = 0; i < 8; i++) { int t = warp_off[i]; warp_off[i] = s; s += t; }
        g_cnt[b] = s;
    }
    __syncthreads();
    int pos = warp_off[wid] + pre - c;
#pragma unroll
    for (int i = 0; i < 8; i++)
        if (vals[i]) g_idx[b][pos++] = tid * 8 + i;
}

// ---------------- fp16 1-call GEMM building blocks ---------------------------
#define BM 128
#define BN 128
#define GBK 32
#define ROWB 80
#define TILEB (128 * ROWB)
#define BUFB  (2 * TILEB)       // A, B
#define GEMM_SMEM (2 * BUFB)    // 40960

__device__ __forceinline__ void g2s_chunk(
    uint32_t sbuf, const __half* Ap, const __half* Bw, int tid)
{
#pragma unroll
    for (int r = 0; r < 2; r++) {
        int c = tid + (r << 8);
        int row = c >> 2, c16 = c & 3;
        uint32_t soff = (uint32_t)row * ROWB + (uint32_t)c16 * 16;
        size_t goff = (size_t)row * D_ + c16 * 8;
        cp16(sbuf + 0 * TILEB + soff, Ap + goff);
        cp16(sbuf + 1 * TILEB + soff, Bw + goff);
    }
}

__device__ __forceinline__ void gemm_mainloop(
    uint32_t sb, const __half* Ap, const __half* Bp,
    int tid, int lane, int wm, int wn, float acc[4][4][4])
{
#pragma unroll
    for (int i = 0; i < 4; i++)
#pragma unroll
        for (int j = 0; j < 4; j++)
#pragma unroll
            for (int k = 0; k < 4; k++) acc[i][j][k] = 0.f;

    g2s_chunk(sb,        Ap,       Bp,       tid); cp_commit();
    g2s_chunk(sb + BUFB, Ap + GBK, Bp + GBK, tid); cp_commit();

    const int lr = lane & 7, lq = lane >> 3;
    const uint32_t a_base_off =
        (uint32_t)(wm * 64 + (lq & 1) * 8 + lr) * ROWB + (uint32_t)((lq >> 1) * 8) * 2;
    const uint32_t b_base_off =
        (uint32_t)(wn * 32 + (lq >> 1) * 8 + lr) * ROWB + (uint32_t)((lq & 1) * 8) * 2;

    const int NCHUNK = D_ / GBK;
#pragma unroll 1
    for (int c = 0; c < NCHUNK; c++) {
        if (c >= NCHUNK - 2) asm volatile("cp.async.wait_group 0;" ::: "memory");
        else                 asm volatile("cp.async.wait_group 1;" ::: "memory");
        __syncthreads();

        const uint32_t buf = sb + (uint32_t)(c & 1) * BUFB;
        const uint32_t sA = buf, sB = buf + TILEB;

#pragma unroll
        for (int ks = 0; ks < 2; ks++) {
            const uint32_t ko = (uint32_t)(ks * 16) * 2;
            uint32_t ar[4][4], br[2][4];
#pragma unroll
            for (int mt = 0; mt < 4; mt++)
                ldsm4(ar[mt], sA + a_base_off + ko + (uint32_t)mt * (16 * ROWB));
#pragma unroll
            for (int np = 0; np < 2; np++)
                ldsm4(br[np], sB + b_base_off + ko + (uint32_t)np * (16 * ROWB));
#pragma unroll
            for (int mt = 0; mt < 4; mt++)
#pragma unroll
                for (int nt = 0; nt < 4; nt++)
                    mma_f16(acc[mt][nt], ar[mt], &br[nt >> 1][(nt & 1) * 2]);
        }
        __syncthreads();

        if (c + 2 < NCHUNK) {
            const int kc = (c + 2) * GBK;
            g2s_chunk(sb + (uint32_t)(c & 1) * BUFB, Ap + kc, Bp + kc, tid);
            cp_commit();
        }
    }
}

// Fused projection GEMM: grid.z selects (X, W, bias, out, scale).
__global__ __launch_bounds__(256) void gemm_proj_kernel(
    const __half* __restrict__ xq, const __half* __restrict__ xk,
    const __half* __restrict__ xv,
    const __half* __restrict__ wq, const __half* __restrict__ wk,
    const __half* __restrict__ wv,
    const float* __restrict__ bq, const float* __restrict__ bk,
    const float* __restrict__ bv,
    __half* __restrict__ oq, __half* __restrict__ ok, __half* __restrict__ ov)
{
    const uint32_t sb = smem_u32(dynsmem);
    const int tid = threadIdx.x, wid = tid >> 5, lane = tid & 31;
    const int wm = wid >> 2, wn = wid & 3;
    const int n0 = blockIdx.x * BN, m0 = blockIdx.y * BM;
    const int z = blockIdx.z;

    const __half* Ab  = z == 0 ? xq : (z == 1 ? xk : xv);
    const __half* Wb  = z == 0 ? wq : (z == 1 ? wk : wv);
    const float* bias = z == 0 ? bq : (z == 1 ? bk : bv);
    __half* outp      = z == 0 ? oq : (z == 1 ? ok : ov);
    const float oscale = z == 0 ? SCALE_L2E : 1.0f;

    float acc[4][4][4];
    gemm_mainloop(sb, Ab + (size_t)m0 * D_, Wb + (size_t)n0 * D_,
                  tid, lane, wm, wn, acc);

    const int g = lane >> 2, tq = lane & 3;
#pragma unroll
    for (int mt = 0; mt < 4; mt++) {
#pragma unroll
        for (int nt = 0; nt < 4; nt++) {
            int row = m0 + wm * 64 + mt * 16 + g;
            int col = n0 + wn * 32 + nt * 8 + tq * 2;
            float2 bv2 = *(const float2*)&bias[col];
            float v0 = (acc[mt][nt][0] + bv2.x) * oscale;
            float v1 = (acc[mt][nt][1] + bv2.y) * oscale;
            float v2 = (acc[mt][nt][2] + bv2.x) * oscale;
            float v3 = (acc[mt][nt][3] + bv2.y) * oscale;
            int bb = row >> 11, s = row & 2047, hh = col >> 6, d = col & 63;
            size_t i0 = ((size_t)(bb * H_ + hh) * S_ + s) * HD_ + d;
            size_t i1 = i0 + 8 * HD_;
            *(uint32_t*)&outp[i0] = pack2h(v0, v1);
            *(uint32_t*)&outp[i1] = pack2h(v2, v3);
        }
    }
}

// Final GEMM: single-A fp16, fp32 out.
__global__ __launch_bounds__(256) void gemm_out_kernel(
    const __half* __restrict__ Ahi, const __half* __restrict__ Bw,
    const float* __restrict__ bias, float* __restrict__ out)
{
    const uint32_t sb = smem_u32(dynsmem);
    const int tid = threadIdx.x, wid = tid >> 5, lane = tid & 31;
    const int wm = wid >> 2, wn = wid & 3;
    const int n0 = blockIdx.x * BN, m0 = blockIdx.y * BM;

    float acc[4][4][4];
    gemm_mainloop(sb, Ahi + (size_t)m0 * D_, Bw + (size_t)n0 * D_,
                  tid, lane, wm, wn, acc);

    const int g = lane >> 2, tq = lane & 3;
#pragma unroll
    for (int mt = 0; mt < 4; mt++) {
#pragma unroll
        for (int nt = 0; nt < 4; nt++) {
            int row = m0 + wm * 64 + mt * 16 + g;
            int col = n0 + wn * 32 + nt * 8 + tq * 2;
            float2 bv2 = *(const float2*)&bias[col];
            *(float2*)&out[(size_t)row * D_ + col] =
                make_float2(acc[mt][nt][0] + bv2.x, acc[mt][nt][1] + bv2.y);
            *(float2*)&out[(size_t)(row + 8) * D_ + col] =
                make_float2(acc[mt][nt][2] + bv2.x, acc[mt][nt][3] + bv2.y);
        }
    }
}

// ---------------- gather: compact K rows; compact + transpose V --------------
__global__ __launch_bounds__(256) void gather_kv_kernel()
{
    __shared__ __align__(16) unsigned short ts[64 * 66];
    __shared__ int sidx[64];
    const int b = blockIdx.z, h = blockIdx.y, st = blockIdx.x;
    const int bh = b * H_ + h;
    const int j0 = st * 64;
    const int tid = threadIdx.x;
    const int cnt = g_cnt[b];

    if (tid < 64) sidx[tid] = (j0 + tid < cnt) ? g_idx[b][j0 + tid] : -1;
    __syncthreads();

    {
        int r = tid >> 2, part = tid & 3;
        int s = sidx[r];
        const uint4* srcp = (const uint4*)(g_k + ((size_t)bh * S_ + (s < 0 ? 0 : s)) * HD_)
                            + part * 2;
        uint4 z = make_uint4(0, 0, 0, 0);
        uint4 v0 = s >= 0 ? srcp[0] : z;
        uint4 v1 = s >= 0 ? srcp[1] : z;
        uint4* dstp = (uint4*)(g_kc + ((size_t)bh * S_ + j0 + r) * HD_) + part * 2;
        dstp[0] = v0;
        dstp[1] = v1;
    }

#pragma unroll
    for (int i = 0; i < 8; i++) {
        int flat = tid + i * 256;
        int r = flat >> 5, c2 = flat & 31;
        int s = sidx[r];
        uint32_t v = 0;
        if (s >= 0)
            v = ((const uint32_t*)(g_v + ((size_t)bh * S_ + s) * HD_))[c2];
        *(uint32_t*)&ts[r * 66 + c2 * 2] = v;
    }
    __syncthreads();
    uint32_t* dst = (uint32_t*)(g_vt + (size_t)bh * HD_ * S_ + j0);
#pragma unroll
    for (int i = 0; i < 8; i++) {
        int flat = tid + i * 256;
        int d = flat >> 5, sp = flat & 31;
        uint32_t v = (uint32_t)ts[(2 * sp) * 66 + d] |
                     ((uint32_t)ts[(2 * sp + 1) * 66 + d] << 16);
        dst[(size_t)d * (S_ / 2) + sp] = v;
    }
}

// ---------------- tensor-core flash attention (compacted keys) ---------------
#define FQ   0u
#define FKV  18432u
#define FBUF 18432u
#define FLASH_SMEM 55296

__global__ __launch_bounds__(256) void flash_tc_kernel()
{
    char* sm = dynsmem;
    const uint32_t sb = smem_u32(sm);
    const int tid = threadIdx.x, w = tid >> 5, lane = tid & 31;
    const int lr = lane & 7, lq = lane >> 3, g = lane >> 2, q = lane & 3;
    const int b = blockIdx.z, h = blockIdx.y;
    const int bh = b * H_ + h;
    const int q0 = blockIdx.x * 128;

    const int cnt = g_cnt[b];
    int nkt = (cnt + 63) >> 6;
    if (nkt < 1) nkt = 1;

    const __half* Qp  = g_q  + ((size_t)bh * S_ + q0) * HD_;
    const __half* Kp  = g_kc + (size_t)bh * S_ * HD_;
    const __half* Vtp = g_vt + (size_t)bh * HD_ * S_;

    {
        int r = tid >> 1, halfr = tid & 1;
        const __half* src = Qp + (size_t)r * HD_ + halfr * 32;
        uint32_t dst = sb + FQ + (uint32_t)r * 144u + (uint32_t)halfr * 64u;
#pragma unroll
        for (int j = 0; j < 4; j++) cp16(dst + j * 16, src + j * 8);
    }
    cp_commit();

    auto load_tile = [&](int kt, int buf) {
        int k0 = kt * 64;
        int which = tid & 1;
        int halfr = (tid >> 1) & 1;
        int r = tid >> 2;
        uint32_t dst = sb + FKV + (uint32_t)buf * FBUF + (uint32_t)which * 9216u +
                       (uint32_t)r * 144u + (uint32_t)halfr * 64u;
        const __half* src = which ? (Vtp + (size_t)r * S_ + k0 + halfr * 32)
                                  : (Kp + (size_t)(k0 + r) * HD_ + halfr * 32);
#pragma unroll
        for (int j = 0; j < 4; j++) cp16(dst + j * 16, src + j * 8);
        cp_commit();
    };
    load_tile(0, 0);
    load_tile(1, 1);

    asm volatile("cp.async.wait_group 2;" ::: "memory");
    __syncthreads();

    uint32_t qf[4][4];
    {
        uint32_t aoff = (uint32_t)(w * 16 + (lq & 1) * 8 + lr) * 144u +
                        (uint32_t)((lq >> 1) * 8) * 2u;
#pragma unroll
        for (int ks = 0; ks < 4; ks++)
            ldsm4(qf[ks], sb + FQ + aoff + ks * 32);
    }

    float o[8][4];
#pragma unroll
    for (int i = 0; i < 8; i++) { o[i][0] = o[i][1] = o[i][2] = o[i][3] = 0.f; }
    float m0r = -1e30f, m1r = -1e30f, l0 = 0.f, l1 = 0.f;
    const uint32_t boff = (uint32_t)((lq >> 1) * 8 + lr) * 144u +
                          (uint32_t)((lq & 1) * 8) * 2u;

#pragma unroll 1
    for (int kt = 0; kt < nkt; kt++) {
        if (kt >= nkt - 2) asm volatile("cp.async.wait_group 0;" ::: "memory");
        else               asm volatile("cp.async.wait_group 1;" ::: "memory");
        __syncthreads();

        const uint32_t kb = sb + FKV + (uint32_t)(kt & 1) * FBUF;

        float sc[8][4];
#pragma unroll
        for (int i = 0; i < 8; i++) { sc[i][0] = sc[i][1] = sc[i][2] = sc[i][3] = 0.f; }

#pragma unroll
        for (int ks = 0; ks < 4; ks++) {
            uint32_t kf[4][4];
#pragma unroll
            for (int np = 0; np < 4; np++)
                ldsm4(kf[np], kb + boff + (uint32_t)np * 2304u + ks * 32);
#pragma unroll
            for (int nt = 0; nt < 8; nt++)
                mma_f16(sc[nt], qf[ks], &kf[nt >> 1][(nt & 1) * 2]);
        }

#pragma unroll
        for (int nt = 0; nt < 8; nt++) {
            int j = kt * 64 + nt * 8 + q * 2;
            bool p0 = j < cnt, p1 = j + 1 < cnt;
            sc[nt][0] = p0 ? sc[nt][0] : -1e10f;
            sc[nt][1] = p1 ? sc[nt][1] : -1e10f;
            sc[nt][2] = p0 ? sc[nt][2] : -1e10f;
            sc[nt][3] = p1 ? sc[nt][3] : -1e10f;
        }

        float tm0 = -1e30f, tm1 = -1e30f;
#pragma unroll
        for (int nt = 0; nt < 8; nt++) {
            tm0 = fmaxf(tm0, fmaxf(sc[nt][0], sc[nt][1]));
            tm1 = fmaxf(tm1, fmaxf(sc[nt][2], sc[nt][3]));
        }
        tm0 = fmaxf(tm0, __shfl_xor_sync(0xffffffffu, tm0, 1));
        tm0 = fmaxf(tm0, __shfl_xor_sync(0xffffffffu, tm0, 2));
        tm1 = fmaxf(tm1, __shfl_xor_sync(0xffffffffu, tm1, 1));
        tm1 = fmaxf(tm1, __shfl_xor_sync(0xffffffffu, tm1, 2));
        float nm0 = fmaxf(m0r, tm0), nm1 = fmaxf(m1r, tm1);
        float al0 = exp2f(m0r - nm0), al1 = exp2f(m1r - nm1);
        m0r = nm0; m1r = nm1;
        float rs0 = 0.f, rs1 = 0.f;
#pragma unroll
        for (int nt = 0; nt < 8; nt++) {
            sc[nt][0] = exp2f(sc[nt][0] - nm0);
            sc[nt][1] = exp2f(sc[nt][1] - nm0);
            sc[nt][2] = exp2f(sc[nt][2] - nm1);
            sc[nt][3] = exp2f(sc[nt][3] - nm1);
            rs0 += sc[nt][0] + sc[nt][1];
            rs1 += sc[nt][2] + sc[nt][3];
        }
        rs0 += __shfl_xor_sync(0xffffffffu, rs0, 1);
        rs0 += __shfl_xor_sync(0xffffffffu, rs0, 2);
        rs1 += __shfl_xor_sync(0xffffffffu, rs1, 1);
        rs1 += __shfl_xor_sync(0xffffffffu, rs1, 2);
        l0 = l0 * al0 + rs0;
        l1 = l1 * al1 + rs1;
#pragma unroll
        for (int nt = 0; nt < 8; nt++) {
            o[nt][0] *= al0; o[nt][1] *= al0; o[nt][2] *= al1; o[nt][3] *= al1;
        }

#pragma unroll
        for (int ks = 0; ks < 4; ks++) {
            const int t0 = 2 * ks, t1 = t0 + 1;
            uint32_t ah[4];
            ah[0] = pack2h(sc[t0][0], sc[t0][1]);
            ah[1] = pack2h(sc[t0][2], sc[t0][3]);
            ah[2] = pack2h(sc[t1][0], sc[t1][1]);
            ah[3] = pack2h(sc[t1][2], sc[t1][3]);
            uint32_t vf[4][4];
#pragma unroll
            for (int np = 0; np < 4; np++)
                ldsm4(vf[np], kb + 9216u + boff + (uint32_t)np * 2304u + ks * 32);
#pragma unroll
            for (int nt = 0; nt < 8; nt++)
                mma_f16(o[nt], ah, &vf[nt >> 1][(nt & 1) * 2]);
        }
        __syncthreads();
        if (kt + 2 < nkt) load_tile(kt + 2, kt & 1);
    }

    float inv0 = 1.f / l0, inv1 = 1.f / l1;
    size_t row0 = (size_t)(b * S_ + q0 + w * 16 + g);
    int colb = h * HD_;
#pragma unroll
    for (int nt = 0; nt < 8; nt++) {
        int col = colb + nt * 8 + q * 2;
        *(uint32_t*)&g_hh[row0 * D_ + col] = pack2h(o[nt][0] * inv0, o[nt][1] * inv0);
        *(uint32_t*)&g_hh[(row0 + 8) * D_ + col] = pack2h(o[nt][2] * inv1, o[nt][3] * inv1);
    }
}

// ---------------------------------------------------------------------------
extern "C" void kernel_launch(void* const* d_in, const int* in_sizes, int n_in,
                              void* d_out, int out_size)
{
    const float* query = (const float*)d_in[0];
    const float* key   = (const float*)d_in[1];
    const float* value = (const float*)d_in[2];
    const int*   mask  = (const int*)d_in[3];
    const float* Wq = (const float*)d_in[4];
    const float* bq = (const float*)d_in[5];
    const float* Wk = (const float*)d_in[6];
    const float* bk = (const float*)d_in[7];
    const float* Wv = (const float*)d_in[8];
    const float* bv = (const float*)d_in[9];
    const float* Wo = (const float*)d_in[10];
    const float* bo = (const float*)d_in[11];
    float* out = (float*)d_out;

    __half *xq,*xk,*xv,*wq,*wk,*wv,*wo,*hh,*qq,*kk,*vv;
    cudaGetSymbolAddress((void**)&xq, g_xq);
    cudaGetSymbolAddress((void**)&xk, g_xk);
    cudaGetSymbolAddress((void**)&xv, g_xv);
    cudaGetSymbolAddress((void**)&wq, g_wq);
    cudaGetSymbolAddress((void**)&wk, g_wk);
    cudaGetSymbolAddress((void**)&wv, g_wv);
    cudaGetSymbolAddress((void**)&wo, g_wo);
    cudaGetSymbolAddress((void**)&qq, g_q);
    cudaGetSymbolAddress((void**)&kk, g_k);
    cudaGetSymbolAddress((void**)&vv, g_v);
    cudaGetSymbolAddress((void**)&hh, g_hh);

    static int attr_set = 0;
    if (!attr_set) {
        cudaFuncSetAttribute((const void*)gemm_proj_kernel,
                             cudaFuncAttributeMaxDynamicSharedMemorySize, GEMM_SMEM);
        cudaFuncSetAttribute((const void*)gemm_out_kernel,
                             cudaFuncAttributeMaxDynamicSharedMemorySize, GEMM_SMEM);
        cudaFuncSetAttribute((const void*)flash_tc_kernel,
                             cudaFuncAttributeMaxDynamicSharedMemorySize, FLASH_SMEM);
        attr_set = 1;
    }

    const int NX4 = M_ * D_ / 4;
    cvt_all_kernel<<<dim3((NX4 + 255) / 256, 7), 256>>>(
        query, key, value, Wq, Wk, Wv, Wo, xq, xk, xv, wq, wk, wv, wo);

    mask_compact_kernel<<<B_, 256>>>(mask);

    gemm_proj_kernel<<<dim3(D_ / BN, M_ / BM, 3), 256, GEMM_SMEM>>>(
        xq, xk, xv, wq, wk, wv, bq, bk, bv, qq, kk, vv);

    gather_kv_kernel<<<dim3(S_ / 64, H_, B_), 256>>>();

    flash_tc_kernel<<<dim3(S_ / 128, H_, B_), 256, FLASH_SMEM>>>();

    gemm_out_kernel<<<dim3(D_ / BN, M_ / BM), 256, GEMM_SMEM>>>(hh, wo, bo, out);
}

// round 14
// speedup vs baseline: 4.8105x; 1.1120x over previous
#include <cuda_runtime.h>
#include <cuda_bf16.h>
#include <cuda_fp16.h>
#include <cstdint>

// Problem constants
#define B_  4
#define S_  2048
#define D_  1024
#define H_  16
#define HD_ 64
#define M_  (B_*S_)   // 8192

// ---------------- scratch (__device__ globals) ------------------------------
__device__ __half g_xq[(size_t)M_*D_], g_xk[(size_t)M_*D_], g_xv[(size_t)M_*D_];
__device__ __half g_wq[(size_t)D_*D_], g_wk[(size_t)D_*D_];
__device__ __half g_wv[(size_t)D_*D_], g_wo[(size_t)D_*D_];
__device__ __half g_q [(size_t)M_*D_];
__device__ __half g_k [(size_t)M_*D_];
__device__ __half g_v [(size_t)M_*D_];
__device__ __half g_kc[(size_t)M_*D_];
__device__ __half g_vt[(size_t)M_*D_];
__device__ __half g_hh[(size_t)M_*D_];
__device__ int g_cnt[B_];
__device__ int g_idx[B_][S_];

extern __shared__ char dynsmem[];

// 0.125 * log2(e)
#define SCALE_L2E 0.18033688011112042f

// ---------------- PTX helpers ------------------------------------------------
__device__ __forceinline__ uint32_t smem_u32(const void* p) {
    uint32_t a;
    asm("{ .reg .u64 t; cvta.to.shared.u64 t, %1; cvt.u32.u64 %0, t; }" : "=r"(a) : "l"(p));
    return a;
}
__device__ __forceinline__ void cp16(uint32_t dst, const void* src) {
    asm volatile("cp.async.cg.shared.global [%0], [%1], 16;" :: "r"(dst), "l"(src) : "memory");
}
__device__ __forceinline__ void cp_commit() {
    asm volatile("cp.async.commit_group;" ::: "memory");
}
__device__ __forceinline__ void ldsm4(uint32_t* r, uint32_t addr) {
    asm volatile("ldmatrix.sync.aligned.m8n8.x4.shared.b16 {%0,%1,%2,%3}, [%4];"
                 : "=r"(r[0]), "=r"(r[1]), "=r"(r[2]), "=r"(r[3]) : "r"(addr));
}
__device__ __forceinline__ void mma_f16(float* d, const uint32_t* a, const uint32_t* b) {
    asm volatile(
        "mma.sync.aligned.m16n8k16.row.col.f32.f16.f16.f32 "
        "{%0,%1,%2,%3}, {%4,%5,%6,%7}, {%8,%9}, {%0,%1,%2,%3};"
        : "+f"(d[0]), "+f"(d[1]), "+f"(d[2]), "+f"(d[3])
        : "r"(a[0]), "r"(a[1]), "r"(a[2]), "r"(a[3]), "r"(b[0]), "r"(b[1]));
}
__device__ __forceinline__ uint32_t pack2h(float x0, float x1) {
    __half2 h = __floats2half2_rn(x0, x1);
    return *(uint32_t*)&h;
}

// ---------------- fused conversion kernel ------------------------------------
__global__ __launch_bounds__(256) void cvt_all_kernel(
    const float* __restrict__ xq, const float* __restrict__ xk, const float* __restrict__ xv,
    const float* __restrict__ Wq, const float* __restrict__ Wk,
    const float* __restrict__ Wv, const float* __restrict__ Wo,
    __half* __restrict__ oxq, __half* __restrict__ oxk, __half* __restrict__ oxv,
    __half* __restrict__ owq, __half* __restrict__ owk,
    __half* __restrict__ owv, __half* __restrict__ owo)
{
    const int y = blockIdx.y;
    int i = blockIdx.x * blockDim.x + threadIdx.x;
    const int n4 = (y < 3) ? (M_ * D_ / 4) : (D_ * D_ / 4);
    if (i >= n4) return;
    const float* s = y == 0 ? xq : (y == 1 ? xk : (y == 2 ? xv :
                     (y == 3 ? Wq : (y == 4 ? Wk : (y == 5 ? Wv : Wo)))));
    __half* o = y == 0 ? oxq : (y == 1 ? oxk : (y == 2 ? oxv :
                (y == 3 ? owq : (y == 4 ? owk : (y == 5 ? owv : owo)))));
    float4 v = ((const float4*)s)[i];
    ((uint2*)o)[i] = make_uint2(pack2h(v.x, v.y), pack2h(v.z, v.w));
}

// ---------------- mask compaction: one block per batch -----------------------
__global__ __launch_bounds__(256) void mask_compact_kernel(const int* __restrict__ mask)
{
    __shared__ int warp_off[8];
    const int b = blockIdx.x;
    const int tid = threadIdx.x, lane = tid & 31, wid = tid >> 5;
    const int* m = mask + b * S_;
    int vals[8], c = 0;
#pragma unroll
    for (int i = 0; i < 8; i++) { vals[i] = m[tid * 8 + i]; c += (vals[i] != 0); }
    int pre = c;
#pragma unroll
    for (int off = 1; off < 32; off <<= 1) {
        int t = __shfl_up_sync(0xffffffffu, pre, off);
        if (lane >= off) pre += t;
    }
    if (lane == 31) warp_off[wid] = pre;
    __syncthreads();
    if (tid == 0) {
        int s = 0;
#pragma unroll
        for (int i = 0; i < 8; i++) { int t = warp_off[i]; warp_off[i] = s; s += t; }
        g_cnt[b] = s;
    }
    __syncthreads();
    int pos = warp_off[wid] + pre - c;
#pragma unroll
    for (int i = 0; i < 8; i++)
        if (vals[i]) g_idx[b][pos++] = tid * 8 + i;
}

// ---------------- fp16 1-call GEMM, 3-stage pipeline -------------------------
#define BM 128
#define BN 128
#define GBK 32
#define ROWB 80
#define TILEB (128 * ROWB)
#define BUFB  (2 * TILEB)       // A, B
#define GEMM_SMEM (3 * BUFB)    // 61440

__device__ __forceinline__ void g2s_chunk(
    uint32_t sbuf, const __half* Ap, const __half* Bw, int tid)
{
#pragma unroll
    for (int r = 0; r < 2; r++) {
        int c = tid + (r << 8);
        int row = c >> 2, c16 = c & 3;
        uint32_t soff = (uint32_t)row * ROWB + (uint32_t)c16 * 16;
        size_t goff = (size_t)row * D_ + c16 * 8;
        cp16(sbuf + 0 * TILEB + soff, Ap + goff);
        cp16(sbuf + 1 * TILEB + soff, Bw + goff);
    }
}

__device__ __forceinline__ void gemm_mainloop(
    uint32_t sb, const __half* Ap, const __half* Bp,
    int tid, int lane, int wm, int wn, float acc[4][4][4])
{
#pragma unroll
    for (int i = 0; i < 4; i++)
#pragma unroll
        for (int j = 0; j < 4; j++)
#pragma unroll
            for (int k = 0; k < 4; k++) acc[i][j][k] = 0.f;

    g2s_chunk(sb,        Ap,       Bp,       tid); cp_commit();
    g2s_chunk(sb + BUFB, Ap + GBK, Bp + GBK, tid); cp_commit();

    const int lr = lane & 7, lq = lane >> 3;
    const uint32_t a_base_off =
        (uint32_t)(wm * 64 + (lq & 1) * 8 + lr) * ROWB + (uint32_t)((lq >> 1) * 8) * 2;
    const uint32_t b_base_off =
        (uint32_t)(wn * 32 + (lq >> 1) * 8 + lr) * ROWB + (uint32_t)((lq & 1) * 8) * 2;

    const int NCHUNK = D_ / GBK;   // 32
    int cur = 0, nxt = 2;          // buffer indices mod 3
#pragma unroll 1
    for (int c = 0; c < NCHUNK; c++) {
        if (c >= NCHUNK - 2) asm volatile("cp.async.wait_group 0;" ::: "memory");
        else                 asm volatile("cp.async.wait_group 1;" ::: "memory");
        __syncthreads();

        const uint32_t buf = sb + (uint32_t)cur * BUFB;
        const uint32_t sA = buf, sB = buf + TILEB;

#pragma unroll
        for (int ks = 0; ks < 2; ks++) {
            const uint32_t ko = (uint32_t)(ks * 16) * 2;
            uint32_t ar[4][4], br[2][4];
#pragma unroll
            for (int mt = 0; mt < 4; mt++)
                ldsm4(ar[mt], sA + a_base_off + ko + (uint32_t)mt * (16 * ROWB));
#pragma unroll
            for (int np = 0; np < 2; np++)
                ldsm4(br[np], sB + b_base_off + ko + (uint32_t)np * (16 * ROWB));
#pragma unroll
            for (int mt = 0; mt < 4; mt++)
#pragma unroll
                for (int nt = 0; nt < 4; nt++)
                    mma_f16(acc[mt][nt], ar[mt], &br[nt >> 1][(nt & 1) * 2]);
        }

        // prefetch into buffer last read at iteration c-1 (3-stage: no 2nd barrier)
        if (c + 2 < NCHUNK) {
            const int kc = (c + 2) * GBK;
            g2s_chunk(sb + (uint32_t)nxt * BUFB, Ap + kc, Bp + kc, tid);
            cp_commit();
        }
        cur = cur == 2 ? 0 : cur + 1;
        nxt = nxt == 2 ? 0 : nxt + 1;
    }
}

// Fused projection GEMM: grid.z selects (X, W, bias, out, scale).
__global__ __launch_bounds__(256) void gemm_proj_kernel(
    const __half* __restrict__ xq, const __half* __restrict__ xk,
    const __half* __restrict__ xv,
    const __half* __restrict__ wq, const __half* __restrict__ wk,
    const __half* __restrict__ wv,
    const float* __restrict__ bq, const float* __restrict__ bk,
    const float* __restrict__ bv,
    __half* __restrict__ oq, __half* __restrict__ ok, __half* __restrict__ ov)
{
    const uint32_t sb = smem_u32(dynsmem);
    const int tid = threadIdx.x, wid = tid >> 5, lane = tid & 31;
    const int wm = wid >> 2, wn = wid & 3;
    const int n0 = blockIdx.x * BN, m0 = blockIdx.y * BM;
    const int z = blockIdx.z;

    const __half* Ab  = z == 0 ? xq : (z == 1 ? xk : xv);
    const __half* Wb  = z == 0 ? wq : (z == 1 ? wk : wv);
    const float* bias = z == 0 ? bq : (z == 1 ? bk : bv);
    __half* outp      = z == 0 ? oq : (z == 1 ? ok : ov);
    const float oscale = z == 0 ? SCALE_L2E : 1.0f;

    float acc[4][4][4];
    gemm_mainloop(sb, Ab + (size_t)m0 * D_, Wb + (size_t)n0 * D_,
                  tid, lane, wm, wn, acc);

    const int g = lane >> 2, tq = lane & 3;
#pragma unroll
    for (int mt = 0; mt < 4; mt++) {
#pragma unroll
        for (int nt = 0; nt < 4; nt++) {
            int row = m0 + wm * 64 + mt * 16 + g;
            int col = n0 + wn * 32 + nt * 8 + tq * 2;
            float2 bv2 = *(const float2*)&bias[col];
            float v0 = (acc[mt][nt][0] + bv2.x) * oscale;
            float v1 = (acc[mt][nt][1] + bv2.y) * oscale;
            float v2 = (acc[mt][nt][2] + bv2.x) * oscale;
            float v3 = (acc[mt][nt][3] + bv2.y) * oscale;
            int bb = row >> 11, s = row & 2047, hh = col >> 6, d = col & 63;
            size_t i0 = ((size_t)(bb * H_ + hh) * S_ + s) * HD_ + d;
            size_t i1 = i0 + 8 * HD_;
            *(uint32_t*)&outp[i0] = pack2h(v0, v1);
            *(uint32_t*)&outp[i1] = pack2h(v2, v3);
        }
    }
}

// Final GEMM: single-A fp16, fp32 out.
__global__ __launch_bounds__(256) void gemm_out_kernel(
    const __half* __restrict__ Ahi, const __half* __restrict__ Bw,
    const float* __restrict__ bias, float* __restrict__ out)
{
    const uint32_t sb = smem_u32(dynsmem);
    const int tid = threadIdx.x, wid = tid >> 5, lane = tid & 31;
    const int wm = wid >> 2, wn = wid & 3;
    const int n0 = blockIdx.x * BN, m0 = blockIdx.y * BM;

    float acc[4][4][4];
    gemm_mainloop(sb, Ahi + (size_t)m0 * D_, Bw + (size_t)n0 * D_,
                  tid, lane, wm, wn, acc);

    const int g = lane >> 2, tq = lane & 3;
#pragma unroll
    for (int mt = 0; mt < 4; mt++) {
#pragma unroll
        for (int nt = 0; nt < 4; nt++) {
            int row = m0 + wm * 64 + mt * 16 + g;
            int col = n0 + wn * 32 + nt * 8 + tq * 2;
            float2 bv2 = *(const float2*)&bias[col];
            *(float2*)&out[(size_t)row * D_ + col] =
                make_float2(acc[mt][nt][0] + bv2.x, acc[mt][nt][1] + bv2.y);
            *(float2*)&out[(size_t)(row + 8) * D_ + col] =
                make_float2(acc[mt][nt][2] + bv2.x, acc[mt][nt][3] + bv2.y);
        }
    }
}

// ---------------- gather: compact K rows; compact + transpose V --------------
__global__ __launch_bounds__(256) void gather_kv_kernel()
{
    __shared__ __align__(16) unsigned short ts[64 * 66];
    __shared__ int sidx[64];
    const int b = blockIdx.z, h = blockIdx.y, st = blockIdx.x;
    const int bh = b * H_ + h;
    const int j0 = st * 64;
    const int tid = threadIdx.x;
    const int cnt = g_cnt[b];

    if (tid < 64) sidx[tid] = (j0 + tid < cnt) ? g_idx[b][j0 + tid] : -1;
    __syncthreads();

    {
        int r = tid >> 2, part = tid & 3;
        int s = sidx[r];
        const uint4* srcp = (const uint4*)(g_k + ((size_t)bh * S_ + (s < 0 ? 0 : s)) * HD_)
                            + part * 2;
        uint4 z = make_uint4(0, 0, 0, 0);
        uint4 v0 = s >= 0 ? srcp[0] : z;
        uint4 v1 = s >= 0 ? srcp[1] : z;
        uint4* dstp = (uint4*)(g_kc + ((size_t)bh * S_ + j0 + r) * HD_) + part * 2;
        dstp[0] = v0;
        dstp[1] = v1;
    }

#pragma unroll
    for (int i = 0; i < 8; i++) {
        int flat = tid + i * 256;
        int r = flat >> 5, c2 = flat & 31;
        int s = sidx[r];
        uint32_t v = 0;
        if (s >= 0)
            v = ((const uint32_t*)(g_v + ((size_t)bh * S_ + s) * HD_))[c2];
        *(uint32_t*)&ts[r * 66 + c2 * 2] = v;
    }
    __syncthreads();
    uint32_t* dst = (uint32_t*)(g_vt + (size_t)bh * HD_ * S_ + j0);
#pragma unroll
    for (int i = 0; i < 8; i++) {
        int flat = tid + i * 256;
        int d = flat >> 5, sp = flat & 31;
        uint32_t v = (uint32_t)ts[(2 * sp) * 66 + d] |
                     ((uint32_t)ts[(2 * sp + 1) * 66 + d] << 16);
        dst[(size_t)d * (S_ / 2) + sp] = v;
    }
}

// ---------------- tensor-core flash attention, 3-stage KV pipeline -----------
#define FQ   0u
#define FKV  18432u
#define FBUF 18432u
#define FLASH_SMEM 73728   // Q + 3 KV stages

__global__ __launch_bounds__(256) void flash_tc_kernel()
{
    char* sm = dynsmem;
    const uint32_t sb = smem_u32(sm);
    const int tid = threadIdx.x, w = tid >> 5, lane = tid & 31;
    const int lr = lane & 7, lq = lane >> 3, g = lane >> 2, q = lane & 3;
    const int b = blockIdx.z, h = blockIdx.y;
    const int bh = b * H_ + h;
    const int q0 = blockIdx.x * 128;

    const int cnt = g_cnt[b];
    int nkt = (cnt + 63) >> 6;
    if (nkt < 1) nkt = 1;

    const __half* Qp  = g_q  + ((size_t)bh * S_ + q0) * HD_;
    const __half* Kp  = g_kc + (size_t)bh * S_ * HD_;
    const __half* Vtp = g_vt + (size_t)bh * HD_ * S_;

    {
        int r = tid >> 1, halfr = tid & 1;
        const __half* src = Qp + (size_t)r * HD_ + halfr * 32;
        uint32_t dst = sb + FQ + (uint32_t)r * 144u + (uint32_t)halfr * 64u;
#pragma unroll
        for (int j = 0; j < 4; j++) cp16(dst + j * 16, src + j * 8);
    }
    cp_commit();

    auto load_tile = [&](int kt, int buf) {
        int k0 = kt * 64;
        int which = tid & 1;
        int halfr = (tid >> 1) & 1;
        int r = tid >> 2;
        uint32_t dst = sb + FKV + (uint32_t)buf * FBUF + (uint32_t)which * 9216u +
                       (uint32_t)r * 144u + (uint32_t)halfr * 64u;
        const __half* src = which ? (Vtp + (size_t)r * S_ + k0 + halfr * 32)
                                  : (Kp + (size_t)(k0 + r) * HD_ + halfr * 32);
#pragma unroll
        for (int j = 0; j < 4; j++) cp16(dst + j * 16, src + j * 8);
        cp_commit();
    };
    load_tile(0, 0);
    load_tile(1, 1);

    asm volatile("cp.async.wait_group 2;" ::: "memory");
    __syncthreads();

    uint32_t qf[4][4];
    {
        uint32_t aoff = (uint32_t)(w * 16 + (lq & 1) * 8 + lr) * 144u +
                        (uint32_t)((lq >> 1) * 8) * 2u;
#pragma unroll
        for (int ks = 0; ks < 4; ks++)
            ldsm4(qf[ks], sb + FQ + aoff + ks * 32);
    }

    float o[8][4];
#pragma unroll
    for (int i = 0; i < 8; i++) { o[i][0] = o[i][1] = o[i][2] = o[i][3] = 0.f; }
    float m0r = -1e30f, m1r = -1e30f, l0 = 0.f, l1 = 0.f;
    const uint32_t boff = (uint32_t)((lq >> 1) * 8 + lr) * 144u +
                          (uint32_t)((lq & 1) * 8) * 2u;

    int cur = 0, nxt = 2;   // KV stage indices mod 3
#pragma unroll 1
    for (int kt = 0; kt < nkt; kt++) {
        if (kt >= nkt - 2) asm volatile("cp.async.wait_group 0;" ::: "memory");
        else               asm volatile("cp.async.wait_group 1;" ::: "memory");
        __syncthreads();

        const uint32_t kb = sb + FKV + (uint32_t)cur * FBUF;

        float sc[8][4];
#pragma unroll
        for (int i = 0; i < 8; i++) { sc[i][0] = sc[i][1] = sc[i][2] = sc[i][3] = 0.f; }

#pragma unroll
        for (int ks = 0; ks < 4; ks++) {
            uint32_t kf[4][4];
#pragma unroll
            for (int np = 0; np < 4; np++)
                ldsm4(kf[np], kb + boff + (uint32_t)np * 2304u + ks * 32);
#pragma unroll
            for (int nt = 0; nt < 8; nt++)
                mma_f16(sc[nt], qf[ks], &kf[nt >> 1][(nt & 1) * 2]);
        }

        // issue next tile's loads early (3-stage: target buffer not in use)
        if (kt + 2 < nkt) load_tile(kt + 2, nxt);

#pragma unroll
        for (int nt = 0; nt < 8; nt++) {
            int j = kt * 64 + nt * 8 + q * 2;
            bool p0 = j < cnt, p1 = j + 1 < cnt;
            sc[nt][0] = p0 ? sc[nt][0] : -1e10f;
            sc[nt][1] = p1 ? sc[nt][1] : -1e10f;
            sc[nt][2] = p0 ? sc[nt][2] : -1e10f;
            sc[nt][3] = p1 ? sc[nt][3] : -1e10f;
        }

        float tm0 = -1e30f, tm1 = -1e30f;
#pragma unroll
        for (int nt = 0; nt < 8; nt++) {
            tm0 = fmaxf(tm0, fmaxf(sc[nt][0], sc[nt][1]));
            tm1 = fmaxf(tm1, fmaxf(sc[nt][2], sc[nt][3]));
        }
        tm0 = fmaxf(tm0, __shfl_xor_sync(0xffffffffu, tm0, 1));
        tm0 = fmaxf(tm0, __shfl_xor_sync(0xffffffffu, tm0, 2));
        tm1 = fmaxf(tm1, __shfl_xor_sync(0xffffffffu, tm1, 1));
        tm1 = fmaxf(tm1, __shfl_xor_sync(0xffffffffu, tm1, 2));
        float nm0 = fmaxf(m0r, tm0), nm1 = fmaxf(m1r, tm1);
        float al0 = exp2f(m0r - nm0), al1 = exp2f(m1r - nm1);
        m0r = nm0; m1r = nm1;
        float rs0 = 0.f, rs1 = 0.f;
#pragma unroll
        for (int nt = 0; nt < 8; nt++) {
            sc[nt][0] = exp2f(sc[nt][0] - nm0);
            sc[nt][1] = exp2f(sc[nt][1] - nm0);
            sc[nt][2] = exp2f(sc[nt][2] - nm1);
            sc[nt][3] = exp2f(sc[nt][3] - nm1);
            rs0 += sc[nt][0] + sc[nt][1];
            rs1 += sc[nt][2] + sc[nt][3];
        }
        rs0 += __shfl_xor_sync(0xffffffffu, rs0, 1);
        rs0 += __shfl_xor_sync(0xffffffffu, rs0, 2);
        rs1 += __shfl_xor_sync(0xffffffffu, rs1, 1);
        rs1 += __shfl_xor_sync(0xffffffffu, rs1, 2);
        l0 = l0 * al0 + rs0;
        l1 = l1 * al1 + rs1;
#pragma unroll
        for (int nt = 0; nt < 8; nt++) {
            o[nt][0] *= al0; o[nt][1] *= al0; o[nt][2] *= al1; o[nt][3] *= al1;
        }

#pragma unroll
        for (int ks = 0; ks < 4; ks++) {
            const int t0 = 2 * ks, t1 = t0 + 1;
            uint32_t ah[4];
            ah[0] = pack2h(sc[t0][0], sc[t0][1]);
            ah[1] = pack2h(sc[t0][2], sc[t0][3]);
            ah[2] = pack2h(sc[t1][0], sc[t1][1]);
            ah[3] = pack2h(sc[t1][2], sc[t1][3]);
            uint32_t vf[4][4];
#pragma unroll
            for (int np = 0; np < 4; np++)
                ldsm4(vf[np], kb + 9216u + boff + (uint32_t)np * 2304u + ks * 32);
#pragma unroll
            for (int nt = 0; nt < 8; nt++)
                mma_f16(o[nt], ah, &vf[nt >> 1][(nt & 1) * 2]);
        }
        cur = cur == 2 ? 0 : cur + 1;
        nxt = nxt == 2 ? 0 : nxt + 1;
    }

    float inv0 = 1.f / l0, inv1 = 1.f / l1;
    size_t row0 = (size_t)(b * S_ + q0 + w * 16 + g);
    int colb = h * HD_;
#pragma unroll
    for (int nt = 0; nt < 8; nt++) {
        int col = colb + nt * 8 + q * 2;
        *(uint32_t*)&g_hh[row0 * D_ + col] = pack2h(o[nt][0] * inv0, o[nt][1] * inv0);
        *(uint32_t*)&g_hh[(row0 + 8) * D_ + col] = pack2h(o[nt][2] * inv1, o[nt][3] * inv1);
    }
}

// ---------------------------------------------------------------------------
extern "C" void kernel_launch(void* const* d_in, const int* in_sizes, int n_in,
                              void* d_out, int out_size)
{
    const float* query = (const float*)d_in[0];
    const float* key   = (const float*)d_in[1];
    const float* value = (const float*)d_in[2];
    const int*   mask  = (const int*)d_in[3];
    const float* Wq = (const float*)d_in[4];
    const float* bq = (const float*)d_in[5];
    const float* Wk = (const float*)d_in[6];
    const float* bk = (const float*)d_in[7];
    const float* Wv = (const float*)d_in[8];
    const float* bv = (const float*)d_in[9];
    const float* Wo = (const float*)d_in[10];
    const float* bo = (const float*)d_in[11];
    float* out = (float*)d_out;

    __half *xq,*xk,*xv,*wq,*wk,*wv,*wo,*hh,*qq,*kk,*vv;
    cudaGetSymbolAddress((void**)&xq, g_xq);
    cudaGetSymbolAddress((void**)&xk, g_xk);
    cudaGetSymbolAddress((void**)&xv, g_xv);
    cudaGetSymbolAddress((void**)&wq, g_wq);
    cudaGetSymbolAddress((void**)&wk, g_wk);
    cudaGetSymbolAddress((void**)&wv, g_wv);
    cudaGetSymbolAddress((void**)&wo, g_wo);
    cudaGetSymbolAddress((void**)&qq, g_q);
    cudaGetSymbolAddress((void**)&kk, g_k);
    cudaGetSymbolAddress((void**)&vv, g_v);
    cudaGetSymbolAddress((void**)&hh, g_hh);

    static int attr_set = 0;
    if (!attr_set) {
        cudaFuncSetAttribute((const void*)gemm_proj_kernel,
                             cudaFuncAttributeMaxDynamicSharedMemorySize, GEMM_SMEM);
        cudaFuncSetAttribute((const void*)gemm_out_kernel,
                             cudaFuncAttributeMaxDynamicSharedMemorySize, GEMM_SMEM);
        cudaFuncSetAttribute((const void*)flash_tc_kernel,
                             cudaFuncAttributeMaxDynamicSharedMemorySize, FLASH_SMEM);
        attr_set = 1;
    }

    const int NX4 = M_ * D_ / 4;
    cvt_all_kernel<<<dim3((NX4 + 255) / 256, 7), 256>>>(
        query, key, value, Wq, Wk, Wv, Wo, xq, xk, xv, wq, wk, wv, wo);

    mask_compact_kernel<<<B_, 256>>>(mask);

    gemm_proj_kernel<<<dim3(D_ / BN, M_ / BM, 3), 256, GEMM_SMEM>>>(
        xq, xk, xv, wq, wk, wv, bq, bk, bv, qq, kk, vv);

    gather_kv_kernel<<<dim3(S_ / 64, H_, B_), 256>>>();

    flash_tc_kernel<<<dim3(S_ / 128, H_, B_), 256, FLASH_SMEM>>>();

    gemm_out_kernel<<<dim3(D_ / BN, M_ / BM), 256, GEMM_SMEM>>>(hh, wo, bo, out);
}